// round 1
// baseline (speedup 1.0000x reference)
#include <cuda_runtime.h>
#include <cstdint>

#define WDIM 512
#define NPIX (512*512)
#define ZM 30

typedef unsigned long long ull;

// ---------------- device scratch ----------------
__device__ __align__(16) float2 d_tmpA[(size_t)ZM * NPIX];   // 63 MB
__device__ __align__(16) float2 d_tmpB[(size_t)ZM * NPIX];   // 63 MB
__device__ __align__(16) float  d_q   [(size_t)ZM * NPIX];   // 31.5 MB
__device__ __align__(16) float  d_fluo[(size_t)ZM * NPIX];   // 31.5 MB
__device__ __align__(16) float  d_xyf [(size_t)NPIX * 16];   // 16 MB
__device__ int   d_psum;
__device__ float d_cscale;

// ---------------- f32x2 helpers ----------------
__device__ __forceinline__ ull pk(float lo, float hi) {
    ull r; asm("mov.b64 %0, {%1,%2};" : "=l"(r) : "f"(lo), "f"(hi)); return r;
}
__device__ __forceinline__ void upk(ull v, float& lo, float& hi) {
    asm("mov.b64 {%0,%1}, %2;" : "=f"(lo), "=f"(hi) : "l"(v));
}
__device__ __forceinline__ ull fma2(ull a, ull b, ull c) {
    ull d; asm("fma.rn.f32x2 %0, %1, %2, %3;" : "=l"(d) : "l"(a), "l"(b), "l"(c)); return d;
}
__device__ __forceinline__ ull mul2(ull a, ull b) {
    ull d; asm("mul.rn.f32x2 %0, %1, %2;" : "=l"(d) : "l"(a), "l"(b)); return d;
}
__device__ __forceinline__ ull relu2(ull v) {
    float a, b; upk(v, a, b);
    a = fmaxf(a, 0.0f); b = fmaxf(b, 0.0f);
    return pk(a, b);
}

// ---------------- pupil sum (deterministic int reduction) ----------------
__global__ void zero_k() { d_psum = 0; }

__global__ void reduce_pupil(const float* __restrict__ pupil) {
    int i = blockIdx.x * blockDim.x + threadIdx.x;
    int v = 0;
    for (; i < NPIX; i += gridDim.x * blockDim.x)
        v += (pupil[i] > 0.5f) ? 1 : 0;
    #pragma unroll
    for (int o = 16; o; o >>= 1) v += __shfl_xor_sync(0xffffffffu, v, o);
    if ((threadIdx.x & 31) == 0) atomicAdd(&d_psum, v);
}

__global__ void calc_c() {
    // c = 1 / (N^4 * sum_pupil),  N^2 = 262144 -> N^4 = 68719476736
    d_cscale = (float)(1.0 / (68719476736.0 * (double)d_psum));
}

// ---------------- bilinear xy_feat (z-independent) ----------------
__global__ void __launch_bounds__(256) xyfeat_kernel(
    const float* __restrict__ grid, const float* __restrict__ lerp,
    const int* __restrict__ x0, const int* __restrict__ y0,
    const int* __restrict__ x1, const int* __restrict__ y1)
{
    int p = blockIdx.x * 256 + threadIdx.x;
    float2 l = ((const float2*)lerp)[p];
    float lx = l.x, ly = l.y;
    int X0 = x0[p], Y0 = y0[p], X1 = x1[p], Y1 = y1[p];
    float w00 = (1.f - lx) * (1.f - ly);
    float w10 = lx * (1.f - ly);
    float w01 = (1.f - lx) * ly;
    float w11 = lx * ly;
    const float4* g00 = (const float4*)(grid + ((size_t)Y0 * WDIM + X0) * 16);
    const float4* g10 = (const float4*)(grid + ((size_t)Y0 * WDIM + X1) * 16);
    const float4* g01 = (const float4*)(grid + ((size_t)Y1 * WDIM + X0) * 16);
    const float4* g11 = (const float4*)(grid + ((size_t)Y1 * WDIM + X1) * 16);
    float4* o = (float4*)(d_xyf + (size_t)p * 16);
    #pragma unroll
    for (int q = 0; q < 4; q++) {
        float4 a = g00[q], b = g10[q], c = g01[q], d = g11[q];
        float4 r;
        r.x = a.x * w00 + b.x * w10 + c.x * w01 + d.x * w11;
        r.y = a.y * w00 + b.y * w10 + c.y * w01 + d.y * w11;
        r.z = a.z * w00 + b.z * w10 + c.z * w01 + d.z * w11;
        r.w = a.w * w00 + b.w * w10 + c.w * w01 + d.w * w11;
        o[q] = r;
    }
}

// ---------------- fused 3-layer MLP, 2 pixels/thread via f32x2 ----------------
__global__ void __launch_bounds__(256, 1) mlp_kernel(
    const float* __restrict__ zarr, const float* __restrict__ zdat,
    const float* __restrict__ w1, const float* __restrict__ b1,
    const float* __restrict__ w2, const float* __restrict__ b2,
    const float* __restrict__ w3, const float* __restrict__ b3)
{
    __shared__ __align__(16) ull w1p[16 * 32];
    __shared__ __align__(16) ull w2p[32 * 32];
    __shared__ __align__(16) ull w3p[32];
    __shared__ ull b1p[32], b2p[32], zfp[16];
    __shared__ float b3s;

    int tid = threadIdx.x;
    int z = blockIdx.y;

    {
        float v = w1[tid];        w1p[tid]       = pk(v, v);
        v = w1[tid + 256];        w1p[tid + 256] = pk(v, v);
        #pragma unroll
        for (int q = 0; q < 4; q++) {
            v = w2[tid + q * 256]; w2p[tid + q * 256] = pk(v, v);
        }
        if (tid < 32) {
            float bb = b1[tid]; b1p[tid] = pk(bb, bb);
            bb = b2[tid];       b2p[tid] = pk(bb, bb);
            bb = w3[tid];       w3p[tid] = pk(bb, bb);
        }
        if (tid == 0) b3s = b3[0];
        if (tid < 16) {
            float zv = zarr[z];
            float zn = (29.0f * zv) / 30.0f;
            float zfl = floorf(zn);
            int z0 = (int)zfl; z0 = min(max(z0, 0), ZM - 1);
            int z1 = min(z0 + 1, ZM - 1);
            float zl = zn - zfl;
            float v2 = zdat[z0 * 16 + tid] * (1.0f - zl) + zdat[z1 * 16 + tid] * zl;
            zfp[tid] = pk(v2, v2);
        }
    }
    __syncthreads();

    int pp = blockIdx.x * 256 + tid;        // pixel pair index
    size_t px = (size_t)pp * 2;

    const float4* xp = (const float4*)(d_xyf + px * 16);
    float A[16], B[16];
    #pragma unroll
    for (int q = 0; q < 4; q++) {
        float4 t = xp[q];
        A[q * 4] = t.x; A[q * 4 + 1] = t.y; A[q * 4 + 2] = t.z; A[q * 4 + 3] = t.w;
    }
    #pragma unroll
    for (int q = 0; q < 4; q++) {
        float4 t = xp[4 + q];
        B[q * 4] = t.x; B[q * 4 + 1] = t.y; B[q * 4 + 2] = t.z; B[q * 4 + 3] = t.w;
    }

    ull f[16];
    #pragma unroll
    for (int k = 0; k < 16; k++) f[k] = mul2(pk(A[k], B[k]), zfp[k]);

    // layer 1: 16 -> 32
    ull h[32];
    #pragma unroll
    for (int j = 0; j < 32; j++) h[j] = b1p[j];
    #pragma unroll
    for (int k = 0; k < 16; k++) {
        ull fk = f[k];
        const ulonglong2* wp = (const ulonglong2*)(w1p + k * 32);
        #pragma unroll
        for (int j = 0; j < 16; j++) {
            ulonglong2 ww = wp[j];
            h[2 * j]     = fma2(fk, ww.x, h[2 * j]);
            h[2 * j + 1] = fma2(fk, ww.y, h[2 * j + 1]);
        }
    }
    #pragma unroll
    for (int j = 0; j < 32; j++) h[j] = relu2(h[j]);

    // layer 2: 32 -> 32
    ull g[32];
    #pragma unroll
    for (int j = 0; j < 32; j++) g[j] = b2p[j];
    #pragma unroll
    for (int k = 0; k < 32; k++) {
        ull hk = h[k];
        const ulonglong2* wp = (const ulonglong2*)(w2p + k * 32);
        #pragma unroll
        for (int j = 0; j < 16; j++) {
            ulonglong2 ww = wp[j];
            g[2 * j]     = fma2(hk, ww.x, g[2 * j]);
            g[2 * j + 1] = fma2(hk, ww.y, g[2 * j + 1]);
        }
    }
    #pragma unroll
    for (int j = 0; j < 32; j++) g[j] = relu2(g[j]);

    // layer 3: 32 -> 1
    ull acc = pk(b3s, b3s);
    #pragma unroll
    for (int j = 0; j < 32; j++) acc = fma2(g[j], w3p[j], acc);

    float o0, o1; upk(acc, o0, o1);
    *(float2*)(d_fluo + (size_t)z * NPIX + px) = make_float2(o0, o1);
}

// ---------------- 512-pt radix-2 DIT FFT in shared memory ----------------
// 256 threads cooperate; a[] holds 512 complex values loaded in bit-reversed
// order; after the 9 stages a[] holds the natural-order DFT.
// DIR=+1: forward (e^{-i}); DIR=-1: inverse unnormalized (e^{+i}).
template<int DIR>
__device__ __forceinline__ void fft512_smem(float2* a, const float2* tw, int tid)
{
    #pragma unroll
    for (int s = 0; s < 9; s++) {
        __syncthreads();
        int half = 1 << s;
        int k = tid & (half - 1);
        int pos = ((tid >> s) << (s + 1)) | k;
        float2 w = tw[k << (8 - s)];
        float wy = (DIR > 0) ? w.y : -w.y;
        float2 u = a[pos];
        float2 v = a[pos + half];
        float vr = v.x * w.x - v.y * wy;
        float vi = v.x * wy + v.y * w.x;
        a[pos]        = make_float2(u.x + vr, u.y + vi);
        a[pos + half] = make_float2(u.x - vr, u.y - vi);
    }
    __syncthreads();
}

// Row pass.  MODE 0: build P = pupil * exp(i*aberr)   (rin=pupil, aberr)
//            MODE 1: real input -> complex             (rin)
//            MODE 2: complex input                     (cin)
template<int DIR, int MODE>
__global__ void __launch_bounds__(256) fft_row(
    const float* __restrict__ rin, const float* __restrict__ aberr,
    const float2* __restrict__ cin, float2* __restrict__ cout)
{
    __shared__ float2 a[512];
    __shared__ float2 tw[256];
    int tid = threadIdx.x;
    int r = blockIdx.x, z = blockIdx.y;
    { float sn, cs; sincospif(tid * (1.0f / 256.0f), &sn, &cs); tw[tid] = make_float2(cs, -sn); }
    size_t pbase = (size_t)r * WDIM;
    size_t zbase = (size_t)z * NPIX + pbase;
    #pragma unroll
    for (int q = 0; q < 2; q++) {
        int i = tid + q * 256;
        int ri = __brev(i) >> 23;
        float2 v;
        if (MODE == 0) {
            float p = rin[pbase + i];
            float ab = aberr[zbase + i];
            float sn, cs; __sincosf(ab, &sn, &cs);
            v = make_float2(p * cs, p * sn);
        } else if (MODE == 1) {
            v = make_float2(rin[zbase + i], 0.0f);
        } else {
            v = cin[zbase + i];
        }
        a[ri] = v;
    }
    fft512_smem<DIR>(a, tw, tid);
    #pragma unroll
    for (int q = 0; q < 2; q++) {
        int i = tid + q * 256;
        cout[zbase + i] = a[i];
    }
}

// Column pass on an 8-column tile.
//  MODE 0: write |x|^2 (real)         -> rout
//  MODE 1: write complex              -> cout
//  MODE 2: multiply by mul[] and d_cscale, write complex -> cout (in-place ok)
//  MODE 3: write real part            -> rout
template<int DIR, int MODE>
__global__ void __launch_bounds__(256) fft_col(
    const float2* __restrict__ in, float2* __restrict__ cout,
    float* __restrict__ rout, const float2* __restrict__ mul)
{
    __shared__ float2 a[8 * 512];
    __shared__ float2 tw[256];
    int tid = threadIdx.x;
    int z = blockIdx.y;
    int col0 = blockIdx.x * 8;
    { float sn, cs; sincospif(tid * (1.0f / 256.0f), &sn, &cs); tw[tid] = make_float2(cs, -sn); }
    size_t zb = (size_t)z * NPIX;

    #pragma unroll 4
    for (int l = tid; l < 4096; l += 256) {
        int i = l >> 3, c = l & 7;
        int ri = __brev(i) >> 23;
        a[c * 512 + ri] = in[zb + (size_t)i * WDIM + col0 + c];
    }

    #pragma unroll
    for (int s = 0; s < 9; s++) {
        __syncthreads();
        int half = 1 << s;
        int k = tid & (half - 1);
        int pos = ((tid >> s) << (s + 1)) | k;
        float2 w = tw[k << (8 - s)];
        float wy = (DIR > 0) ? w.y : -w.y;
        #pragma unroll
        for (int c = 0; c < 8; c++) {
            float2* ac = a + c * 512;
            float2 u = ac[pos];
            float2 v = ac[pos + half];
            float vr = v.x * w.x - v.y * wy;
            float vi = v.x * wy + v.y * w.x;
            ac[pos]        = make_float2(u.x + vr, u.y + vi);
            ac[pos + half] = make_float2(u.x - vr, u.y - vi);
        }
    }
    __syncthreads();

    #pragma unroll 4
    for (int l = tid; l < 4096; l += 256) {
        int i = l >> 3, c = l & 7;
        float2 v = a[c * 512 + i];
        size_t gidx = zb + (size_t)i * WDIM + col0 + c;
        if (MODE == 0) {
            rout[gidx] = v.x * v.x + v.y * v.y;
        } else if (MODE == 1) {
            cout[gidx] = v;
        } else if (MODE == 2) {
            float2 m = mul[gidx];
            float cc = d_cscale;
            cout[gidx] = make_float2((v.x * m.x - v.y * m.y) * cc,
                                     (v.x * m.y + v.y * m.x) * cc);
        } else {
            rout[gidx] = v.x;
        }
    }
}

// ---------------- launcher ----------------
extern "C" void kernel_launch(void* const* d_in, const int* in_sizes, int n_in,
                              void* d_out, int out_size)
{
    const float* z     = (const float*)d_in[0];
    const float* grid  = (const float*)d_in[1];
    const float* zdat  = (const float*)d_in[2];
    const float* w1    = (const float*)d_in[3];
    const float* b1    = (const float*)d_in[4];
    const float* w2    = (const float*)d_in[5];
    const float* b2    = (const float*)d_in[6];
    const float* w3    = (const float*)d_in[7];
    const float* b3    = (const float*)d_in[8];
    const float* pupil = (const float*)d_in[9];
    const float* aberr = (const float*)d_in[10];
    const float* lerp  = (const float*)d_in[11];
    const int*   x0    = (const int*)d_in[12];
    const int*   y0    = (const int*)d_in[13];
    const int*   x1    = (const int*)d_in[14];
    const int*   y1    = (const int*)d_in[15];
    float* out = (float*)d_out;

    float2* tmpA; float2* tmpB; float* qbuf; float* fluo;
    cudaGetSymbolAddress((void**)&tmpA, d_tmpA);
    cudaGetSymbolAddress((void**)&tmpB, d_tmpB);
    cudaGetSymbolAddress((void**)&qbuf, d_q);
    cudaGetSymbolAddress((void**)&fluo, d_fluo);

    // scalar normalizer 1/(N^4 * sum(pupil))
    zero_k<<<1, 1>>>();
    reduce_pupil<<<256, 256>>>(pupil);
    calc_c<<<1, 1>>>();

    // render path
    xyfeat_kernel<<<NPIX / 256, 256>>>(grid, lerp, x0, y0, x1, y1);
    mlp_kernel<<<dim3(512, ZM), 256>>>(z, zdat, w1, b1, w2, b2, w3, b3);

    dim3 gr(WDIM, ZM);       // row passes: one 512-pt FFT per block
    dim3 gc(WDIM / 8, ZM);   // col passes: 8 columns per block

    // pupil path: A = G(P); q = |A|^2
    fft_row<-1, 0><<<gr, 256>>>(pupil, aberr, nullptr, tmpA);
    fft_col<-1, 0><<<gc, 256>>>(tmpA, nullptr, qbuf, nullptr);

    // Bq = F(q)
    fft_row<+1, 1><<<gr, 256>>>(qbuf, nullptr, nullptr, tmpB);
    fft_col<+1, 1><<<gc, 256>>>(tmpB, tmpA, nullptr, nullptr);   // Bq -> tmpA

    // O = F(fluo); C = O * Bq * cscale  (fused into col pass, in-place)
    fft_row<+1, 1><<<gr, 256>>>(fluo, nullptr, nullptr, tmpB);
    fft_col<+1, 2><<<gc, 256>>>(tmpB, tmpB, nullptr, tmpA);

    // out = Re(G(C))
    fft_row<-1, 2><<<gr, 256>>>(nullptr, nullptr, tmpB, tmpB);
    fft_col<-1, 3><<<gc, 256>>>(tmpB, nullptr, out, nullptr);
}

// round 2
// speedup vs baseline: 1.6265x; 1.6265x over previous
#include <cuda_runtime.h>
#include <cstdint>

#define WDIM 512
#define NPIX (512*512)
#define ZM 30
#define NZP (ZM/2)

typedef unsigned long long ull;

// ---------------- device scratch ----------------
__device__ __align__(16) float2 d_tmpA[(size_t)ZM * NPIX];   // 63 MB
__device__ __align__(16) float2 d_tmpB[(size_t)ZM * NPIX];   // 63 MB
__device__ __align__(16) float  d_q   [(size_t)ZM * NPIX];   // 31.5 MB
__device__ __align__(16) float  d_fluo[(size_t)ZM * NPIX];   // 31.5 MB (reused as Cbuf)
__device__ __align__(16) float  d_xyf [(size_t)NPIX * 16];   // 16 MB
__device__ int   d_psum;
__device__ float d_cscale;

// ---------------- f32x2 helpers ----------------
__device__ __forceinline__ ull pk(float lo, float hi) {
    ull r; asm("mov.b64 %0, {%1,%2};" : "=l"(r) : "f"(lo), "f"(hi)); return r;
}
__device__ __forceinline__ void upk(ull v, float& lo, float& hi) {
    asm("mov.b64 {%0,%1}, %2;" : "=f"(lo), "=f"(hi) : "l"(v));
}
__device__ __forceinline__ ull fma2(ull a, ull b, ull c) {
    ull d; asm("fma.rn.f32x2 %0, %1, %2, %3;" : "=l"(d) : "l"(a), "l"(b), "l"(c)); return d;
}
__device__ __forceinline__ ull mul2(ull a, ull b) {
    ull d; asm("mul.rn.f32x2 %0, %1, %2;" : "=l"(d) : "l"(a), "l"(b)); return d;
}
__device__ __forceinline__ ull relu2(ull v) {
    float a, b; upk(v, a, b);
    a = fmaxf(a, 0.0f); b = fmaxf(b, 0.0f);
    return pk(a, b);
}

// ---------------- complex helpers ----------------
__device__ __forceinline__ float2 cmul(float2 a, float2 b) {
    return make_float2(fmaf(a.x, b.x, -a.y * b.y), fmaf(a.x, b.y, a.y * b.x));
}
__device__ __forceinline__ float2 cadd(float2 a, float2 b) { return make_float2(a.x + b.x, a.y + b.y); }
__device__ __forceinline__ float2 csub(float2 a, float2 b) { return make_float2(a.x - b.x, a.y - b.y); }

__device__ __forceinline__ int brev3(int j) { return ((j & 1) << 2) | (j & 2) | ((j >> 2) & 1); }
__device__ __forceinline__ int brev6(int t) { return (int)(__brev((unsigned)t) >> 26); }

#define PADI(p) ((p) + ((p) >> 5))
#define CSTRIDE 532

// ---------------- radix-8 butterfly (3 radix-2 DIT stages fused) ----------------
// r = k/(4h). DIR=+1: e^{-i}; DIR=-1: e^{+i}.
template<int DIR>
__device__ __forceinline__ void bf8(float2 e[8], float r)
{
    const float d = (DIR > 0) ? 1.0f : -1.0f;
    float s1, c1, s2, c2, s4, c4;
    sincospif(r,        &s1, &c1);
    sincospif(2.0f * r, &s2, &c2);
    sincospif(4.0f * r, &s4, &c4);
    float2 t1 = make_float2(c1, -d * s1);
    float2 t2 = make_float2(c2, -d * s2);
    float2 t4 = make_float2(c4, -d * s4);

    // stage A: pairs (0,1)(2,3)(4,5)(6,7), tw = t4
    float2 f[8];
    #pragma unroll
    for (int m = 0; m < 4; m++) {
        float2 v = cmul(e[2 * m + 1], t4);
        f[2 * m]     = cadd(e[2 * m], v);
        f[2 * m + 1] = csub(e[2 * m], v);
    }
    // stage B: pairs (j, j+2), tw: b=0 -> t2, b=1 -> (-i*d)*t2
    float2 wb1 = make_float2(d * t2.y, -d * t2.x);
    float2 g[8];
    #pragma unroll
    for (int h = 0; h < 2; h++) {
        int o = 4 * h;
        float2 v0 = cmul(f[o + 2], t2);
        float2 v1 = cmul(f[o + 3], wb1);
        g[o + 0] = cadd(f[o + 0], v0); g[o + 2] = csub(f[o + 0], v0);
        g[o + 1] = cadd(f[o + 1], v1); g[o + 3] = csub(f[o + 1], v1);
    }
    // stage C: pairs (j, j+4), tw = W8^j * t1
    const float S2 = 0.70710678118654752f;
    float2 wc1 = make_float2(S2 * (t1.x + d * t1.y), S2 * (t1.y - d * t1.x));
    float2 wc2 = make_float2(d * t1.y, -d * t1.x);
    float2 wc3 = make_float2(S2 * (-t1.x + d * t1.y), S2 * (-t1.y - d * t1.x));
    float2 v0 = cmul(g[4], t1);
    float2 v1 = cmul(g[5], wc1);
    float2 v2 = cmul(g[6], wc2);
    float2 v3 = cmul(g[7], wc3);
    e[0] = cadd(g[0], v0); e[4] = csub(g[0], v0);
    e[1] = cadd(g[1], v1); e[5] = csub(g[1], v1);
    e[2] = cadd(g[2], v2); e[6] = csub(g[2], v2);
    e[3] = cadd(g[3], v3); e[7] = csub(g[3], v3);
}

// ---------------- pupil sum (deterministic int reduction) ----------------
__global__ void zero_k() { d_psum = 0; }

__global__ void reduce_pupil(const float* __restrict__ pupil) {
    int i = blockIdx.x * blockDim.x + threadIdx.x;
    int v = 0;
    for (; i < NPIX; i += gridDim.x * blockDim.x)
        v += (pupil[i] > 0.5f) ? 1 : 0;
    #pragma unroll
    for (int o = 16; o; o >>= 1) v += __shfl_xor_sync(0xffffffffu, v, o);
    if ((threadIdx.x & 31) == 0) atomicAdd(&d_psum, v);
}

__global__ void calc_c() {
    // c = 1 / (N^4 * sum_pupil),  N^2 = 262144 -> N^4 = 68719476736
    d_cscale = (float)(1.0 / (68719476736.0 * (double)d_psum));
}

// ---------------- bilinear xy_feat (z-independent) ----------------
__global__ void __launch_bounds__(256) xyfeat_kernel(
    const float* __restrict__ grid, const float* __restrict__ lerp,
    const int* __restrict__ x0, const int* __restrict__ y0,
    const int* __restrict__ x1, const int* __restrict__ y1)
{
    int p = blockIdx.x * 256 + threadIdx.x;
    float2 l = ((const float2*)lerp)[p];
    float lx = l.x, ly = l.y;
    int X0 = x0[p], Y0 = y0[p], X1 = x1[p], Y1 = y1[p];
    float w00 = (1.f - lx) * (1.f - ly);
    float w10 = lx * (1.f - ly);
    float w01 = (1.f - lx) * ly;
    float w11 = lx * ly;
    const float4* g00 = (const float4*)(grid + ((size_t)Y0 * WDIM + X0) * 16);
    const float4* g10 = (const float4*)(grid + ((size_t)Y0 * WDIM + X1) * 16);
    const float4* g01 = (const float4*)(grid + ((size_t)Y1 * WDIM + X0) * 16);
    const float4* g11 = (const float4*)(grid + ((size_t)Y1 * WDIM + X1) * 16);
    float4* o = (float4*)(d_xyf + (size_t)p * 16);
    #pragma unroll
    for (int q = 0; q < 4; q++) {
        float4 a = g00[q], b = g10[q], c = g01[q], d = g11[q];
        float4 r;
        r.x = a.x * w00 + b.x * w10 + c.x * w01 + d.x * w11;
        r.y = a.y * w00 + b.y * w10 + c.y * w01 + d.y * w11;
        r.z = a.z * w00 + b.z * w10 + c.z * w01 + d.z * w11;
        r.w = a.w * w00 + b.w * w10 + c.w * w01 + d.w * w11;
        o[q] = r;
    }
}

// ---------------- fused 3-layer MLP, 2 pixels/thread via f32x2 ----------------
__global__ void __launch_bounds__(256, 1) mlp_kernel(
    const float* __restrict__ zarr, const float* __restrict__ zdat,
    const float* __restrict__ w1, const float* __restrict__ b1,
    const float* __restrict__ w2, const float* __restrict__ b2,
    const float* __restrict__ w3, const float* __restrict__ b3)
{
    __shared__ __align__(16) ull w1p[16 * 32];
    __shared__ __align__(16) ull w2p[32 * 32];
    __shared__ __align__(16) ull w3p[32];
    __shared__ ull b1p[32], b2p[32], zfp[16];
    __shared__ float b3s;

    int tid = threadIdx.x;
    int z = blockIdx.y;

    {
        float v = w1[tid];        w1p[tid]       = pk(v, v);
        v = w1[tid + 256];        w1p[tid + 256] = pk(v, v);
        #pragma unroll
        for (int q = 0; q < 4; q++) {
            v = w2[tid + q * 256]; w2p[tid + q * 256] = pk(v, v);
        }
        if (tid < 32) {
            float bb = b1[tid]; b1p[tid] = pk(bb, bb);
            bb = b2[tid];       b2p[tid] = pk(bb, bb);
            bb = w3[tid];       w3p[tid] = pk(bb, bb);
        }
        if (tid == 0) b3s = b3[0];
        if (tid < 16) {
            float zv = zarr[z];
            float zn = (29.0f * zv) / 30.0f;
            float zfl = floorf(zn);
            int z0 = (int)zfl; z0 = min(max(z0, 0), ZM - 1);
            int z1 = min(z0 + 1, ZM - 1);
            float zl = zn - zfl;
            float v2 = zdat[z0 * 16 + tid] * (1.0f - zl) + zdat[z1 * 16 + tid] * zl;
            zfp[tid] = pk(v2, v2);
        }
    }
    __syncthreads();

    int pp = blockIdx.x * 256 + tid;        // pixel pair index
    size_t px = (size_t)pp * 2;

    const float4* xp = (const float4*)(d_xyf + px * 16);
    float A[16], B[16];
    #pragma unroll
    for (int q = 0; q < 4; q++) {
        float4 t = xp[q];
        A[q * 4] = t.x; A[q * 4 + 1] = t.y; A[q * 4 + 2] = t.z; A[q * 4 + 3] = t.w;
    }
    #pragma unroll
    for (int q = 0; q < 4; q++) {
        float4 t = xp[4 + q];
        B[q * 4] = t.x; B[q * 4 + 1] = t.y; B[q * 4 + 2] = t.z; B[q * 4 + 3] = t.w;
    }

    ull f[16];
    #pragma unroll
    for (int k = 0; k < 16; k++) f[k] = mul2(pk(A[k], B[k]), zfp[k]);

    // layer 1: 16 -> 32
    ull h[32];
    #pragma unroll
    for (int j = 0; j < 32; j++) h[j] = b1p[j];
    #pragma unroll
    for (int k = 0; k < 16; k++) {
        ull fk = f[k];
        const ulonglong2* wp = (const ulonglong2*)(w1p + k * 32);
        #pragma unroll
        for (int j = 0; j < 16; j++) {
            ulonglong2 ww = wp[j];
            h[2 * j]     = fma2(fk, ww.x, h[2 * j]);
            h[2 * j + 1] = fma2(fk, ww.y, h[2 * j + 1]);
        }
    }
    #pragma unroll
    for (int j = 0; j < 32; j++) h[j] = relu2(h[j]);

    // layer 2: 32 -> 32
    ull g[32];
    #pragma unroll
    for (int j = 0; j < 32; j++) g[j] = b2p[j];
    #pragma unroll
    for (int k = 0; k < 32; k++) {
        ull hk = h[k];
        const ulonglong2* wp = (const ulonglong2*)(w2p + k * 32);
        #pragma unroll
        for (int j = 0; j < 16; j++) {
            ulonglong2 ww = wp[j];
            g[2 * j]     = fma2(hk, ww.x, g[2 * j]);
            g[2 * j + 1] = fma2(hk, ww.y, g[2 * j + 1]);
        }
    }
    #pragma unroll
    for (int j = 0; j < 32; j++) g[j] = relu2(g[j]);

    // layer 3: 32 -> 1
    ull acc = pk(b3s, b3s);
    #pragma unroll
    for (int j = 0; j < 32; j++) acc = fma2(g[j], w3p[j], acc);

    float o0, o1; upk(acc, o0, o1);
    *(float2*)(d_fluo + (size_t)z * NPIX + px) = make_float2(o0, o1);
}

// ---------------- radix-8 row pass ----------------
// 64 threads per 512-pt FFT, 4 rows per block.
// MODE 0: build P = pupil * exp(i*aberr)                 (DIR=-1, zp in [0,30))
// MODE 1: pack real plane pair (rin[2zp], rin[2zp+1])    (DIR=+1, zp in [0,15))
// MODE 2: Hermitian cross-spectrum C_a + i*C_b from Sq,So (DIR=-1, zp in [0,15))
template<int DIR, int MODE>
__global__ void __launch_bounds__(256) fft_row8(
    const float* __restrict__ rin, const float* __restrict__ aberr,
    const float2* __restrict__ cSq, const float2* __restrict__ cSo,
    float2* __restrict__ cout)
{
    __shared__ float2 sm[4][CSTRIDE];
    int tid = threadIdx.x;
    int u = tid >> 6, t = tid & 63;
    int r = blockIdx.x * 4 + u;
    int zp = blockIdx.y;
    size_t zb = (size_t)zp * NPIX;
    size_t rb = zb + (size_t)r * WDIM;

    float2 e[8];
    if (MODE == 0) {
        #pragma unroll
        for (int j = 0; j < 8; j++) {
            int n = t + 64 * j;
            float p = rin[(size_t)r * WDIM + n];
            float ab = aberr[rb + n];
            float sn, cs; __sincosf(ab, &sn, &cs);
            e[brev3(j)] = make_float2(p * cs, p * sn);
        }
    } else if (MODE == 1) {
        size_t b0 = (size_t)(2 * zp) * NPIX + (size_t)r * WDIM;
        size_t b1 = b0 + NPIX;
        #pragma unroll
        for (int j = 0; j < 8; j++) {
            int n = t + 64 * j;
            e[brev3(j)] = make_float2(rin[b0 + n], rin[b1 + n]);
        }
    } else {
        int rn = (WDIM - r) & (WDIM - 1);
        size_t rbm = zb + (size_t)rn * WDIM;
        float s = 0.25f * d_cscale;
        #pragma unroll
        for (int j = 0; j < 8; j++) {
            int n = t + 64 * j;
            int nn = (WDIM - n) & (WDIM - 1);
            float2 So  = cSo[rb + n],  Som = cSo[rbm + nn];
            float2 Sq  = cSq[rb + n],  Sqm = cSq[rbm + nn];
            float2 Po = make_float2(So.x + Som.x, So.y - Som.y);   // So + conj(Som)
            float2 Mo = make_float2(So.x - Som.x, So.y + Som.y);   // So - conj(Som)
            float2 Pq = make_float2(Sq.x + Sqm.x, Sq.y - Sqm.y);
            float2 Mq = make_float2(Sq.x - Sqm.x, Sq.y + Sqm.y);
            float2 PP = cmul(Po, Pq);
            float2 MM = cmul(Mo, Mq);
            // C_a + i C_b = 0.25*c*(PP - i*MM)
            e[brev3(j)] = make_float2(s * (PP.x + MM.y), s * (PP.y - MM.x));
        }
    }

    bf8<DIR>(e, 0.0f);
    int b = brev6(t);
    #pragma unroll
    for (int j = 0; j < 8; j++) { int p = 8 * b + j; sm[u][PADI(p)] = e[j]; }
    __syncthreads();

    int b2 = t >> 3, k = t & 7;
    #pragma unroll
    for (int j = 0; j < 8; j++) { int p = b2 * 64 + j * 8 + k; e[j] = sm[u][PADI(p)]; }
    bf8<DIR>(e, (float)k * (1.0f / 32.0f));
    #pragma unroll
    for (int j = 0; j < 8; j++) { int p = b2 * 64 + j * 8 + k; sm[u][PADI(p)] = e[j]; }
    __syncthreads();

    #pragma unroll
    for (int j = 0; j < 8; j++) { int p = j * 64 + t; e[j] = sm[u][PADI(p)]; }
    bf8<DIR>(e, (float)t * (1.0f / 256.0f));

    #pragma unroll
    for (int j = 0; j < 8; j++) cout[rb + j * 64 + t] = e[j];
}

// ---------------- radix-8 column pass ----------------
// 512 threads, 8 columns per block (one 64-thread FFT unit per column).
// MODE 0: write |v|^2 real to rout[zp]        (DIR=-1)
// MODE 1: write complex to cout               (in-place safe)
// MODE 2: split: rout[2zp]=Re, rout[2zp+1]=Im (DIR=-1)
template<int DIR, int MODE>
__global__ void __launch_bounds__(512) fft_col8(
    const float2* __restrict__ in, float2* __restrict__ cout, float* __restrict__ rout)
{
    __shared__ float2 sm[8 * CSTRIDE];
    int tid = threadIdx.x;
    int zp = blockIdx.y;
    int col0 = blockIdx.x * 8;
    size_t zb = (size_t)zp * NPIX;

    #pragma unroll
    for (int q = 0; q < 8; q++) {
        int l = tid + q * 512;
        int c = l & 7, i = l >> 3;
        sm[c * CSTRIDE + PADI(i)] = in[zb + (size_t)i * WDIM + col0 + c];
    }
    __syncthreads();

    int u = tid >> 6, t = tid & 63;
    float2* s = sm + u * CSTRIDE;
    float2 e[8];
    #pragma unroll
    for (int j = 0; j < 8; j++) { int n = t + 64 * j; e[brev3(j)] = s[PADI(n)]; }
    bf8<DIR>(e, 0.0f);
    __syncthreads();
    int b = brev6(t);
    #pragma unroll
    for (int j = 0; j < 8; j++) { int p = 8 * b + j; s[PADI(p)] = e[j]; }
    __syncthreads();

    int b2 = t >> 3, k = t & 7;
    #pragma unroll
    for (int j = 0; j < 8; j++) { int p = b2 * 64 + j * 8 + k; e[j] = s[PADI(p)]; }
    bf8<DIR>(e, (float)k * (1.0f / 32.0f));
    #pragma unroll
    for (int j = 0; j < 8; j++) { int p = b2 * 64 + j * 8 + k; s[PADI(p)] = e[j]; }
    __syncthreads();

    #pragma unroll
    for (int j = 0; j < 8; j++) { int p = j * 64 + t; e[j] = s[PADI(p)]; }
    bf8<DIR>(e, (float)t * (1.0f / 256.0f));
    #pragma unroll
    for (int j = 0; j < 8; j++) { int p = j * 64 + t; s[PADI(p)] = e[j]; }
    __syncthreads();

    #pragma unroll
    for (int q = 0; q < 8; q++) {
        int l = tid + q * 512;
        int c = l & 7, i = l >> 3;
        float2 v = sm[c * CSTRIDE + PADI(i)];
        size_t sp = (size_t)i * WDIM + col0 + c;
        if (MODE == 0) {
            rout[zb + sp] = v.x * v.x + v.y * v.y;
        } else if (MODE == 1) {
            cout[zb + sp] = v;
        } else {
            rout[(size_t)(2 * zp) * NPIX + sp]     = v.x;
            rout[(size_t)(2 * zp + 1) * NPIX + sp] = v.y;
        }
    }
}

// ---------------- launcher ----------------
extern "C" void kernel_launch(void* const* d_in, const int* in_sizes, int n_in,
                              void* d_out, int out_size)
{
    const float* z     = (const float*)d_in[0];
    const float* grid  = (const float*)d_in[1];
    const float* zdat  = (const float*)d_in[2];
    const float* w1    = (const float*)d_in[3];
    const float* b1    = (const float*)d_in[4];
    const float* w2    = (const float*)d_in[5];
    const float* b2    = (const float*)d_in[6];
    const float* w3    = (const float*)d_in[7];
    const float* b3    = (const float*)d_in[8];
    const float* pupil = (const float*)d_in[9];
    const float* aberr = (const float*)d_in[10];
    const float* lerp  = (const float*)d_in[11];
    const int*   x0    = (const int*)d_in[12];
    const int*   y0    = (const int*)d_in[13];
    const int*   x1    = (const int*)d_in[14];
    const int*   y1    = (const int*)d_in[15];
    float* out = (float*)d_out;

    float2* tmpA; float2* tmpB; float* qbuf; float* fluo;
    cudaGetSymbolAddress((void**)&tmpA, d_tmpA);
    cudaGetSymbolAddress((void**)&tmpB, d_tmpB);
    cudaGetSymbolAddress((void**)&qbuf, d_q);
    cudaGetSymbolAddress((void**)&fluo, d_fluo);
    float2* Cbuf = (float2*)fluo;   // fluo reused after its forward FFT (15 cpx planes)

    // scalar normalizer 1/(N^4 * sum(pupil))
    zero_k<<<1, 1>>>();
    reduce_pupil<<<256, 256>>>(pupil);
    calc_c<<<1, 1>>>();

    // render path
    xyfeat_kernel<<<NPIX / 256, 256>>>(grid, lerp, x0, y0, x1, y1);
    mlp_kernel<<<dim3(512, ZM), 256>>>(z, zdat, w1, b1, w2, b2, w3, b3);

    dim3 grP(WDIM / 4, ZM);   // row pass, pupil path (30 planes)
    dim3 grH(WDIM / 4, NZP);  // row pass, packed (15 pairs)
    dim3 gcP(WDIM / 8, ZM);
    dim3 gcH(WDIM / 8, NZP);

    // pupil path: A = G2(P); q = |A|^2  (30 complex planes)
    fft_row8<-1, 0><<<grP, 256>>>(pupil, aberr, nullptr, nullptr, tmpA);
    fft_col8<-1, 0><<<gcP, 512>>>(tmpA, nullptr, qbuf);

    // Sq = F2(q) packed: 15 complex planes -> tmpA
    fft_row8<+1, 1><<<grH, 256>>>(qbuf, nullptr, nullptr, nullptr, tmpB);
    fft_col8<+1, 1><<<gcH, 512>>>(tmpB, tmpA, nullptr);

    // So = F2(fluo) packed: 15 complex planes -> tmpB (col pass in-place)
    fft_row8<+1, 1><<<grH, 256>>>(fluo, nullptr, nullptr, nullptr, tmpB);
    fft_col8<+1, 1><<<gcH, 512>>>(tmpB, tmpB, nullptr);

    // cross spectrum (Hermitian unpack + multiply + cscale) fused into inverse row pass
    fft_row8<-1, 2><<<grH, 256>>>(nullptr, nullptr, tmpA, tmpB, Cbuf);
    // inverse col pass, split packed planes into the 30 real output planes
    fft_col8<-1, 2><<<gcH, 512>>>(Cbuf, nullptr, out);
}

// round 3
// speedup vs baseline: 1.6819x; 1.0341x over previous
#include <cuda_runtime.h>
#include <cstdint>

#define WDIM 512
#define NPIX (512*512)
#define ZM 30
#define NZP (ZM/2)

typedef unsigned long long ull;

// ---------------- device scratch ----------------
__device__ __align__(16) float2 d_tmpA[(size_t)ZM * NPIX];   // 63 MB
__device__ __align__(16) float2 d_tmpB[(size_t)ZM * NPIX];   // 63 MB
__device__ __align__(16) float  d_q   [(size_t)ZM * NPIX];   // 31.5 MB (packed colFFT(q), 15 cpx planes)
__device__ __align__(16) float  d_fluo[(size_t)ZM * NPIX];   // 31.5 MB (reused as Cbuf)
__device__ __align__(16) float  d_xyf [(size_t)NPIX * 16];   // 16 MB
__device__ int   d_psum;
__device__ float d_cscale;

// ---------------- f32x2 helpers ----------------
__device__ __forceinline__ ull pk(float lo, float hi) {
    ull r; asm("mov.b64 %0, {%1,%2};" : "=l"(r) : "f"(lo), "f"(hi)); return r;
}
__device__ __forceinline__ void upk(ull v, float& lo, float& hi) {
    asm("mov.b64 {%0,%1}, %2;" : "=f"(lo), "=f"(hi) : "l"(v));
}
__device__ __forceinline__ ull fma2(ull a, ull b, ull c) {
    ull d; asm("fma.rn.f32x2 %0, %1, %2, %3;" : "=l"(d) : "l"(a), "l"(b), "l"(c)); return d;
}
__device__ __forceinline__ ull relu2(ull v) {
    float a, b; upk(v, a, b);
    a = fmaxf(a, 0.0f); b = fmaxf(b, 0.0f);
    return pk(a, b);
}

// ---------------- complex helpers ----------------
__device__ __forceinline__ float2 cmul(float2 a, float2 b) {
    return make_float2(fmaf(a.x, b.x, -a.y * b.y), fmaf(a.x, b.y, a.y * b.x));
}
__device__ __forceinline__ float2 cadd(float2 a, float2 b) { return make_float2(a.x + b.x, a.y + b.y); }
__device__ __forceinline__ float2 csub(float2 a, float2 b) { return make_float2(a.x - b.x, a.y - b.y); }

__device__ __forceinline__ int brev3(int j) { return ((j & 1) << 2) | (j & 2) | ((j >> 2) & 1); }
__device__ __forceinline__ int brev6(int t) { return (int)(__brev((unsigned)t) >> 26); }

#define PADI(p) ((p) + ((p) >> 5))
#define CSTRIDE 532

// ---------------- radix-8 butterflies ----------------
// bf8_0: first stage, all twiddles trivial (r = 0). DIR=+1 fwd e^{-i}, -1 inv.
template<int DIR>
__device__ __forceinline__ void bf8_0(float2 e[8])
{
    const float d = (DIR > 0) ? 1.0f : -1.0f;
    float2 f[8];
    #pragma unroll
    for (int m = 0; m < 4; m++) {
        float2 u = e[2 * m], v = e[2 * m + 1];
        f[2 * m]     = cadd(u, v);
        f[2 * m + 1] = csub(u, v);
    }
    float2 g[8];
    #pragma unroll
    for (int hh = 0; hh < 2; hh++) {
        int o = 4 * hh;
        float2 v0 = f[o + 2];
        float2 v1 = make_float2(d * f[o + 3].y, -d * f[o + 3].x);
        g[o + 0] = cadd(f[o + 0], v0); g[o + 2] = csub(f[o + 0], v0);
        g[o + 1] = cadd(f[o + 1], v1); g[o + 3] = csub(f[o + 1], v1);
    }
    const float S2 = 0.70710678118654752f;
    float2 v0 = g[4];
    float2 v1 = cmul(g[5], make_float2(S2, -d * S2));
    float2 v2 = make_float2(d * g[6].y, -d * g[6].x);
    float2 v3 = cmul(g[7], make_float2(-S2, -d * S2));
    e[0] = cadd(g[0], v0); e[4] = csub(g[0], v0);
    e[1] = cadd(g[1], v1); e[5] = csub(g[1], v1);
    e[2] = cadd(g[2], v2); e[6] = csub(g[2], v2);
    e[3] = cadd(g[3], v3); e[7] = csub(g[3], v3);
}

// bf8_g: general stage; one sincospif, t2/t4 by complex squaring.
template<int DIR>
__device__ __forceinline__ void bf8_g(float2 e[8], float r)
{
    const float d = (DIR > 0) ? 1.0f : -1.0f;
    float s1, c1;
    sincospif(r, &s1, &c1);
    float2 t1 = make_float2(c1, -d * s1);
    float2 t2 = cmul(t1, t1);
    float2 t4 = cmul(t2, t2);

    float2 f[8];
    #pragma unroll
    for (int m = 0; m < 4; m++) {
        float2 v = cmul(e[2 * m + 1], t4);
        f[2 * m]     = cadd(e[2 * m], v);
        f[2 * m + 1] = csub(e[2 * m], v);
    }
    float2 wb1 = make_float2(d * t2.y, -d * t2.x);
    float2 g[8];
    #pragma unroll
    for (int hh = 0; hh < 2; hh++) {
        int o = 4 * hh;
        float2 v0 = cmul(f[o + 2], t2);
        float2 v1 = cmul(f[o + 3], wb1);
        g[o + 0] = cadd(f[o + 0], v0); g[o + 2] = csub(f[o + 0], v0);
        g[o + 1] = cadd(f[o + 1], v1); g[o + 3] = csub(f[o + 1], v1);
    }
    const float S2 = 0.70710678118654752f;
    float2 wc1 = make_float2(S2 * (t1.x + d * t1.y), S2 * (t1.y - d * t1.x));
    float2 wc2 = make_float2(d * t1.y, -d * t1.x);
    float2 wc3 = make_float2(S2 * (-t1.x + d * t1.y), S2 * (-t1.y - d * t1.x));
    float2 v0 = cmul(g[4], t1);
    float2 v1 = cmul(g[5], wc1);
    float2 v2 = cmul(g[6], wc2);
    float2 v3 = cmul(g[7], wc3);
    e[0] = cadd(g[0], v0); e[4] = csub(g[0], v0);
    e[1] = cadd(g[1], v1); e[5] = csub(g[1], v1);
    e[2] = cadd(g[2], v2); e[6] = csub(g[2], v2);
    e[3] = cadd(g[3], v3); e[7] = csub(g[3], v3);
}

// 512-pt FFT unit: 64 threads, s = this unit's padded smem region.
// On entry e[brev3(j)] = input[t + 64j]; on exit e[j] = output[j*64 + t].
// PRESYNC: insert a sync between e-prep reads of s and the stage-1 stores.
template<int DIR, bool PRESYNC>
__device__ __forceinline__ void fft_unit(float2* s, float2 e[8], int t, bool active)
{
    if (active) bf8_0<DIR>(e);
    if (PRESYNC) __syncthreads();
    if (active) {
        int b = brev6(t);
        #pragma unroll
        for (int j = 0; j < 8; j++) s[PADI(8 * b + j)] = e[j];
    }
    __syncthreads();
    if (active) {
        int b2 = t >> 3, k = t & 7;
        #pragma unroll
        for (int j = 0; j < 8; j++) e[j] = s[PADI(b2 * 64 + j * 8 + k)];
        bf8_g<DIR>(e, (float)k * (1.0f / 32.0f));
        #pragma unroll
        for (int j = 0; j < 8; j++) s[PADI(b2 * 64 + j * 8 + k)] = e[j];
    }
    __syncthreads();
    if (active) {
        #pragma unroll
        for (int j = 0; j < 8; j++) e[j] = s[PADI(j * 64 + t)];
        bf8_g<DIR>(e, (float)t * (1.0f / 256.0f));
    }
}

// ---------------- pupil sum (deterministic int reduction) ----------------
__global__ void zero_k() { d_psum = 0; }

__global__ void reduce_pupil(const float* __restrict__ pupil) {
    int i = blockIdx.x * blockDim.x + threadIdx.x;
    int v = 0;
    for (; i < NPIX; i += gridDim.x * blockDim.x)
        v += (pupil[i] > 0.5f) ? 1 : 0;
    #pragma unroll
    for (int o = 16; o; o >>= 1) v += __shfl_xor_sync(0xffffffffu, v, o);
    if ((threadIdx.x & 31) == 0) atomicAdd(&d_psum, v);
}

__global__ void calc_c() {
    d_cscale = (float)(1.0 / (68719476736.0 * (double)d_psum));
}

// ---------------- bilinear xy_feat (z-independent) ----------------
__global__ void __launch_bounds__(256) xyfeat_kernel(
    const float* __restrict__ grid, const float* __restrict__ lerp,
    const int* __restrict__ x0, const int* __restrict__ y0,
    const int* __restrict__ x1, const int* __restrict__ y1)
{
    int p = blockIdx.x * 256 + threadIdx.x;
    float2 l = ((const float2*)lerp)[p];
    float lx = l.x, ly = l.y;
    int X0 = x0[p], Y0 = y0[p], X1 = x1[p], Y1 = y1[p];
    float w00 = (1.f - lx) * (1.f - ly);
    float w10 = lx * (1.f - ly);
    float w01 = (1.f - lx) * ly;
    float w11 = lx * ly;
    const float4* g00 = (const float4*)(grid + ((size_t)Y0 * WDIM + X0) * 16);
    const float4* g10 = (const float4*)(grid + ((size_t)Y0 * WDIM + X1) * 16);
    const float4* g01 = (const float4*)(grid + ((size_t)Y1 * WDIM + X0) * 16);
    const float4* g11 = (const float4*)(grid + ((size_t)Y1 * WDIM + X1) * 16);
    float4* o = (float4*)(d_xyf + (size_t)p * 16);
    #pragma unroll
    for (int q = 0; q < 4; q++) {
        float4 a = g00[q], b = g10[q], c = g01[q], d = g11[q];
        float4 r;
        r.x = a.x * w00 + b.x * w10 + c.x * w01 + d.x * w11;
        r.y = a.y * w00 + b.y * w10 + c.y * w01 + d.y * w11;
        r.z = a.z * w00 + b.z * w10 + c.z * w01 + d.z * w11;
        r.w = a.w * w00 + b.w * w10 + c.w * w01 + d.w * w11;
        o[q] = r;
    }
}

// ---------------- fused 3-layer MLP, 2 pixels/thread via f32x2 ----------------
// z_feat is absorbed into the smem copy of W1.
__global__ void __launch_bounds__(256, 1) mlp_kernel(
    const float* __restrict__ zarr, const float* __restrict__ zdat,
    const float* __restrict__ w1, const float* __restrict__ b1,
    const float* __restrict__ w2, const float* __restrict__ b2,
    const float* __restrict__ w3, const float* __restrict__ b3)
{
    __shared__ __align__(16) ull w1p[16 * 32];
    __shared__ __align__(16) ull w2p[32 * 32];
    __shared__ __align__(16) ull w3p[32];
    __shared__ ull b1p[32], b2p[32];
    __shared__ float b3s;

    int tid = threadIdx.x;
    int z = blockIdx.y;

    {
        float zv = zarr[z];
        float zn = (29.0f * zv) / 30.0f;
        float zfl = floorf(zn);
        int z0 = (int)zfl; z0 = min(max(z0, 0), ZM - 1);
        int z1 = min(z0 + 1, ZM - 1);
        float zl = zn - zfl;

        int k0 = tid >> 5;
        float zf0 = zdat[z0 * 16 + k0] * (1.0f - zl) + zdat[z1 * 16 + k0] * zl;
        float v = w1[tid] * zf0;          w1p[tid] = pk(v, v);
        int k1 = (tid + 256) >> 5;
        float zf1 = zdat[z0 * 16 + k1] * (1.0f - zl) + zdat[z1 * 16 + k1] * zl;
        v = w1[tid + 256] * zf1;          w1p[tid + 256] = pk(v, v);
        #pragma unroll
        for (int q = 0; q < 4; q++) {
            v = w2[tid + q * 256]; w2p[tid + q * 256] = pk(v, v);
        }
        if (tid < 32) {
            float bb = b1[tid]; b1p[tid] = pk(bb, bb);
            bb = b2[tid];       b2p[tid] = pk(bb, bb);
            bb = w3[tid];       w3p[tid] = pk(bb, bb);
        }
        if (tid == 0) b3s = b3[0];
    }
    __syncthreads();

    int pp = blockIdx.x * 256 + tid;        // pixel pair index
    size_t px = (size_t)pp * 2;

    const float4* xp = (const float4*)(d_xyf + px * 16);
    float A[16], B[16];
    #pragma unroll
    for (int q = 0; q < 4; q++) {
        float4 t = xp[q];
        A[q * 4] = t.x; A[q * 4 + 1] = t.y; A[q * 4 + 2] = t.z; A[q * 4 + 3] = t.w;
    }
    #pragma unroll
    for (int q = 0; q < 4; q++) {
        float4 t = xp[4 + q];
        B[q * 4] = t.x; B[q * 4 + 1] = t.y; B[q * 4 + 2] = t.z; B[q * 4 + 3] = t.w;
    }

    // layer 1: 16 -> 32 (weights pre-scaled by z_feat)
    ull h[32];
    #pragma unroll
    for (int j = 0; j < 32; j++) h[j] = b1p[j];
    #pragma unroll
    for (int k = 0; k < 16; k++) {
        ull fk = pk(A[k], B[k]);
        const ulonglong2* wp = (const ulonglong2*)(w1p + k * 32);
        #pragma unroll
        for (int j = 0; j < 16; j++) {
            ulonglong2 ww = wp[j];
            h[2 * j]     = fma2(fk, ww.x, h[2 * j]);
            h[2 * j + 1] = fma2(fk, ww.y, h[2 * j + 1]);
        }
    }
    #pragma unroll
    for (int j = 0; j < 32; j++) h[j] = relu2(h[j]);

    // layer 2: 32 -> 32
    ull g[32];
    #pragma unroll
    for (int j = 0; j < 32; j++) g[j] = b2p[j];
    #pragma unroll
    for (int k = 0; k < 32; k++) {
        ull hk = h[k];
        const ulonglong2* wp = (const ulonglong2*)(w2p + k * 32);
        #pragma unroll
        for (int j = 0; j < 16; j++) {
            ulonglong2 ww = wp[j];
            g[2 * j]     = fma2(hk, ww.x, g[2 * j]);
            g[2 * j + 1] = fma2(hk, ww.y, g[2 * j + 1]);
        }
    }
    #pragma unroll
    for (int j = 0; j < 32; j++) g[j] = relu2(g[j]);

    // layer 3: 32 -> 1
    ull acc = pk(b3s, b3s);
    #pragma unroll
    for (int j = 0; j < 32; j++) acc = fma2(g[j], w3p[j], acc);

    float o0, o1; upk(acc, o0, o1);
    *(float2*)(d_fluo + (size_t)z * NPIX + px) = make_float2(o0, o1);
}

// ---------------- radix-8 row pass: 512 threads, 8 rows per block ----------------
// MODE 0: build P = pupil * exp(i*aberr)                  (DIR=-1, zp in [0,30))
// MODE 1: pack real plane pair (rin[2zp], rin[2zp+1])     (DIR=+1, zp in [0,15))
// MODE 2: Hermitian cross-spectrum from cSq,cSo + IFFT    (DIR=-1, zp in [0,15))
// MODE 3: plain complex (cSq as input)                    (any DIR)
template<int DIR, int MODE>
__global__ void __launch_bounds__(512) fft_row8(
    const float* __restrict__ rin, const float* __restrict__ aberr,
    const float2* __restrict__ cSq, const float2* __restrict__ cSo,
    float2* __restrict__ cout)
{
    __shared__ float2 sm[8][CSTRIDE];
    int tid = threadIdx.x;
    int u = tid >> 6, t = tid & 63;
    int r = blockIdx.x * 8 + u;
    int zp = blockIdx.y;
    size_t zb = (size_t)zp * NPIX;
    size_t rb = zb + (size_t)r * WDIM;

    float2 e[8];
    if (MODE == 0) {
        #pragma unroll
        for (int j = 0; j < 8; j++) {
            int n = t + 64 * j;
            float p = rin[(size_t)r * WDIM + n];
            float ab = aberr[rb + n];
            float sn, cs; __sincosf(ab, &sn, &cs);
            e[brev3(j)] = make_float2(p * cs, p * sn);
        }
    } else if (MODE == 1) {
        size_t b0 = (size_t)(2 * zp) * NPIX + (size_t)r * WDIM;
        size_t b1 = b0 + NPIX;
        #pragma unroll
        for (int j = 0; j < 8; j++) {
            int n = t + 64 * j;
            e[brev3(j)] = make_float2(rin[b0 + n], rin[b1 + n]);
        }
    } else if (MODE == 2) {
        int rn = (WDIM - r) & (WDIM - 1);
        size_t rbm = zb + (size_t)rn * WDIM;
        float s = 0.25f * d_cscale;
        #pragma unroll
        for (int j = 0; j < 8; j++) {
            int n = t + 64 * j;
            int nn = (WDIM - n) & (WDIM - 1);
            float2 So  = cSo[rb + n],  Som = cSo[rbm + nn];
            float2 Sq  = cSq[rb + n],  Sqm = cSq[rbm + nn];
            float2 Po = make_float2(So.x + Som.x, So.y - Som.y);
            float2 Mo = make_float2(So.x - Som.x, So.y + Som.y);
            float2 Pq = make_float2(Sq.x + Sqm.x, Sq.y - Sqm.y);
            float2 Mq = make_float2(Sq.x - Sqm.x, Sq.y + Sqm.y);
            float2 PP = cmul(Po, Pq);
            float2 MM = cmul(Mo, Mq);
            e[brev3(j)] = make_float2(s * (PP.x + MM.y), s * (PP.y - MM.x));
        }
    } else {
        #pragma unroll
        for (int j = 0; j < 8; j++) {
            int n = t + 64 * j;
            e[brev3(j)] = cSq[rb + n];
        }
    }

    fft_unit<DIR, false>(&sm[u][0], e, t, true);

    #pragma unroll
    for (int j = 0; j < 8; j++) cout[rb + j * 64 + t] = e[j];
}

// ---------------- fused colQ pass ----------------
// 512 threads, 4 columns, plane pair (2zp, 2zp+1).
// Phase 1 (8 units): inverse col FFT of both planes' columns (A = G2(P) cols).
// Phase 2 (4 units): forward col FFT of packed |A0|^2 + i|A1|^2; write colF(q).
__global__ void __launch_bounds__(512) colq_kernel(
    const float2* __restrict__ in, float2* __restrict__ outp)
{
    __shared__ float2 sm[8 * CSTRIDE];
    int tid = threadIdx.x;
    int u = tid >> 6, t = tid & 63;
    int zp = blockIdx.y;
    int col0 = blockIdx.x * 4;

    // stage in both planes' 4 columns
    #pragma unroll
    for (int q = 0; q < 8; q++) {
        int idx = tid + q * 512;
        int c = idx & 3, pl = (idx >> 2) & 1, i = idx >> 3;
        sm[(pl * 4 + c) * CSTRIDE + PADI(i)] =
            in[(size_t)(2 * zp + pl) * NPIX + (size_t)i * WDIM + col0 + c];
    }
    __syncthreads();

    // phase 1: inverse FFT per unit (u -> plane u>>2, col u&3)
    float2* s = sm + u * CSTRIDE;
    float2 e[8];
    #pragma unroll
    for (int j = 0; j < 8; j++) e[brev3(j)] = s[PADI(t + 64 * j)];
    fft_unit<-1, true>(s, e, t, true);
    #pragma unroll
    for (int j = 0; j < 8; j++) s[PADI(j * 64 + t)] = e[j];
    __syncthreads();

    // phase 2: packed forward FFT (units 0..3; unit c reads planes c and 4+c)
    bool act = (u < 4);
    if (act) {
        float2* s0 = sm + u * CSTRIDE;
        float2* s1 = sm + (4 + u) * CSTRIDE;
        #pragma unroll
        for (int j = 0; j < 8; j++) {
            int n = t + 64 * j;
            float2 a0 = s0[PADI(n)];
            float2 a1 = s1[PADI(n)];
            e[brev3(j)] = make_float2(a0.x * a0.x + a0.y * a0.y,
                                      a1.x * a1.x + a1.y * a1.y);
        }
    }
    fft_unit<+1, true>(s, e, t, act);
    if (act) {
        #pragma unroll
        for (int j = 0; j < 8; j++) s[PADI(j * 64 + t)] = e[j];
    }
    __syncthreads();

    // store 4 cols x 512 rows of packed colF(q)
    #pragma unroll
    for (int q = 0; q < 4; q++) {
        int idx = tid + q * 512;
        int c = idx & 3, i = idx >> 2;
        outp[(size_t)zp * NPIX + (size_t)i * WDIM + col0 + c] =
            sm[c * CSTRIDE + PADI(i)];
    }
}

// ---------------- radix-8 column pass: 512 threads, 8 cols per block ----------------
// MODE 1: write complex to cout (in-place safe)
// MODE 2: split: rout[2zp]=Re, rout[2zp+1]=Im   (DIR=-1)
template<int DIR, int MODE>
__global__ void __launch_bounds__(512) fft_col8(
    const float2* __restrict__ in, float2* __restrict__ cout, float* __restrict__ rout)
{
    __shared__ float2 sm[8 * CSTRIDE];
    int tid = threadIdx.x;
    int zp = blockIdx.y;
    int col0 = blockIdx.x * 8;
    size_t zb = (size_t)zp * NPIX;

    #pragma unroll
    for (int q = 0; q < 8; q++) {
        int l = tid + q * 512;
        int c = l & 7, i = l >> 3;
        sm[c * CSTRIDE + PADI(i)] = in[zb + (size_t)i * WDIM + col0 + c];
    }
    __syncthreads();

    int u = tid >> 6, t = tid & 63;
    float2* s = sm + u * CSTRIDE;
    float2 e[8];
    #pragma unroll
    for (int j = 0; j < 8; j++) e[brev3(j)] = s[PADI(t + 64 * j)];
    fft_unit<DIR, true>(s, e, t, true);
    #pragma unroll
    for (int j = 0; j < 8; j++) s[PADI(j * 64 + t)] = e[j];
    __syncthreads();

    #pragma unroll
    for (int q = 0; q < 8; q++) {
        int l = tid + q * 512;
        int c = l & 7, i = l >> 3;
        float2 v = sm[c * CSTRIDE + PADI(i)];
        size_t sp = (size_t)i * WDIM + col0 + c;
        if (MODE == 1) {
            cout[zb + sp] = v;
        } else {
            rout[(size_t)(2 * zp) * NPIX + sp]     = v.x;
            rout[(size_t)(2 * zp + 1) * NPIX + sp] = v.y;
        }
    }
}

// ---------------- launcher ----------------
extern "C" void kernel_launch(void* const* d_in, const int* in_sizes, int n_in,
                              void* d_out, int out_size)
{
    const float* z     = (const float*)d_in[0];
    const float* grid  = (const float*)d_in[1];
    const float* zdat  = (const float*)d_in[2];
    const float* w1    = (const float*)d_in[3];
    const float* b1    = (const float*)d_in[4];
    const float* w2    = (const float*)d_in[5];
    const float* b2    = (const float*)d_in[6];
    const float* w3    = (const float*)d_in[7];
    const float* b3    = (const float*)d_in[8];
    const float* pupil = (const float*)d_in[9];
    const float* aberr = (const float*)d_in[10];
    const float* lerp  = (const float*)d_in[11];
    const int*   x0    = (const int*)d_in[12];
    const int*   y0    = (const int*)d_in[13];
    const int*   x1    = (const int*)d_in[14];
    const int*   y1    = (const int*)d_in[15];
    float* out = (float*)d_out;

    float2* tmpA; float2* tmpB; float* qbuf; float* fluo;
    cudaGetSymbolAddress((void**)&tmpA, d_tmpA);
    cudaGetSymbolAddress((void**)&tmpB, d_tmpB);
    cudaGetSymbolAddress((void**)&qbuf, d_q);
    cudaGetSymbolAddress((void**)&fluo, d_fluo);
    float2* qcol = (float2*)qbuf;     // packed colF(q), 15 complex planes
    float2* Cbuf = (float2*)fluo;     // reuse fluo after its forward FFT

    // scalar normalizer 1/(N^4 * sum(pupil))
    zero_k<<<1, 1>>>();
    reduce_pupil<<<256, 256>>>(pupil);
    calc_c<<<1, 1>>>();

    // render path
    xyfeat_kernel<<<NPIX / 256, 256>>>(grid, lerp, x0, y0, x1, y1);
    mlp_kernel<<<dim3(512, ZM), 256>>>(z, zdat, w1, b1, w2, b2, w3, b3);

    dim3 grP(WDIM / 8, ZM);    // row pass, 30 planes
    dim3 grH(WDIM / 8, NZP);   // row pass, 15 pairs
    dim3 gq(WDIM / 4, NZP);    // fused colQ
    dim3 gcH(WDIM / 8, NZP);   // col pass, 15 pairs

    // pupil path: rowIFFT(P) -> tmpA (30 planes)
    fft_row8<-1, 0><<<grP, 512>>>(pupil, aberr, nullptr, nullptr, tmpA);
    // fused: col IFFT x2, |.|^2, packed forward col FFT -> qcol (15 planes)
    colq_kernel<<<gq, 512>>>(tmpA, qcol);
    // finish Sq = rowFFT(qcol) -> tmpA (15 planes)
    fft_row8<+1, 3><<<grH, 512>>>(nullptr, nullptr, qcol, nullptr, tmpA);

    // So = F2(fluo) packed -> tmpB (col pass in-place)
    fft_row8<+1, 1><<<grH, 512>>>(fluo, nullptr, nullptr, nullptr, tmpB);
    fft_col8<+1, 1><<<gcH, 512>>>(tmpB, tmpB, nullptr);

    // cross spectrum (Hermitian unpack + multiply + cscale) fused into inverse row pass
    fft_row8<-1, 2><<<grH, 512>>>(nullptr, nullptr, tmpA, tmpB, Cbuf);
    // inverse col pass, split packed planes into the 30 real output planes
    fft_col8<-1, 2><<<gcH, 512>>>(Cbuf, nullptr, out);
}

// round 4
// speedup vs baseline: 1.6916x; 1.0058x over previous
#include <cuda_runtime.h>
#include <cstdint>

#define WDIM 512
#define NPIX (512*512)
#define ZM 30
#define NZP (ZM/2)

typedef unsigned long long ull;

// ---------------- device scratch ----------------
__device__ __align__(16) float2 d_tmpA[(size_t)ZM * NPIX];   // 63 MB
__device__ __align__(16) float2 d_tmpB[(size_t)ZM * NPIX];   // 63 MB
__device__ __align__(16) float  d_q   [(size_t)ZM * NPIX];   // packed colFFT(q), 15 cpx planes
__device__ __align__(16) float  d_fluo[(size_t)ZM * NPIX];   // fluo, reused as Cbuf
__device__ __align__(16) float  d_xyf [(size_t)NPIX * 16];   // 16 MB
__device__ int   d_part[256];
__device__ float d_cscale;

// ---------------- f32x2 helpers ----------------
__device__ __forceinline__ ull pk(float lo, float hi) {
    ull r; asm("mov.b64 %0, {%1,%2};" : "=l"(r) : "f"(lo), "f"(hi)); return r;
}
__device__ __forceinline__ void upk(ull v, float& lo, float& hi) {
    asm("mov.b64 {%0,%1}, %2;" : "=f"(lo), "=f"(hi) : "l"(v));
}
__device__ __forceinline__ ull fma2(ull a, ull b, ull c) {
    ull d; asm("fma.rn.f32x2 %0, %1, %2, %3;" : "=l"(d) : "l"(a), "l"(b), "l"(c)); return d;
}
__device__ __forceinline__ ull relu2(ull v) {
    float a, b; upk(v, a, b);
    a = fmaxf(a, 0.0f); b = fmaxf(b, 0.0f);
    return pk(a, b);
}

// ---------------- complex helpers ----------------
__device__ __forceinline__ float2 cmul(float2 a, float2 b) {
    return make_float2(fmaf(a.x, b.x, -a.y * b.y), fmaf(a.x, b.y, a.y * b.x));
}
__device__ __forceinline__ float2 cadd(float2 a, float2 b) { return make_float2(a.x + b.x, a.y + b.y); }
__device__ __forceinline__ float2 csub(float2 a, float2 b) { return make_float2(a.x - b.x, a.y - b.y); }

__device__ __forceinline__ int brev3(int j) { return ((j & 1) << 2) | (j & 2) | ((j >> 2) & 1); }
__device__ __forceinline__ int brev6(int t) { return (int)(__brev((unsigned)t) >> 26); }

#define PADI(p) ((p) + ((p) >> 5))
#define CSTRIDE 532

// ---------------- radix-8 butterflies ----------------
template<int DIR>
__device__ __forceinline__ void bf8_0(float2 e[8])
{
    const float d = (DIR > 0) ? 1.0f : -1.0f;
    float2 f[8];
    #pragma unroll
    for (int m = 0; m < 4; m++) {
        float2 u = e[2 * m], v = e[2 * m + 1];
        f[2 * m]     = cadd(u, v);
        f[2 * m + 1] = csub(u, v);
    }
    float2 g[8];
    #pragma unroll
    for (int hh = 0; hh < 2; hh++) {
        int o = 4 * hh;
        float2 v0 = f[o + 2];
        float2 v1 = make_float2(d * f[o + 3].y, -d * f[o + 3].x);
        g[o + 0] = cadd(f[o + 0], v0); g[o + 2] = csub(f[o + 0], v0);
        g[o + 1] = cadd(f[o + 1], v1); g[o + 3] = csub(f[o + 1], v1);
    }
    const float S2 = 0.70710678118654752f;
    float2 v0 = g[4];
    float2 v1 = cmul(g[5], make_float2(S2, -d * S2));
    float2 v2 = make_float2(d * g[6].y, -d * g[6].x);
    float2 v3 = cmul(g[7], make_float2(-S2, -d * S2));
    e[0] = cadd(g[0], v0); e[4] = csub(g[0], v0);
    e[1] = cadd(g[1], v1); e[5] = csub(g[1], v1);
    e[2] = cadd(g[2], v2); e[6] = csub(g[2], v2);
    e[3] = cadd(g[3], v3); e[7] = csub(g[3], v3);
}

template<int DIR>
__device__ __forceinline__ void bf8_g(float2 e[8], float r)
{
    const float d = (DIR > 0) ? 1.0f : -1.0f;
    float s1, c1;
    sincospif(r, &s1, &c1);
    float2 t1 = make_float2(c1, -d * s1);
    float2 t2 = cmul(t1, t1);
    float2 t4 = cmul(t2, t2);

    float2 f[8];
    #pragma unroll
    for (int m = 0; m < 4; m++) {
        float2 v = cmul(e[2 * m + 1], t4);
        f[2 * m]     = cadd(e[2 * m], v);
        f[2 * m + 1] = csub(e[2 * m], v);
    }
    float2 wb1 = make_float2(d * t2.y, -d * t2.x);
    float2 g[8];
    #pragma unroll
    for (int hh = 0; hh < 2; hh++) {
        int o = 4 * hh;
        float2 v0 = cmul(f[o + 2], t2);
        float2 v1 = cmul(f[o + 3], wb1);
        g[o + 0] = cadd(f[o + 0], v0); g[o + 2] = csub(f[o + 0], v0);
        g[o + 1] = cadd(f[o + 1], v1); g[o + 3] = csub(f[o + 1], v1);
    }
    const float S2 = 0.70710678118654752f;
    float2 wc1 = make_float2(S2 * (t1.x + d * t1.y), S2 * (t1.y - d * t1.x));
    float2 wc2 = make_float2(d * t1.y, -d * t1.x);
    float2 wc3 = make_float2(S2 * (-t1.x + d * t1.y), S2 * (-t1.y - d * t1.x));
    float2 v0 = cmul(g[4], t1);
    float2 v1 = cmul(g[5], wc1);
    float2 v2 = cmul(g[6], wc2);
    float2 v3 = cmul(g[7], wc3);
    e[0] = cadd(g[0], v0); e[4] = csub(g[0], v0);
    e[1] = cadd(g[1], v1); e[5] = csub(g[1], v1);
    e[2] = cadd(g[2], v2); e[6] = csub(g[2], v2);
    e[3] = cadd(g[3], v3); e[7] = csub(g[3], v3);
}

// 512-pt FFT unit: 64 threads on padded smem region s.
// Entry: e[brev3(j)] = input[t + 64j]. Exit: e[j] = output[j*64 + t].
template<int DIR, bool PRESYNC>
__device__ __forceinline__ void fft_unit(float2* s, float2 e[8], int t, bool active)
{
    if (active) bf8_0<DIR>(e);
    if (PRESYNC) __syncthreads();
    if (active) {
        int b = brev6(t);
        #pragma unroll
        for (int j = 0; j < 8; j++) s[PADI(8 * b + j)] = e[j];
    }
    __syncthreads();
    if (active) {
        int b2 = t >> 3, k = t & 7;
        #pragma unroll
        for (int j = 0; j < 8; j++) e[j] = s[PADI(b2 * 64 + j * 8 + k)];
        bf8_g<DIR>(e, (float)k * (1.0f / 32.0f));
        #pragma unroll
        for (int j = 0; j < 8; j++) s[PADI(b2 * 64 + j * 8 + k)] = e[j];
    }
    __syncthreads();
    if (active) {
        #pragma unroll
        for (int j = 0; j < 8; j++) e[j] = s[PADI(j * 64 + t)];
        bf8_g<DIR>(e, (float)t * (1.0f / 256.0f));
    }
}

// ---------------- pupil sum (2-kernel deterministic reduction) ----------------
__global__ void __launch_bounds__(256) pupil_part(const float* __restrict__ pupil) {
    int tid = threadIdx.x, b = blockIdx.x;
    int v = 0;
    for (int i = b * 1024 + tid; i < (b + 1) * 1024 && false; ) {}
    #pragma unroll 4
    for (int q = 0; q < 4; q++) {
        int i = b * 1024 + q * 256 + tid;
        v += (pupil[i] > 0.5f) ? 1 : 0;
    }
    #pragma unroll
    for (int o = 16; o; o >>= 1) v += __shfl_xor_sync(0xffffffffu, v, o);
    __shared__ int ws[8];
    if ((tid & 31) == 0) ws[tid >> 5] = v;
    __syncthreads();
    if (tid == 0) {
        int s = 0;
        #pragma unroll
        for (int w = 0; w < 8; w++) s += ws[w];
        d_part[b] = s;
    }
}

__global__ void __launch_bounds__(256) pupil_final() {
    int tid = threadIdx.x;
    int v = d_part[tid];
    #pragma unroll
    for (int o = 16; o; o >>= 1) v += __shfl_xor_sync(0xffffffffu, v, o);
    __shared__ int ws[8];
    if ((tid & 31) == 0) ws[tid >> 5] = v;
    __syncthreads();
    if (tid == 0) {
        int s = 0;
        #pragma unroll
        for (int w = 0; w < 8; w++) s += ws[w];
        d_cscale = (float)(1.0 / (68719476736.0 * (double)s));
    }
}

// ---------------- bilinear xy_feat (z-independent) ----------------
__global__ void __launch_bounds__(256) xyfeat_kernel(
    const float* __restrict__ grid, const float* __restrict__ lerp,
    const int* __restrict__ x0, const int* __restrict__ y0,
    const int* __restrict__ x1, const int* __restrict__ y1)
{
    int p = blockIdx.x * 256 + threadIdx.x;
    float2 l = ((const float2*)lerp)[p];
    float lx = l.x, ly = l.y;
    int X0 = x0[p], Y0 = y0[p], X1 = x1[p], Y1 = y1[p];
    float w00 = (1.f - lx) * (1.f - ly);
    float w10 = lx * (1.f - ly);
    float w01 = (1.f - lx) * ly;
    float w11 = lx * ly;
    const float4* g00 = (const float4*)(grid + ((size_t)Y0 * WDIM + X0) * 16);
    const float4* g10 = (const float4*)(grid + ((size_t)Y0 * WDIM + X1) * 16);
    const float4* g01 = (const float4*)(grid + ((size_t)Y1 * WDIM + X0) * 16);
    const float4* g11 = (const float4*)(grid + ((size_t)Y1 * WDIM + X1) * 16);
    float4* o = (float4*)(d_xyf + (size_t)p * 16);
    #pragma unroll
    for (int q = 0; q < 4; q++) {
        float4 a = g00[q], b = g10[q], c = g01[q], d = g11[q];
        float4 r;
        r.x = a.x * w00 + b.x * w10 + c.x * w01 + d.x * w11;
        r.y = a.y * w00 + b.y * w10 + c.y * w01 + d.y * w11;
        r.z = a.z * w00 + b.z * w10 + c.z * w01 + d.z * w11;
        r.w = a.w * w00 + b.w * w10 + c.w * w01 + d.w * w11;
        o[q] = r;
    }
}

// ---------------- fused 3-layer MLP, 2 pixels/thread via f32x2 ----------------
__global__ void __launch_bounds__(256, 1) mlp_kernel(
    const float* __restrict__ zarr, const float* __restrict__ zdat,
    const float* __restrict__ w1, const float* __restrict__ b1,
    const float* __restrict__ w2, const float* __restrict__ b2,
    const float* __restrict__ w3, const float* __restrict__ b3)
{
    __shared__ __align__(16) ull w1p[16 * 32];
    __shared__ __align__(16) ull w2p[32 * 32];
    __shared__ __align__(16) ull w3p[32];
    __shared__ ull b1p[32], b2p[32];
    __shared__ float b3s;

    int tid = threadIdx.x;
    int z = blockIdx.y;

    {
        float zv = zarr[z];
        float zn = (29.0f * zv) / 30.0f;
        float zfl = floorf(zn);
        int z0 = (int)zfl; z0 = min(max(z0, 0), ZM - 1);
        int z1 = min(z0 + 1, ZM - 1);
        float zl = zn - zfl;

        int k0 = tid >> 5;
        float zf0 = zdat[z0 * 16 + k0] * (1.0f - zl) + zdat[z1 * 16 + k0] * zl;
        float v = w1[tid] * zf0;          w1p[tid] = pk(v, v);
        int k1 = (tid + 256) >> 5;
        float zf1 = zdat[z0 * 16 + k1] * (1.0f - zl) + zdat[z1 * 16 + k1] * zl;
        v = w1[tid + 256] * zf1;          w1p[tid + 256] = pk(v, v);
        #pragma unroll
        for (int q = 0; q < 4; q++) {
            v = w2[tid + q * 256]; w2p[tid + q * 256] = pk(v, v);
        }
        if (tid < 32) {
            float bb = b1[tid]; b1p[tid] = pk(bb, bb);
            bb = b2[tid];       b2p[tid] = pk(bb, bb);
            bb = w3[tid];       w3p[tid] = pk(bb, bb);
        }
        if (tid == 0) b3s = b3[0];
    }
    __syncthreads();

    int pp = blockIdx.x * 256 + tid;
    size_t px = (size_t)pp * 2;

    const float4* xp = (const float4*)(d_xyf + px * 16);
    float A[16], B[16];
    #pragma unroll
    for (int q = 0; q < 4; q++) {
        float4 t = xp[q];
        A[q * 4] = t.x; A[q * 4 + 1] = t.y; A[q * 4 + 2] = t.z; A[q * 4 + 3] = t.w;
    }
    #pragma unroll
    for (int q = 0; q < 4; q++) {
        float4 t = xp[4 + q];
        B[q * 4] = t.x; B[q * 4 + 1] = t.y; B[q * 4 + 2] = t.z; B[q * 4 + 3] = t.w;
    }

    ull h[32];
    #pragma unroll
    for (int j = 0; j < 32; j++) h[j] = b1p[j];
    #pragma unroll
    for (int k = 0; k < 16; k++) {
        ull fk = pk(A[k], B[k]);
        const ulonglong2* wp = (const ulonglong2*)(w1p + k * 32);
        #pragma unroll
        for (int j = 0; j < 16; j++) {
            ulonglong2 ww = wp[j];
            h[2 * j]     = fma2(fk, ww.x, h[2 * j]);
            h[2 * j + 1] = fma2(fk, ww.y, h[2 * j + 1]);
        }
    }
    #pragma unroll
    for (int j = 0; j < 32; j++) h[j] = relu2(h[j]);

    ull g[32];
    #pragma unroll
    for (int j = 0; j < 32; j++) g[j] = b2p[j];
    #pragma unroll
    for (int k = 0; k < 32; k++) {
        ull hk = h[k];
        const ulonglong2* wp = (const ulonglong2*)(w2p + k * 32);
        #pragma unroll
        for (int j = 0; j < 16; j++) {
            ulonglong2 ww = wp[j];
            g[2 * j]     = fma2(hk, ww.x, g[2 * j]);
            g[2 * j + 1] = fma2(hk, ww.y, g[2 * j + 1]);
        }
    }
    #pragma unroll
    for (int j = 0; j < 32; j++) g[j] = relu2(g[j]);

    ull acc = pk(b3s, b3s);
    #pragma unroll
    for (int j = 0; j < 32; j++) acc = fma2(g[j], w3p[j], acc);

    float o0, o1; upk(acc, o0, o1);
    *(float2*)(d_fluo + (size_t)z * NPIX + px) = make_float2(o0, o1);
}

// ---------------- radix-8 row pass: 256 threads, 4 rows per block ----------------
// MODE 0: build P = pupil * exp(i*aberr)              (DIR=-1, zp in [0,30))
// MODE 1: pack real plane pair (rin[2zp], rin[2zp+1]) (DIR=+1, zp in [0,15))
template<int DIR, int MODE>
__global__ void __launch_bounds__(256) fft_row4(
    const float* __restrict__ rin, const float* __restrict__ aberr,
    float2* __restrict__ cout)
{
    __shared__ float2 sm[4][CSTRIDE];
    int tid = threadIdx.x;
    int u = tid >> 6, t = tid & 63;
    int r = blockIdx.x * 4 + u;
    int zp = blockIdx.y;
    size_t rb = (size_t)zp * NPIX + (size_t)r * WDIM;

    float2 e[8];
    if (MODE == 0) {
        #pragma unroll
        for (int j = 0; j < 8; j++) {
            int n = t + 64 * j;
            float p = rin[(size_t)r * WDIM + n];
            float ab = aberr[rb + n];
            float sn, cs; __sincosf(ab, &sn, &cs);
            e[brev3(j)] = make_float2(p * cs, p * sn);
        }
    } else {
        size_t b0 = (size_t)(2 * zp) * NPIX + (size_t)r * WDIM;
        size_t b1 = b0 + NPIX;
        #pragma unroll
        for (int j = 0; j < 8; j++) {
            int n = t + 64 * j;
            e[brev3(j)] = make_float2(rin[b0 + n], rin[b1 + n]);
        }
    }

    fft_unit<DIR, false>(&sm[u][0], e, t, true);

    #pragma unroll
    for (int j = 0; j < 8; j++) cout[rb + j * 64 + t] = e[j];
}

// ---------------- fused colQ pass: 256 threads, 2 columns, plane pair ----------------
__global__ void __launch_bounds__(256) colq_kernel(
    const float2* __restrict__ in, float2* __restrict__ outp)
{
    __shared__ float2 sm[4 * CSTRIDE];
    int tid = threadIdx.x;
    int u = tid >> 6, t = tid & 63;
    int zp = blockIdx.y;
    int col0 = blockIdx.x * 2;

    #pragma unroll
    for (int q = 0; q < 8; q++) {
        int idx = tid + q * 256;
        int c = idx & 1, pl = (idx >> 1) & 1, i = idx >> 2;
        sm[(pl * 2 + c) * CSTRIDE + PADI(i)] =
            in[(size_t)(2 * zp + pl) * NPIX + (size_t)i * WDIM + col0 + c];
    }
    __syncthreads();

    // phase 1: inverse FFT per unit (u -> plane u>>1, col u&1)
    float2* s = sm + u * CSTRIDE;
    float2 e[8];
    #pragma unroll
    for (int j = 0; j < 8; j++) e[brev3(j)] = s[PADI(t + 64 * j)];
    fft_unit<-1, true>(s, e, t, true);
    #pragma unroll
    for (int j = 0; j < 8; j++) s[PADI(j * 64 + t)] = e[j];
    __syncthreads();

    // phase 2: packed forward FFT (units 0,1; unit c reads planes c and 2+c)
    bool act = (u < 2);
    if (act) {
        float2* s0 = sm + u * CSTRIDE;
        float2* s1 = sm + (2 + u) * CSTRIDE;
        #pragma unroll
        for (int j = 0; j < 8; j++) {
            int n = t + 64 * j;
            float2 a0 = s0[PADI(n)];
            float2 a1 = s1[PADI(n)];
            e[brev3(j)] = make_float2(a0.x * a0.x + a0.y * a0.y,
                                      a1.x * a1.x + a1.y * a1.y);
        }
    }
    fft_unit<+1, true>(s, e, t, act);
    if (act) {
        #pragma unroll
        for (int j = 0; j < 8; j++) s[PADI(j * 64 + t)] = e[j];
    }
    __syncthreads();

    #pragma unroll
    for (int q = 0; q < 4; q++) {
        int idx = tid + q * 256;
        int c = idx & 1, i = idx >> 1;
        outp[(size_t)zp * NPIX + (size_t)i * WDIM + col0 + c] =
            sm[c * CSTRIDE + PADI(i)];
    }
}

// ---------------- fused crossQ pass ----------------
// 128 threads, 2 units; block handles conjugate row pair.
// Phase A: Sq rows = fwd row FFT of qcol rows (smem only).
// Phase B: Hermitian cross-spectrum with So (global) + inverse row FFT -> Cbuf.
__global__ void __launch_bounds__(128) crossq_kernel(
    const float2* __restrict__ qcol, const float2* __restrict__ cSo,
    float2* __restrict__ cout)
{
    __shared__ float2 sm[2 * CSTRIDE];
    int tid = threadIdx.x;
    int u = tid >> 6, t = tid & 63;
    int b = blockIdx.x;
    int zp = blockIdx.y;
    size_t zb = (size_t)zp * NPIX;

    int ru = (b == 0) ? (u == 0 ? 0 : 256) : (u == 0 ? b : WDIM - b);
    int pu = (b == 0) ? u : 1 - u;           // unit holding the conjugate row
    int rn = (WDIM - ru) & (WDIM - 1);
    size_t rb  = zb + (size_t)ru * WDIM;
    size_t rbm = zb + (size_t)rn * WDIM;

    float2* s = sm + u * CSTRIDE;
    float2* sp = sm + pu * CSTRIDE;

    // phase A: forward FFT of qcol row ru
    float2 e[8];
    #pragma unroll
    for (int j = 0; j < 8; j++) e[brev3(j)] = qcol[rb + t + 64 * j];
    fft_unit<+1, false>(s, e, t, true);
    #pragma unroll
    for (int j = 0; j < 8; j++) s[PADI(j * 64 + t)] = e[j];
    __syncthreads();

    // phase B: cross spectrum + inverse FFT
    float sc = 0.25f * d_cscale;
    #pragma unroll
    for (int j = 0; j < 8; j++) {
        int n = t + 64 * j;
        int nn = (WDIM - n) & (WDIM - 1);
        float2 Sq  = s[PADI(n)];
        float2 Sqm = sp[PADI(nn)];
        float2 So  = cSo[rb + n];
        float2 Som = cSo[rbm + nn];
        float2 Po = make_float2(So.x + Som.x, So.y - Som.y);
        float2 Mo = make_float2(So.x - Som.x, So.y + Som.y);
        float2 Pq = make_float2(Sq.x + Sqm.x, Sq.y - Sqm.y);
        float2 Mq = make_float2(Sq.x - Sqm.x, Sq.y + Sqm.y);
        float2 PP = cmul(Po, Pq);
        float2 MM = cmul(Mo, Mq);
        e[brev3(j)] = make_float2(sc * (PP.x + MM.y), sc * (PP.y - MM.x));
    }
    fft_unit<-1, true>(s, e, t, true);

    #pragma unroll
    for (int j = 0; j < 8; j++) cout[rb + j * 64 + t] = e[j];
}

// ---------------- radix-8 column pass: 256 threads, 4 cols per block ----------------
// MODE 1: write complex (in-place safe)
// MODE 2: split: rout[2zp]=Re, rout[2zp+1]=Im   (DIR=-1)
template<int DIR, int MODE>
__global__ void __launch_bounds__(256) fft_col4(
    const float2* __restrict__ in, float2* __restrict__ cout, float* __restrict__ rout)
{
    __shared__ float2 sm[4 * CSTRIDE];
    int tid = threadIdx.x;
    int zp = blockIdx.y;
    int col0 = blockIdx.x * 4;
    size_t zb = (size_t)zp * NPIX;

    #pragma unroll
    for (int q = 0; q < 8; q++) {
        int l = tid + q * 256;
        int c = l & 3, i = l >> 2;
        sm[c * CSTRIDE + PADI(i)] = in[zb + (size_t)i * WDIM + col0 + c];
    }
    __syncthreads();

    int u = tid >> 6, t = tid & 63;
    float2* s = sm + u * CSTRIDE;
    float2 e[8];
    #pragma unroll
    for (int j = 0; j < 8; j++) e[brev3(j)] = s[PADI(t + 64 * j)];
    fft_unit<DIR, true>(s, e, t, true);
    #pragma unroll
    for (int j = 0; j < 8; j++) s[PADI(j * 64 + t)] = e[j];
    __syncthreads();

    #pragma unroll
    for (int q = 0; q < 8; q++) {
        int l = tid + q * 256;
        int c = l & 3, i = l >> 2;
        float2 v = sm[c * CSTRIDE + PADI(i)];
        size_t sp = (size_t)i * WDIM + col0 + c;
        if (MODE == 1) {
            cout[zb + sp] = v;
        } else {
            rout[(size_t)(2 * zp) * NPIX + sp]     = v.x;
            rout[(size_t)(2 * zp + 1) * NPIX + sp] = v.y;
        }
    }
}

// ---------------- launcher ----------------
extern "C" void kernel_launch(void* const* d_in, const int* in_sizes, int n_in,
                              void* d_out, int out_size)
{
    const float* z     = (const float*)d_in[0];
    const float* grid  = (const float*)d_in[1];
    const float* zdat  = (const float*)d_in[2];
    const float* w1    = (const float*)d_in[3];
    const float* b1    = (const float*)d_in[4];
    const float* w2    = (const float*)d_in[5];
    const float* b2    = (const float*)d_in[6];
    const float* w3    = (const float*)d_in[7];
    const float* b3    = (const float*)d_in[8];
    const float* pupil = (const float*)d_in[9];
    const float* aberr = (const float*)d_in[10];
    const float* lerp  = (const float*)d_in[11];
    const int*   x0    = (const int*)d_in[12];
    const int*   y0    = (const int*)d_in[13];
    const int*   x1    = (const int*)d_in[14];
    const int*   y1    = (const int*)d_in[15];
    float* out = (float*)d_out;

    float2* tmpA; float2* tmpB; float* qbuf; float* fluo;
    cudaGetSymbolAddress((void**)&tmpA, d_tmpA);
    cudaGetSymbolAddress((void**)&tmpB, d_tmpB);
    cudaGetSymbolAddress((void**)&qbuf, d_q);
    cudaGetSymbolAddress((void**)&fluo, d_fluo);
    float2* qcol = (float2*)qbuf;     // packed colF(q), 15 complex planes
    float2* Cbuf = (float2*)fluo;     // reuse fluo after its forward FFT

    // scalar normalizer 1/(N^4 * sum(pupil))
    pupil_part<<<256, 256>>>(pupil);
    pupil_final<<<1, 256>>>();

    // render path
    xyfeat_kernel<<<NPIX / 256, 256>>>(grid, lerp, x0, y0, x1, y1);
    mlp_kernel<<<dim3(512, ZM), 256>>>(z, zdat, w1, b1, w2, b2, w3, b3);

    // pupil path: rowIFFT(P) -> tmpA (30 planes)
    fft_row4<-1, 0><<<dim3(WDIM / 4, ZM), 256>>>(pupil, aberr, tmpA);
    // fused: col IFFT x2, |.|^2, packed forward col FFT -> qcol (15 planes)
    colq_kernel<<<dim3(WDIM / 2, NZP), 256>>>(tmpA, qcol);

    // So = F2(fluo) packed -> tmpB (col pass in-place)
    fft_row4<+1, 1><<<dim3(WDIM / 4, NZP), 256>>>(fluo, nullptr, tmpB);
    fft_col4<+1, 1><<<dim3(WDIM / 4, NZP), 256>>>(tmpB, tmpB, nullptr);

    // fused: Sq rows (fwd FFT of qcol) + Hermitian cross spectrum + row IFFT -> Cbuf
    crossq_kernel<<<dim3(WDIM / 2, NZP), 128>>>(qcol, tmpB, Cbuf);
    // inverse col pass, split packed planes into the 30 real output planes
    fft_col4<-1, 2><<<dim3(WDIM / 4, NZP), 256>>>(Cbuf, nullptr, out);
}

// round 5
// speedup vs baseline: 2.5231x; 1.4915x over previous
#include <cuda_runtime.h>
#include <cstdint>

#define WDIM 512
#define NPIX (512*512)
#define ZM 30
#define NZP (ZM/2)

typedef unsigned long long ull;

// ---------------- device scratch ----------------
__device__ __align__(16) float2 d_tmpA[(size_t)ZM * NPIX];   // 63 MB
__device__ __align__(16) float2 d_tmpB[(size_t)ZM * NPIX];   // 63 MB
__device__ __align__(16) float  d_q   [(size_t)ZM * NPIX];   // packed colFFT(q), 15 cpx planes
__device__ __align__(16) float  d_fluo[(size_t)ZM * NPIX];   // fluo, reused as Cbuf
__device__ __align__(16) float  d_xyf [(size_t)NPIX * 16];   // 16 MB
__device__ int   d_part[256];
__device__ float d_cscale;

// ---------------- f32x2 helpers ----------------
__device__ __forceinline__ ull pk(float lo, float hi) {
    ull r; asm("mov.b64 %0, {%1,%2};" : "=l"(r) : "f"(lo), "f"(hi)); return r;
}
__device__ __forceinline__ void upk(ull v, float& lo, float& hi) {
    asm("mov.b64 {%0,%1}, %2;" : "=f"(lo), "=f"(hi) : "l"(v));
}
__device__ __forceinline__ ull fma2(ull a, ull b, ull c) {
    ull d; asm("fma.rn.f32x2 %0, %1, %2, %3;" : "=l"(d) : "l"(a), "l"(b), "l"(c)); return d;
}
__device__ __forceinline__ ull relu2(ull v) {
    float a, b; upk(v, a, b);
    a = fmaxf(a, 0.0f); b = fmaxf(b, 0.0f);
    return pk(a, b);
}

// ---------------- complex helpers ----------------
__device__ __forceinline__ float2 cmul(float2 a, float2 b) {
    return make_float2(fmaf(a.x, b.x, -a.y * b.y), fmaf(a.x, b.y, a.y * b.x));
}
__device__ __forceinline__ float2 cadd(float2 a, float2 b) { return make_float2(a.x + b.x, a.y + b.y); }
__device__ __forceinline__ float2 csub(float2 a, float2 b) { return make_float2(a.x - b.x, a.y - b.y); }

__device__ __forceinline__ int brev3(int j) { return ((j & 1) << 2) | (j & 2) | ((j >> 2) & 1); }
__device__ __forceinline__ int brev6(int t) { return (int)(__brev((unsigned)t) >> 26); }

#define PADI(p) ((p) + ((p) >> 5))
#define CSTRIDE 532

// ---------------- radix-8 butterflies ----------------
template<int DIR>
__device__ __forceinline__ void bf8_0(float2 e[8])
{
    const float d = (DIR > 0) ? 1.0f : -1.0f;
    float2 f[8];
    #pragma unroll
    for (int m = 0; m < 4; m++) {
        float2 u = e[2 * m], v = e[2 * m + 1];
        f[2 * m]     = cadd(u, v);
        f[2 * m + 1] = csub(u, v);
    }
    float2 g[8];
    #pragma unroll
    for (int hh = 0; hh < 2; hh++) {
        int o = 4 * hh;
        float2 v0 = f[o + 2];
        float2 v1 = make_float2(d * f[o + 3].y, -d * f[o + 3].x);
        g[o + 0] = cadd(f[o + 0], v0); g[o + 2] = csub(f[o + 0], v0);
        g[o + 1] = cadd(f[o + 1], v1); g[o + 3] = csub(f[o + 1], v1);
    }
    const float S2 = 0.70710678118654752f;
    float2 v0 = g[4];
    float2 v1 = cmul(g[5], make_float2(S2, -d * S2));
    float2 v2 = make_float2(d * g[6].y, -d * g[6].x);
    float2 v3 = cmul(g[7], make_float2(-S2, -d * S2));
    e[0] = cadd(g[0], v0); e[4] = csub(g[0], v0);
    e[1] = cadd(g[1], v1); e[5] = csub(g[1], v1);
    e[2] = cadd(g[2], v2); e[6] = csub(g[2], v2);
    e[3] = cadd(g[3], v3); e[7] = csub(g[3], v3);
}

template<int DIR>
__device__ __forceinline__ void bf8_g(float2 e[8], float r)
{
    const float d = (DIR > 0) ? 1.0f : -1.0f;
    float s1, c1;
    sincospif(r, &s1, &c1);
    float2 t1 = make_float2(c1, -d * s1);
    float2 t2 = cmul(t1, t1);
    float2 t4 = cmul(t2, t2);

    float2 f[8];
    #pragma unroll
    for (int m = 0; m < 4; m++) {
        float2 v = cmul(e[2 * m + 1], t4);
        f[2 * m]     = cadd(e[2 * m], v);
        f[2 * m + 1] = csub(e[2 * m], v);
    }
    float2 wb1 = make_float2(d * t2.y, -d * t2.x);
    float2 g[8];
    #pragma unroll
    for (int hh = 0; hh < 2; hh++) {
        int o = 4 * hh;
        float2 v0 = cmul(f[o + 2], t2);
        float2 v1 = cmul(f[o + 3], wb1);
        g[o + 0] = cadd(f[o + 0], v0); g[o + 2] = csub(f[o + 0], v0);
        g[o + 1] = cadd(f[o + 1], v1); g[o + 3] = csub(f[o + 1], v1);
    }
    const float S2 = 0.70710678118654752f;
    float2 wc1 = make_float2(S2 * (t1.x + d * t1.y), S2 * (t1.y - d * t1.x));
    float2 wc2 = make_float2(d * t1.y, -d * t1.x);
    float2 wc3 = make_float2(S2 * (-t1.x + d * t1.y), S2 * (-t1.y - d * t1.x));
    float2 v0 = cmul(g[4], t1);
    float2 v1 = cmul(g[5], wc1);
    float2 v2 = cmul(g[6], wc2);
    float2 v3 = cmul(g[7], wc3);
    e[0] = cadd(g[0], v0); e[4] = csub(g[0], v0);
    e[1] = cadd(g[1], v1); e[5] = csub(g[1], v1);
    e[2] = cadd(g[2], v2); e[6] = csub(g[2], v2);
    e[3] = cadd(g[3], v3); e[7] = csub(g[3], v3);
}

// 512-pt FFT unit: 64 threads on padded smem region s.
template<int DIR, bool PRESYNC>
__device__ __forceinline__ void fft_unit(float2* s, float2 e[8], int t, bool active)
{
    if (active) bf8_0<DIR>(e);
    if (PRESYNC) __syncthreads();
    if (active) {
        int b = brev6(t);
        #pragma unroll
        for (int j = 0; j < 8; j++) s[PADI(8 * b + j)] = e[j];
    }
    __syncthreads();
    if (active) {
        int b2 = t >> 3, k = t & 7;
        #pragma unroll
        for (int j = 0; j < 8; j++) e[j] = s[PADI(b2 * 64 + j * 8 + k)];
        bf8_g<DIR>(e, (float)k * (1.0f / 32.0f));
        #pragma unroll
        for (int j = 0; j < 8; j++) s[PADI(b2 * 64 + j * 8 + k)] = e[j];
    }
    __syncthreads();
    if (active) {
        #pragma unroll
        for (int j = 0; j < 8; j++) e[j] = s[PADI(j * 64 + t)];
        bf8_g<DIR>(e, (float)t * (1.0f / 256.0f));
    }
}

// ---------------- pupil sum (2-kernel deterministic reduction) ----------------
__global__ void __launch_bounds__(256) pupil_part(const float* __restrict__ pupil) {
    int tid = threadIdx.x, b = blockIdx.x;
    int v = 0;
    #pragma unroll 4
    for (int q = 0; q < 4; q++) {
        int i = b * 1024 + q * 256 + tid;
        v += (pupil[i] > 0.5f) ? 1 : 0;
    }
    #pragma unroll
    for (int o = 16; o; o >>= 1) v += __shfl_xor_sync(0xffffffffu, v, o);
    __shared__ int ws[8];
    if ((tid & 31) == 0) ws[tid >> 5] = v;
    __syncthreads();
    if (tid == 0) {
        int s = 0;
        #pragma unroll
        for (int w = 0; w < 8; w++) s += ws[w];
        d_part[b] = s;
    }
}

__global__ void __launch_bounds__(256) pupil_final() {
    int tid = threadIdx.x;
    int v = d_part[tid];
    #pragma unroll
    for (int o = 16; o; o >>= 1) v += __shfl_xor_sync(0xffffffffu, v, o);
    __shared__ int ws[8];
    if ((tid & 31) == 0) ws[tid >> 5] = v;
    __syncthreads();
    if (tid == 0) {
        int s = 0;
        #pragma unroll
        for (int w = 0; w < 8; w++) s += ws[w];
        d_cscale = (float)(1.0 / (68719476736.0 * (double)s));
    }
}

// ---------------- bilinear xy_feat (z-independent) ----------------
__global__ void __launch_bounds__(256) xyfeat_kernel(
    const float* __restrict__ grid, const float* __restrict__ lerp,
    const int* __restrict__ x0, const int* __restrict__ y0,
    const int* __restrict__ x1, const int* __restrict__ y1)
{
    int p = blockIdx.x * 256 + threadIdx.x;
    float2 l = ((const float2*)lerp)[p];
    float lx = l.x, ly = l.y;
    int X0 = x0[p], Y0 = y0[p], X1 = x1[p], Y1 = y1[p];
    float w00 = (1.f - lx) * (1.f - ly);
    float w10 = lx * (1.f - ly);
    float w01 = (1.f - lx) * ly;
    float w11 = lx * ly;
    const float4* g00 = (const float4*)(grid + ((size_t)Y0 * WDIM + X0) * 16);
    const float4* g10 = (const float4*)(grid + ((size_t)Y0 * WDIM + X1) * 16);
    const float4* g01 = (const float4*)(grid + ((size_t)Y1 * WDIM + X0) * 16);
    const float4* g11 = (const float4*)(grid + ((size_t)Y1 * WDIM + X1) * 16);
    float4* o = (float4*)(d_xyf + (size_t)p * 16);
    #pragma unroll
    for (int q = 0; q < 4; q++) {
        float4 a = g00[q], b = g10[q], c = g01[q], d = g11[q];
        float4 r;
        r.x = a.x * w00 + b.x * w10 + c.x * w01 + d.x * w11;
        r.y = a.y * w00 + b.y * w10 + c.y * w01 + d.y * w11;
        r.z = a.z * w00 + b.z * w10 + c.z * w01 + d.z * w11;
        r.w = a.w * w00 + b.w * w10 + c.w * w01 + d.w * w11;
        o[q] = r;
    }
}

// ---------------- fused 3-layer MLP ----------------
// 2 pixels per thread; FMA2 lanes pack NEURON pairs (2j, 2j+1), so smem weights
// are stored UNduplicated: one LDS.128 = 4 distinct weights = 2 FMA2 operands.
// Pixel-side operand is pk(f_k, f_k) built in-register.
__global__ void __launch_bounds__(128, 3) mlp_kernel(
    const float* __restrict__ zarr, const float* __restrict__ zdat,
    const float* __restrict__ w1, const float* __restrict__ b1,
    const float* __restrict__ w2, const float* __restrict__ b2,
    const float* __restrict__ w3, const float* __restrict__ b3)
{
    __shared__ __align__(16) float w1s[16 * 32];   // pre-scaled by z_feat
    __shared__ __align__(16) float w2s[32 * 32];
    __shared__ __align__(16) float w3s[32];
    __shared__ __align__(16) float b1s[32];
    __shared__ __align__(16) float b2s[32];
    __shared__ float b3s;

    int tid = threadIdx.x;
    int z = blockIdx.y;

    {
        float zv = zarr[z];
        float zn = (29.0f * zv) / 30.0f;
        float zfl = floorf(zn);
        int z0 = (int)zfl; z0 = min(max(z0, 0), ZM - 1);
        int z1 = min(z0 + 1, ZM - 1);
        float zl = zn - zfl;

        #pragma unroll
        for (int q = 0; q < 4; q++) {
            int idx = tid + q * 128;
            int k = idx >> 5;
            float zf = zdat[z0 * 16 + k] * (1.0f - zl) + zdat[z1 * 16 + k] * zl;
            w1s[idx] = w1[idx] * zf;
        }
        #pragma unroll
        for (int q = 0; q < 8; q++) {
            int idx = tid + q * 128;
            w2s[idx] = w2[idx];
        }
        if (tid < 32) { w3s[tid] = w3[tid]; b1s[tid] = b1[tid]; b2s[tid] = b2[tid]; }
        if (tid == 0) b3s = b3[0];
    }
    __syncthreads();

    int pp = blockIdx.x * 128 + tid;     // pixel-pair index
    size_t px = (size_t)pp * 2;

    const float4* xp = (const float4*)(d_xyf + px * 16);
    float A[16], B[16];
    #pragma unroll
    for (int q = 0; q < 4; q++) {
        float4 t = xp[q];
        A[q * 4] = t.x; A[q * 4 + 1] = t.y; A[q * 4 + 2] = t.z; A[q * 4 + 3] = t.w;
    }
    #pragma unroll
    for (int q = 0; q < 4; q++) {
        float4 t = xp[4 + q];
        B[q * 4] = t.x; B[q * 4 + 1] = t.y; B[q * 4 + 2] = t.z; B[q * 4 + 3] = t.w;
    }

    // layer 1: 16 -> 32, neuron-packed accumulators per pixel
    const ull* b1p = (const ull*)b1s;    // (b1[2j], b1[2j+1]) pairs
    ull hA[16], hB[16];
    #pragma unroll
    for (int j = 0; j < 16; j++) { ull bb = b1p[j]; hA[j] = bb; hB[j] = bb; }
    #pragma unroll
    for (int k = 0; k < 16; k++) {
        ull fa = pk(A[k], A[k]);
        ull fb = pk(B[k], B[k]);
        const ulonglong2* wp = (const ulonglong2*)(w1s + k * 32);
        #pragma unroll
        for (int j = 0; j < 8; j++) {
            ulonglong2 ww = wp[j];
            hA[2 * j]     = fma2(fa, ww.x, hA[2 * j]);
            hA[2 * j + 1] = fma2(fa, ww.y, hA[2 * j + 1]);
            hB[2 * j]     = fma2(fb, ww.x, hB[2 * j]);
            hB[2 * j + 1] = fma2(fb, ww.y, hB[2 * j + 1]);
        }
    }
    #pragma unroll
    for (int j = 0; j < 16; j++) { hA[j] = relu2(hA[j]); hB[j] = relu2(hB[j]); }

    // layer 2: 32 -> 32
    const ull* b2p = (const ull*)b2s;
    ull gA[16], gB[16];
    #pragma unroll
    for (int j = 0; j < 16; j++) { ull bb = b2p[j]; gA[j] = bb; gB[j] = bb; }
    #pragma unroll
    for (int k = 0; k < 32; k++) {
        float lo, hi, va, vb;
        upk(hA[k >> 1], lo, hi); va = (k & 1) ? hi : lo;
        upk(hB[k >> 1], lo, hi); vb = (k & 1) ? hi : lo;
        ull fa = pk(va, va);
        ull fb = pk(vb, vb);
        const ulonglong2* wp = (const ulonglong2*)(w2s + k * 32);
        #pragma unroll
        for (int j = 0; j < 8; j++) {
            ulonglong2 ww = wp[j];
            gA[2 * j]     = fma2(fa, ww.x, gA[2 * j]);
            gA[2 * j + 1] = fma2(fa, ww.y, gA[2 * j + 1]);
            gB[2 * j]     = fma2(fb, ww.x, gB[2 * j]);
            gB[2 * j + 1] = fma2(fb, ww.y, gB[2 * j + 1]);
        }
    }

    // layer 3: 32 -> 1 (relu fused; packed partial sums, fold lo+hi at the end)
    const ull* w3p = (const ull*)w3s;
    ull accA = pk(0.0f, 0.0f), accB = pk(0.0f, 0.0f);
    #pragma unroll
    for (int j = 0; j < 16; j++) {
        ull wj = w3p[j];
        accA = fma2(relu2(gA[j]), wj, accA);
        accB = fma2(relu2(gB[j]), wj, accB);
    }
    float la, ha, lb, hb;
    upk(accA, la, ha);
    upk(accB, lb, hb);
    *(float2*)(d_fluo + (size_t)z * NPIX + px) =
        make_float2(la + ha + b3s, lb + hb + b3s);
}

// ---------------- radix-8 row pass: 256 threads, 4 rows per block ----------------
template<int DIR, int MODE>
__global__ void __launch_bounds__(256) fft_row4(
    const float* __restrict__ rin, const float* __restrict__ aberr,
    float2* __restrict__ cout)
{
    __shared__ float2 sm[4][CSTRIDE];
    int tid = threadIdx.x;
    int u = tid >> 6, t = tid & 63;
    int r = blockIdx.x * 4 + u;
    int zp = blockIdx.y;
    size_t rb = (size_t)zp * NPIX + (size_t)r * WDIM;

    float2 e[8];
    if (MODE == 0) {
        #pragma unroll
        for (int j = 0; j < 8; j++) {
            int n = t + 64 * j;
            float p = rin[(size_t)r * WDIM + n];
            float ab = aberr[rb + n];
            float sn, cs; __sincosf(ab, &sn, &cs);
            e[brev3(j)] = make_float2(p * cs, p * sn);
        }
    } else {
        size_t b0 = (size_t)(2 * zp) * NPIX + (size_t)r * WDIM;
        size_t b1 = b0 + NPIX;
        #pragma unroll
        for (int j = 0; j < 8; j++) {
            int n = t + 64 * j;
            e[brev3(j)] = make_float2(rin[b0 + n], rin[b1 + n]);
        }
    }

    fft_unit<DIR, false>(&sm[u][0], e, t, true);

    #pragma unroll
    for (int j = 0; j < 8; j++) cout[rb + j * 64 + t] = e[j];
}

// ---------------- fused colQ pass: 256 threads, 2 columns, plane pair ----------------
__global__ void __launch_bounds__(256) colq_kernel(
    const float2* __restrict__ in, float2* __restrict__ outp)
{
    __shared__ float2 sm[4 * CSTRIDE];
    int tid = threadIdx.x;
    int u = tid >> 6, t = tid & 63;
    int zp = blockIdx.y;
    int col0 = blockIdx.x * 2;

    #pragma unroll
    for (int q = 0; q < 8; q++) {
        int idx = tid + q * 256;
        int c = idx & 1, pl = (idx >> 1) & 1, i = idx >> 2;
        sm[(pl * 2 + c) * CSTRIDE + PADI(i)] =
            in[(size_t)(2 * zp + pl) * NPIX + (size_t)i * WDIM + col0 + c];
    }
    __syncthreads();

    float2* s = sm + u * CSTRIDE;
    float2 e[8];
    #pragma unroll
    for (int j = 0; j < 8; j++) e[brev3(j)] = s[PADI(t + 64 * j)];
    fft_unit<-1, true>(s, e, t, true);
    #pragma unroll
    for (int j = 0; j < 8; j++) s[PADI(j * 64 + t)] = e[j];
    __syncthreads();

    bool act = (u < 2);
    if (act) {
        float2* s0 = sm + u * CSTRIDE;
        float2* s1 = sm + (2 + u) * CSTRIDE;
        #pragma unroll
        for (int j = 0; j < 8; j++) {
            int n = t + 64 * j;
            float2 a0 = s0[PADI(n)];
            float2 a1 = s1[PADI(n)];
            e[brev3(j)] = make_float2(a0.x * a0.x + a0.y * a0.y,
                                      a1.x * a1.x + a1.y * a1.y);
        }
    }
    fft_unit<+1, true>(s, e, t, act);
    if (act) {
        #pragma unroll
        for (int j = 0; j < 8; j++) s[PADI(j * 64 + t)] = e[j];
    }
    __syncthreads();

    #pragma unroll
    for (int q = 0; q < 4; q++) {
        int idx = tid + q * 256;
        int c = idx & 1, i = idx >> 1;
        outp[(size_t)zp * NPIX + (size_t)i * WDIM + col0 + c] =
            sm[c * CSTRIDE + PADI(i)];
    }
}

// ---------------- fused crossQ pass ----------------
__global__ void __launch_bounds__(128) crossq_kernel(
    const float2* __restrict__ qcol, const float2* __restrict__ cSo,
    float2* __restrict__ cout)
{
    __shared__ float2 sm[2 * CSTRIDE];
    int tid = threadIdx.x;
    int u = tid >> 6, t = tid & 63;
    int b = blockIdx.x;
    int zp = blockIdx.y;
    size_t zb = (size_t)zp * NPIX;

    int ru = (b == 0) ? (u == 0 ? 0 : 256) : (u == 0 ? b : WDIM - b);
    int pu = (b == 0) ? u : 1 - u;
    int rn = (WDIM - ru) & (WDIM - 1);
    size_t rb  = zb + (size_t)ru * WDIM;
    size_t rbm = zb + (size_t)rn * WDIM;

    float2* s = sm + u * CSTRIDE;
    float2* sp = sm + pu * CSTRIDE;

    float2 e[8];
    #pragma unroll
    for (int j = 0; j < 8; j++) e[brev3(j)] = qcol[rb + t + 64 * j];
    fft_unit<+1, false>(s, e, t, true);
    #pragma unroll
    for (int j = 0; j < 8; j++) s[PADI(j * 64 + t)] = e[j];
    __syncthreads();

    float sc = 0.25f * d_cscale;
    #pragma unroll
    for (int j = 0; j < 8; j++) {
        int n = t + 64 * j;
        int nn = (WDIM - n) & (WDIM - 1);
        float2 Sq  = s[PADI(n)];
        float2 Sqm = sp[PADI(nn)];
        float2 So  = cSo[rb + n];
        float2 Som = cSo[rbm + nn];
        float2 Po = make_float2(So.x + Som.x, So.y - Som.y);
        float2 Mo = make_float2(So.x - Som.x, So.y + Som.y);
        float2 Pq = make_float2(Sq.x + Sqm.x, Sq.y - Sqm.y);
        float2 Mq = make_float2(Sq.x - Sqm.x, Sq.y + Sqm.y);
        float2 PP = cmul(Po, Pq);
        float2 MM = cmul(Mo, Mq);
        e[brev3(j)] = make_float2(sc * (PP.x + MM.y), sc * (PP.y - MM.x));
    }
    fft_unit<-1, true>(s, e, t, true);

    #pragma unroll
    for (int j = 0; j < 8; j++) cout[rb + j * 64 + t] = e[j];
}

// ---------------- radix-8 column pass: 256 threads, 4 cols per block ----------------
template<int DIR, int MODE>
__global__ void __launch_bounds__(256) fft_col4(
    const float2* __restrict__ in, float2* __restrict__ cout, float* __restrict__ rout)
{
    __shared__ float2 sm[4 * CSTRIDE];
    int tid = threadIdx.x;
    int zp = blockIdx.y;
    int col0 = blockIdx.x * 4;
    size_t zb = (size_t)zp * NPIX;

    #pragma unroll
    for (int q = 0; q < 8; q++) {
        int l = tid + q * 256;
        int c = l & 3, i = l >> 2;
        sm[c * CSTRIDE + PADI(i)] = in[zb + (size_t)i * WDIM + col0 + c];
    }
    __syncthreads();

    int u = tid >> 6, t = tid & 63;
    float2* s = sm + u * CSTRIDE;
    float2 e[8];
    #pragma unroll
    for (int j = 0; j < 8; j++) e[brev3(j)] = s[PADI(t + 64 * j)];
    fft_unit<DIR, true>(s, e, t, true);
    #pragma unroll
    for (int j = 0; j < 8; j++) s[PADI(j * 64 + t)] = e[j];
    __syncthreads();

    #pragma unroll
    for (int q = 0; q < 8; q++) {
        int l = tid + q * 256;
        int c = l & 3, i = l >> 2;
        float2 v = sm[c * CSTRIDE + PADI(i)];
        size_t sp = (size_t)i * WDIM + col0 + c;
        if (MODE == 1) {
            cout[zb + sp] = v;
        } else {
            rout[(size_t)(2 * zp) * NPIX + sp]     = v.x;
            rout[(size_t)(2 * zp + 1) * NPIX + sp] = v.y;
        }
    }
}

// ---------------- launcher ----------------
extern "C" void kernel_launch(void* const* d_in, const int* in_sizes, int n_in,
                              void* d_out, int out_size)
{
    const float* z     = (const float*)d_in[0];
    const float* grid  = (const float*)d_in[1];
    const float* zdat  = (const float*)d_in[2];
    const float* w1    = (const float*)d_in[3];
    const float* b1    = (const float*)d_in[4];
    const float* w2    = (const float*)d_in[5];
    const float* b2    = (const float*)d_in[6];
    const float* w3    = (const float*)d_in[7];
    const float* b3    = (const float*)d_in[8];
    const float* pupil = (const float*)d_in[9];
    const float* aberr = (const float*)d_in[10];
    const float* lerp  = (const float*)d_in[11];
    const int*   x0    = (const int*)d_in[12];
    const int*   y0    = (const int*)d_in[13];
    const int*   x1    = (const int*)d_in[14];
    const int*   y1    = (const int*)d_in[15];
    float* out = (float*)d_out;

    float2* tmpA; float2* tmpB; float* qbuf; float* fluo;
    cudaGetSymbolAddress((void**)&tmpA, d_tmpA);
    cudaGetSymbolAddress((void**)&tmpB, d_tmpB);
    cudaGetSymbolAddress((void**)&qbuf, d_q);
    cudaGetSymbolAddress((void**)&fluo, d_fluo);
    float2* qcol = (float2*)qbuf;
    float2* Cbuf = (float2*)fluo;

    // scalar normalizer 1/(N^4 * sum(pupil))
    pupil_part<<<256, 256>>>(pupil);
    pupil_final<<<1, 256>>>();

    // render path
    xyfeat_kernel<<<NPIX / 256, 256>>>(grid, lerp, x0, y0, x1, y1);
    mlp_kernel<<<dim3(1024, ZM), 128>>>(z, zdat, w1, b1, w2, b2, w3, b3);

    // pupil path: rowIFFT(P) -> tmpA (30 planes)
    fft_row4<-1, 0><<<dim3(WDIM / 4, ZM), 256>>>(pupil, aberr, tmpA);
    // fused: col IFFT x2, |.|^2, packed forward col FFT -> qcol (15 planes)
    colq_kernel<<<dim3(WDIM / 2, NZP), 256>>>(tmpA, qcol);

    // So = F2(fluo) packed -> tmpB (col pass in-place)
    fft_row4<+1, 1><<<dim3(WDIM / 4, NZP), 256>>>(fluo, nullptr, tmpB);
    fft_col4<+1, 1><<<dim3(WDIM / 4, NZP), 256>>>(tmpB, tmpB, nullptr);

    // fused: Sq rows + Hermitian cross spectrum + row IFFT -> Cbuf
    crossq_kernel<<<dim3(WDIM / 2, NZP), 128>>>(qcol, tmpB, Cbuf);
    // inverse col pass, split packed planes into the 30 real output planes
    fft_col4<-1, 2><<<dim3(WDIM / 4, NZP), 256>>>(Cbuf, nullptr, out);
}

// round 8
// speedup vs baseline: 3.8279x; 1.5171x over previous
#include <cuda_runtime.h>
#include <cstdint>

#define WDIM 512
#define NPIX (512*512)
#define ZM 30
#define NZP (ZM/2)

typedef unsigned long long ull;
typedef unsigned int uint;

// ---------------- device scratch ----------------
__device__ __align__(16) float2 d_tmpA[(size_t)ZM * NPIX];   // 63 MB
__device__ __align__(16) float2 d_tmpB[(size_t)ZM * NPIX];   // 63 MB
__device__ __align__(16) float  d_q   [(size_t)ZM * NPIX];   // packed colFFT(q), 15 cpx planes
__device__ __align__(16) float  d_fluo[(size_t)ZM * NPIX];   // fluo, reused as Cbuf
__device__ __align__(16) float  d_xyf [(size_t)NPIX * 16];   // 16 MB: [0,8MB)=hi b32 pairs, [8,16MB)=lo
__device__ int   d_part[256];
__device__ float d_cscale;

// ---------------- bf16 split helpers ----------------
// pack (x0 -> low bf16, x1 -> high bf16); lo = residual pair
__device__ __forceinline__ void split2(float x0, float x1, uint& h, uint& l) {
    uint hp;
    asm("cvt.rn.bf16x2.f32 %0, %1, %2;" : "=r"(hp) : "f"(x1), "f"(x0));
    float h0 = __uint_as_float(hp << 16);
    float h1 = __uint_as_float(hp & 0xffff0000u);
    float l0 = x0 - h0, l1 = x1 - h1;
    asm("cvt.rn.bf16x2.f32 %0, %1, %2;" : "=r"(l) : "f"(l1), "f"(l0));
    h = hp;
}

__device__ __forceinline__ void mma16816(float c[4], const uint a[4], uint2 b) {
    asm("mma.sync.aligned.m16n8k16.row.col.f32.bf16.bf16.f32 "
        "{%0,%1,%2,%3}, {%4,%5,%6,%7}, {%8,%9}, {%0,%1,%2,%3};"
        : "+f"(c[0]), "+f"(c[1]), "+f"(c[2]), "+f"(c[3])
        : "r"(a[0]), "r"(a[1]), "r"(a[2]), "r"(a[3]), "r"(b.x), "r"(b.y));
}

// ---------------- complex helpers ----------------
__device__ __forceinline__ float2 cmul(float2 a, float2 b) {
    return make_float2(fmaf(a.x, b.x, -a.y * b.y), fmaf(a.x, b.y, a.y * b.x));
}
__device__ __forceinline__ float2 cadd(float2 a, float2 b) { return make_float2(a.x + b.x, a.y + b.y); }
__device__ __forceinline__ float2 csub(float2 a, float2 b) { return make_float2(a.x - b.x, a.y - b.y); }

__device__ __forceinline__ int brev3(int j) { return ((j & 1) << 2) | (j & 2) | ((j >> 2) & 1); }
__device__ __forceinline__ int brev6(int t) { return (int)(__brev((unsigned)t) >> 26); }

#define PADI(p) ((p) + ((p) >> 5))
#define CSTRIDE 532

// ---------------- radix-8 butterflies ----------------
template<int DIR>
__device__ __forceinline__ void bf8_0(float2 e[8])
{
    const float d = (DIR > 0) ? 1.0f : -1.0f;
    float2 f[8];
    #pragma unroll
    for (int m = 0; m < 4; m++) {
        float2 u = e[2 * m], v = e[2 * m + 1];
        f[2 * m]     = cadd(u, v);
        f[2 * m + 1] = csub(u, v);
    }
    float2 g[8];
    #pragma unroll
    for (int hh = 0; hh < 2; hh++) {
        int o = 4 * hh;
        float2 v0 = f[o + 2];
        float2 v1 = make_float2(d * f[o + 3].y, -d * f[o + 3].x);
        g[o + 0] = cadd(f[o + 0], v0); g[o + 2] = csub(f[o + 0], v0);
        g[o + 1] = cadd(f[o + 1], v1); g[o + 3] = csub(f[o + 1], v1);
    }
    const float S2 = 0.70710678118654752f;
    float2 v0 = g[4];
    float2 v1 = cmul(g[5], make_float2(S2, -d * S2));
    float2 v2 = make_float2(d * g[6].y, -d * g[6].x);
    float2 v3 = cmul(g[7], make_float2(-S2, -d * S2));
    e[0] = cadd(g[0], v0); e[4] = csub(g[0], v0);
    e[1] = cadd(g[1], v1); e[5] = csub(g[1], v1);
    e[2] = cadd(g[2], v2); e[6] = csub(g[2], v2);
    e[3] = cadd(g[3], v3); e[7] = csub(g[3], v3);
}

template<int DIR>
__device__ __forceinline__ void bf8_g(float2 e[8], float r)
{
    const float d = (DIR > 0) ? 1.0f : -1.0f;
    float s1, c1;
    sincospif(r, &s1, &c1);
    float2 t1 = make_float2(c1, -d * s1);
    float2 t2 = cmul(t1, t1);
    float2 t4 = cmul(t2, t2);

    float2 f[8];
    #pragma unroll
    for (int m = 0; m < 4; m++) {
        float2 v = cmul(e[2 * m + 1], t4);
        f[2 * m]     = cadd(e[2 * m], v);
        f[2 * m + 1] = csub(e[2 * m], v);
    }
    float2 wb1 = make_float2(d * t2.y, -d * t2.x);
    float2 g[8];
    #pragma unroll
    for (int hh = 0; hh < 2; hh++) {
        int o = 4 * hh;
        float2 v0 = cmul(f[o + 2], t2);
        float2 v1 = cmul(f[o + 3], wb1);
        g[o + 0] = cadd(f[o + 0], v0); g[o + 2] = csub(f[o + 0], v0);
        g[o + 1] = cadd(f[o + 1], v1); g[o + 3] = csub(f[o + 1], v1);
    }
    const float S2 = 0.70710678118654752f;
    float2 wc1 = make_float2(S2 * (t1.x + d * t1.y), S2 * (t1.y - d * t1.x));
    float2 wc2 = make_float2(d * t1.y, -d * t1.x);
    float2 wc3 = make_float2(S2 * (-t1.x + d * t1.y), S2 * (-t1.y - d * t1.x));
    float2 v0 = cmul(g[4], t1);
    float2 v1 = cmul(g[5], wc1);
    float2 v2 = cmul(g[6], wc2);
    float2 v3 = cmul(g[7], wc3);
    e[0] = cadd(g[0], v0); e[4] = csub(g[0], v0);
    e[1] = cadd(g[1], v1); e[5] = csub(g[1], v1);
    e[2] = cadd(g[2], v2); e[6] = csub(g[2], v2);
    e[3] = cadd(g[3], v3); e[7] = csub(g[3], v3);
}

template<int DIR, bool PRESYNC>
__device__ __forceinline__ void fft_unit(float2* s, float2 e[8], int t, bool active)
{
    if (active) bf8_0<DIR>(e);
    if (PRESYNC) __syncthreads();
    if (active) {
        int b = brev6(t);
        #pragma unroll
        for (int j = 0; j < 8; j++) s[PADI(8 * b + j)] = e[j];
    }
    __syncthreads();
    if (active) {
        int b2 = t >> 3, k = t & 7;
        #pragma unroll
        for (int j = 0; j < 8; j++) e[j] = s[PADI(b2 * 64 + j * 8 + k)];
        bf8_g<DIR>(e, (float)k * (1.0f / 32.0f));
        #pragma unroll
        for (int j = 0; j < 8; j++) s[PADI(b2 * 64 + j * 8 + k)] = e[j];
    }
    __syncthreads();
    if (active) {
        #pragma unroll
        for (int j = 0; j < 8; j++) e[j] = s[PADI(j * 64 + t)];
        bf8_g<DIR>(e, (float)t * (1.0f / 256.0f));
    }
}

// ---------------- pupil sum ----------------
__global__ void __launch_bounds__(256) pupil_part(const float* __restrict__ pupil) {
    int tid = threadIdx.x, b = blockIdx.x;
    int v = 0;
    #pragma unroll 4
    for (int q = 0; q < 4; q++) {
        int i = b * 1024 + q * 256 + tid;
        v += (pupil[i] > 0.5f) ? 1 : 0;
    }
    #pragma unroll
    for (int o = 16; o; o >>= 1) v += __shfl_xor_sync(0xffffffffu, v, o);
    __shared__ int ws[8];
    if ((tid & 31) == 0) ws[tid >> 5] = v;
    __syncthreads();
    if (tid == 0) {
        int s = 0;
        #pragma unroll
        for (int w = 0; w < 8; w++) s += ws[w];
        d_part[b] = s;
    }
}

__global__ void __launch_bounds__(256) pupil_final() {
    int tid = threadIdx.x;
    int v = d_part[tid];
    #pragma unroll
    for (int o = 16; o; o >>= 1) v += __shfl_xor_sync(0xffffffffu, v, o);
    __shared__ int ws[8];
    if ((tid & 31) == 0) ws[tid >> 5] = v;
    __syncthreads();
    if (tid == 0) {
        int s = 0;
        #pragma unroll
        for (int w = 0; w < 8; w++) s += ws[w];
        d_cscale = (float)(1.0 / (68719476736.0 * (double)s));
    }
}

// ---------------- bilinear xy_feat + bf16 hi/lo split ----------------
__global__ void __launch_bounds__(256) xyfeat_kernel(
    const float* __restrict__ grid, const float* __restrict__ lerp,
    const int* __restrict__ x0, const int* __restrict__ y0,
    const int* __restrict__ x1, const int* __restrict__ y1)
{
    int p = blockIdx.x * 256 + threadIdx.x;
    float2 l = ((const float2*)lerp)[p];
    float lx = l.x, ly = l.y;
    int X0 = x0[p], Y0 = y0[p], X1 = x1[p], Y1 = y1[p];
    float w00 = (1.f - lx) * (1.f - ly);
    float w10 = lx * (1.f - ly);
    float w01 = (1.f - lx) * ly;
    float w11 = lx * ly;
    const float4* g00 = (const float4*)(grid + ((size_t)Y0 * WDIM + X0) * 16);
    const float4* g10 = (const float4*)(grid + ((size_t)Y0 * WDIM + X1) * 16);
    const float4* g01 = (const float4*)(grid + ((size_t)Y1 * WDIM + X0) * 16);
    const float4* g11 = (const float4*)(grid + ((size_t)Y1 * WDIM + X1) * 16);
    float f[16];
    #pragma unroll
    for (int q = 0; q < 4; q++) {
        float4 a = g00[q], b = g10[q], c = g01[q], d = g11[q];
        f[q * 4 + 0] = a.x * w00 + b.x * w10 + c.x * w01 + d.x * w11;
        f[q * 4 + 1] = a.y * w00 + b.y * w10 + c.y * w01 + d.y * w11;
        f[q * 4 + 2] = a.z * w00 + b.z * w10 + c.z * w01 + d.z * w11;
        f[q * 4 + 3] = a.w * w00 + b.w * w10 + c.w * w01 + d.w * w11;
    }
    uint hi[8], lo[8];
    #pragma unroll
    for (int t = 0; t < 8; t++) split2(f[2 * t], f[2 * t + 1], hi[t], lo[t]);
    uint* hip = (uint*)d_xyf;
    uint* lop = hip + (size_t)NPIX * 8;
    ((uint4*)(hip + (size_t)p * 8))[0] = make_uint4(hi[0], hi[1], hi[2], hi[3]);
    ((uint4*)(hip + (size_t)p * 8))[1] = make_uint4(hi[4], hi[5], hi[6], hi[7]);
    ((uint4*)(lop + (size_t)p * 8))[0] = make_uint4(lo[0], lo[1], lo[2], lo[3]);
    ((uint4*)(lop + (size_t)p * 8))[1] = make_uint4(lo[4], lo[5], lo[6], lo[7]);
}

// ---------------- tensor-core MLP (bf16 3-term split) ----------------
// Block: 128 threads (4 warps), each warp does 32 pixels (2 m16 tiles), one z.
// Chain: feat[16] -> 32 -> 32 -> 1, relu between; inter-layer data stays in
// registers (C-fragment layout == A-fragment layout for m16n8k16).
__global__ void __launch_bounds__(128) mlp_kernel(
    const float* __restrict__ zarr, const float* __restrict__ zdat,
    const float* __restrict__ w1, const float* __restrict__ b1,
    const float* __restrict__ w2, const float* __restrict__ b2,
    const float* __restrict__ w3, const float* __restrict__ b3)
{
    __shared__ uint2 w1h[4][32], w1l[4][32];     // [n][lane]
    __shared__ uint2 w2h[8][32], w2l[8][32];     // [s*4+n][lane]
    __shared__ uint2 w3h[2][32], w3l[2][32];     // [s][lane]
    __shared__ float b1s[32], b2s[32];
    __shared__ float b3s;

    int tid = threadIdx.x, lane = tid & 31, warp = tid >> 5;
    int gid = lane >> 2, tig = lane & 3;
    int z = blockIdx.y;

    if (warp == 0) {
        float zv = zarr[z];
        float zn = (29.0f * zv) / 30.0f;
        float zfl = floorf(zn);
        int z0 = (int)zfl; z0 = min(max(z0, 0), ZM - 1);
        int z1 = min(z0 + 1, ZM - 1);
        float zl = zn - zfl;

        int ks[4] = { 2 * tig, 2 * tig + 1, 2 * tig + 8, 2 * tig + 9 };
        float zf[4];
        #pragma unroll
        for (int i = 0; i < 4; i++)
            zf[i] = zdat[z0 * 16 + ks[i]] * (1.0f - zl) + zdat[z1 * 16 + ks[i]] * zl;

        #pragma unroll
        for (int n = 0; n < 4; n++) {
            float wv[4];
            #pragma unroll
            for (int i = 0; i < 4; i++) wv[i] = w1[ks[i] * 32 + 8 * n + gid] * zf[i];
            uint h0, l0, h1, l1;
            split2(wv[0], wv[1], h0, l0);
            split2(wv[2], wv[3], h1, l1);
            w1h[n][lane] = make_uint2(h0, h1);
            w1l[n][lane] = make_uint2(l0, l1);
        }
        #pragma unroll
        for (int s = 0; s < 2; s++)
            #pragma unroll
            for (int n = 0; n < 4; n++) {
                float wv[4];
                #pragma unroll
                for (int i = 0; i < 4; i++) wv[i] = w2[(16 * s + ks[i]) * 32 + 8 * n + gid];
                uint h0, l0, h1, l1;
                split2(wv[0], wv[1], h0, l0);
                split2(wv[2], wv[3], h1, l1);
                w2h[s * 4 + n][lane] = make_uint2(h0, h1);
                w2l[s * 4 + n][lane] = make_uint2(l0, l1);
            }
        #pragma unroll
        for (int s = 0; s < 2; s++) {
            float wv[4];
            #pragma unroll
            for (int i = 0; i < 4; i++) wv[i] = (gid == 0) ? w3[16 * s + ks[i]] : 0.0f;
            uint h0, l0, h1, l1;
            split2(wv[0], wv[1], h0, l0);
            split2(wv[2], wv[3], h1, l1);
            w3h[s][lane] = make_uint2(h0, h1);
            w3l[s][lane] = make_uint2(l0, l1);
        }
        b1s[lane] = b1[lane];
        b2s[lane] = b2[lane];
        if (lane == 0) b3s = b3[0];
    }
    __syncthreads();

    const uint* hip = (const uint*)d_xyf;
    const uint* lop = hip + (size_t)NPIX * 8;
    int pxb = blockIdx.x * 128 + warp * 32;

    #pragma unroll
    for (int m = 0; m < 2; m++) {
        int pb = pxb + m * 16;
        size_t r0 = (size_t)(pb + gid) * 8;
        size_t r1 = (size_t)(pb + gid + 8) * 8;
        uint Ah[4], Al[4];
        Ah[0] = hip[r0 + tig];     Ah[1] = hip[r1 + tig];
        Ah[2] = hip[r0 + tig + 4]; Ah[3] = hip[r1 + tig + 4];
        Al[0] = lop[r0 + tig];     Al[1] = lop[r1 + tig];
        Al[2] = lop[r0 + tig + 4]; Al[3] = lop[r1 + tig + 4];

        // layer 1: 16 -> 32
        float acc[4][4];
        #pragma unroll
        for (int n = 0; n < 4; n++) {
            float bb0 = b1s[8 * n + 2 * tig], bb1 = b1s[8 * n + 2 * tig + 1];
            acc[n][0] = bb0; acc[n][1] = bb1; acc[n][2] = bb0; acc[n][3] = bb1;
        }
        #pragma unroll
        for (int n = 0; n < 4; n++) {
            uint2 bh = w1h[n][lane], bl = w1l[n][lane];
            mma16816(acc[n], Ah, bh);
            mma16816(acc[n], Ah, bl);
            mma16816(acc[n], Al, bh);
        }

        // relu + split -> layer-2 A frags
        uint A2h[2][4], A2l[2][4];
        #pragma unroll
        for (int s = 0; s < 2; s++) {
            split2(fmaxf(acc[2*s][0], 0.f),   fmaxf(acc[2*s][1], 0.f),   A2h[s][0], A2l[s][0]);
            split2(fmaxf(acc[2*s][2], 0.f),   fmaxf(acc[2*s][3], 0.f),   A2h[s][1], A2l[s][1]);
            split2(fmaxf(acc[2*s+1][0], 0.f), fmaxf(acc[2*s+1][1], 0.f), A2h[s][2], A2l[s][2]);
            split2(fmaxf(acc[2*s+1][2], 0.f), fmaxf(acc[2*s+1][3], 0.f), A2h[s][3], A2l[s][3]);
        }

        // layer 2: 32 -> 32
        float acc2[4][4];
        #pragma unroll
        for (int n = 0; n < 4; n++) {
            float bb0 = b2s[8 * n + 2 * tig], bb1 = b2s[8 * n + 2 * tig + 1];
            acc2[n][0] = bb0; acc2[n][1] = bb1; acc2[n][2] = bb0; acc2[n][3] = bb1;
        }
        #pragma unroll
        for (int n = 0; n < 4; n++)
            #pragma unroll
            for (int s = 0; s < 2; s++) {
                uint2 bh = w2h[s * 4 + n][lane], bl = w2l[s * 4 + n][lane];
                mma16816(acc2[n], A2h[s], bh);
                mma16816(acc2[n], A2h[s], bl);
                mma16816(acc2[n], A2l[s], bh);
            }

        // relu + split -> layer-3 A frags
        uint A3h[2][4], A3l[2][4];
        #pragma unroll
        for (int s = 0; s < 2; s++) {
            split2(fmaxf(acc2[2*s][0], 0.f),   fmaxf(acc2[2*s][1], 0.f),   A3h[s][0], A3l[s][0]);
            split2(fmaxf(acc2[2*s][2], 0.f),   fmaxf(acc2[2*s][3], 0.f),   A3h[s][1], A3l[s][1]);
            split2(fmaxf(acc2[2*s+1][0], 0.f), fmaxf(acc2[2*s+1][1], 0.f), A3h[s][2], A3l[s][2]);
            split2(fmaxf(acc2[2*s+1][2], 0.f), fmaxf(acc2[2*s+1][3], 0.f), A3h[s][3], A3l[s][3]);
        }

        // layer 3: 32 -> 1 (padded to n8; only col 0 meaningful)
        float acc3[4];
        acc3[0] = (tig == 0) ? b3s : 0.0f;
        acc3[1] = 0.0f;
        acc3[2] = acc3[0];
        acc3[3] = 0.0f;
        #pragma unroll
        for (int s = 0; s < 2; s++) {
            uint2 bh = w3h[s][lane], bl = w3l[s][lane];
            mma16816(acc3, A3h[s], bh);
            mma16816(acc3, A3h[s], bl);
            mma16816(acc3, A3l[s], bh);
        }

        if (tig == 0) {
            d_fluo[(size_t)z * NPIX + pb + gid]     = acc3[0];
            d_fluo[(size_t)z * NPIX + pb + gid + 8] = acc3[2];
        }
    }
}

// ---------------- radix-8 row pass: 256 threads, 4 rows per block ----------------
template<int DIR, int MODE>
__global__ void __launch_bounds__(256) fft_row4(
    const float* __restrict__ rin, const float* __restrict__ aberr,
    float2* __restrict__ cout)
{
    __shared__ float2 sm[4][CSTRIDE];
    int tid = threadIdx.x;
    int u = tid >> 6, t = tid & 63;
    int r = blockIdx.x * 4 + u;
    int zp = blockIdx.y;
    size_t rb = (size_t)zp * NPIX + (size_t)r * WDIM;

    float2 e[8];
    if (MODE == 0) {
        #pragma unroll
        for (int j = 0; j < 8; j++) {
            int n = t + 64 * j;
            float p = rin[(size_t)r * WDIM + n];
            float ab = aberr[rb + n];
            float sn, cs; __sincosf(ab, &sn, &cs);
            e[brev3(j)] = make_float2(p * cs, p * sn);
        }
    } else {
        size_t b0 = (size_t)(2 * zp) * NPIX + (size_t)r * WDIM;
        size_t b1 = b0 + NPIX;
        #pragma unroll
        for (int j = 0; j < 8; j++) {
            int n = t + 64 * j;
            e[brev3(j)] = make_float2(rin[b0 + n], rin[b1 + n]);
        }
    }

    fft_unit<DIR, false>(&sm[u][0], e, t, true);

    #pragma unroll
    for (int j = 0; j < 8; j++) cout[rb + j * 64 + t] = e[j];
}

// ---------------- fused colQ pass ----------------
__global__ void __launch_bounds__(256) colq_kernel(
    const float2* __restrict__ in, float2* __restrict__ outp)
{
    __shared__ float2 sm[4 * CSTRIDE];
    int tid = threadIdx.x;
    int u = tid >> 6, t = tid & 63;
    int zp = blockIdx.y;
    int col0 = blockIdx.x * 2;

    #pragma unroll
    for (int q = 0; q < 8; q++) {
        int idx = tid + q * 256;
        int c = idx & 1, pl = (idx >> 1) & 1, i = idx >> 2;
        sm[(pl * 2 + c) * CSTRIDE + PADI(i)] =
            in[(size_t)(2 * zp + pl) * NPIX + (size_t)i * WDIM + col0 + c];
    }
    __syncthreads();

    float2* s = sm + u * CSTRIDE;
    float2 e[8];
    #pragma unroll
    for (int j = 0; j < 8; j++) e[brev3(j)] = s[PADI(t + 64 * j)];
    fft_unit<-1, true>(s, e, t, true);
    #pragma unroll
    for (int j = 0; j < 8; j++) s[PADI(j * 64 + t)] = e[j];
    __syncthreads();

    bool act = (u < 2);
    if (act) {
        float2* s0 = sm + u * CSTRIDE;
        float2* s1 = sm + (2 + u) * CSTRIDE;
        #pragma unroll
        for (int j = 0; j < 8; j++) {
            int n = t + 64 * j;
            float2 a0 = s0[PADI(n)];
            float2 a1 = s1[PADI(n)];
            e[brev3(j)] = make_float2(a0.x * a0.x + a0.y * a0.y,
                                      a1.x * a1.x + a1.y * a1.y);
        }
    }
    fft_unit<+1, true>(s, e, t, act);
    if (act) {
        #pragma unroll
        for (int j = 0; j < 8; j++) s[PADI(j * 64 + t)] = e[j];
    }
    __syncthreads();

    #pragma unroll
    for (int q = 0; q < 4; q++) {
        int idx = tid + q * 256;
        int c = idx & 1, i = idx >> 1;
        outp[(size_t)zp * NPIX + (size_t)i * WDIM + col0 + c] =
            sm[c * CSTRIDE + PADI(i)];
    }
}

// ---------------- fused crossQ pass ----------------
__global__ void __launch_bounds__(128) crossq_kernel(
    const float2* __restrict__ qcol, const float2* __restrict__ cSo,
    float2* __restrict__ cout)
{
    __shared__ float2 sm[2 * CSTRIDE];
    int tid = threadIdx.x;
    int u = tid >> 6, t = tid & 63;
    int b = blockIdx.x;
    int zp = blockIdx.y;
    size_t zb = (size_t)zp * NPIX;

    int ru = (b == 0) ? (u == 0 ? 0 : 256) : (u == 0 ? b : WDIM - b);
    int pu = (b == 0) ? u : 1 - u;
    int rn = (WDIM - ru) & (WDIM - 1);
    size_t rb  = zb + (size_t)ru * WDIM;
    size_t rbm = zb + (size_t)rn * WDIM;

    float2* s = sm + u * CSTRIDE;
    float2* sp = sm + pu * CSTRIDE;

    float2 e[8];
    #pragma unroll
    for (int j = 0; j < 8; j++) e[brev3(j)] = qcol[rb + t + 64 * j];
    fft_unit<+1, false>(s, e, t, true);
    #pragma unroll
    for (int j = 0; j < 8; j++) s[PADI(j * 64 + t)] = e[j];
    __syncthreads();

    float sc = 0.25f * d_cscale;
    #pragma unroll
    for (int j = 0; j < 8; j++) {
        int n = t + 64 * j;
        int nn = (WDIM - n) & (WDIM - 1);
        float2 Sq  = s[PADI(n)];
        float2 Sqm = sp[PADI(nn)];
        float2 So  = cSo[rb + n];
        float2 Som = cSo[rbm + nn];
        float2 Po = make_float2(So.x + Som.x, So.y - Som.y);
        float2 Mo = make_float2(So.x - Som.x, So.y + Som.y);
        float2 Pq = make_float2(Sq.x + Sqm.x, Sq.y - Sqm.y);
        float2 Mq = make_float2(Sq.x - Sqm.x, Sq.y + Sqm.y);
        float2 PP = cmul(Po, Pq);
        float2 MM = cmul(Mo, Mq);
        e[brev3(j)] = make_float2(sc * (PP.x + MM.y), sc * (PP.y - MM.x));
    }
    fft_unit<-1, true>(s, e, t, true);

    #pragma unroll
    for (int j = 0; j < 8; j++) cout[rb + j * 64 + t] = e[j];
}

// ---------------- radix-8 column pass: 256 threads, 4 cols per block ----------------
template<int DIR, int MODE>
__global__ void __launch_bounds__(256) fft_col4(
    const float2* __restrict__ in, float2* __restrict__ cout, float* __restrict__ rout)
{
    __shared__ float2 sm[4 * CSTRIDE];
    int tid = threadIdx.x;
    int zp = blockIdx.y;
    int col0 = blockIdx.x * 4;
    size_t zb = (size_t)zp * NPIX;

    #pragma unroll
    for (int q = 0; q < 8; q++) {
        int l = tid + q * 256;
        int c = l & 3, i = l >> 2;
        sm[c * CSTRIDE + PADI(i)] = in[zb + (size_t)i * WDIM + col0 + c];
    }
    __syncthreads();

    int u = tid >> 6, t = tid & 63;
    float2* s = sm + u * CSTRIDE;
    float2 e[8];
    #pragma unroll
    for (int j = 0; j < 8; j++) e[brev3(j)] = s[PADI(t + 64 * j)];
    fft_unit<DIR, true>(s, e, t, true);
    #pragma unroll
    for (int j = 0; j < 8; j++) s[PADI(j * 64 + t)] = e[j];
    __syncthreads();

    #pragma unroll
    for (int q = 0; q < 8; q++) {
        int l = tid + q * 256;
        int c = l & 3, i = l >> 2;
        float2 v = sm[c * CSTRIDE + PADI(i)];
        size_t sp = (size_t)i * WDIM + col0 + c;
        if (MODE == 1) {
            cout[zb + sp] = v;
        } else {
            rout[(size_t)(2 * zp) * NPIX + sp]     = v.x;
            rout[(size_t)(2 * zp + 1) * NPIX + sp] = v.y;
        }
    }
}

// ---------------- launcher ----------------
extern "C" void kernel_launch(void* const* d_in, const int* in_sizes, int n_in,
                              void* d_out, int out_size)
{
    const float* z     = (const float*)d_in[0];
    const float* grid  = (const float*)d_in[1];
    const float* zdat  = (const float*)d_in[2];
    const float* w1    = (const float*)d_in[3];
    const float* b1    = (const float*)d_in[4];
    const float* w2    = (const float*)d_in[5];
    const float* b2    = (const float*)d_in[6];
    const float* w3    = (const float*)d_in[7];
    const float* b3    = (const float*)d_in[8];
    const float* pupil = (const float*)d_in[9];
    const float* aberr = (const float*)d_in[10];
    const float* lerp  = (const float*)d_in[11];
    const int*   x0    = (const int*)d_in[12];
    const int*   y0    = (const int*)d_in[13];
    const int*   x1    = (const int*)d_in[14];
    const int*   y1    = (const int*)d_in[15];
    float* out = (float*)d_out;

    float2* tmpA; float2* tmpB; float* qbuf; float* fluo;
    cudaGetSymbolAddress((void**)&tmpA, d_tmpA);
    cudaGetSymbolAddress((void**)&tmpB, d_tmpB);
    cudaGetSymbolAddress((void**)&qbuf, d_q);
    cudaGetSymbolAddress((void**)&fluo, d_fluo);
    float2* qcol = (float2*)qbuf;
    float2* Cbuf = (float2*)fluo;

    // scalar normalizer 1/(N^4 * sum(pupil))
    pupil_part<<<256, 256>>>(pupil);
    pupil_final<<<1, 256>>>();

    // render path
    xyfeat_kernel<<<NPIX / 256, 256>>>(grid, lerp, x0, y0, x1, y1);
    mlp_kernel<<<dim3(NPIX / 128, ZM), 128>>>(z, zdat, w1, b1, w2, b2, w3, b3);

    // pupil path: rowIFFT(P) -> tmpA (30 planes)
    fft_row4<-1, 0><<<dim3(WDIM / 4, ZM), 256>>>(pupil, aberr, tmpA);
    // fused: col IFFT x2, |.|^2, packed forward col FFT -> qcol (15 planes)
    colq_kernel<<<dim3(WDIM / 2, NZP), 256>>>(tmpA, qcol);

    // So = F2(fluo) packed -> tmpB (col pass in-place)
    fft_row4<+1, 1><<<dim3(WDIM / 4, NZP), 256>>>(fluo, nullptr, tmpB);
    fft_col4<+1, 1><<<dim3(WDIM / 4, NZP), 256>>>(tmpB, tmpB, nullptr);

    // fused: Sq rows + Hermitian cross spectrum + row IFFT -> Cbuf
    crossq_kernel<<<dim3(WDIM / 2, NZP), 128>>>(qcol, tmpB, Cbuf);
    // inverse col pass, split packed planes into the 30 real output planes
    fft_col4<-1, 2><<<dim3(WDIM / 4, NZP), 256>>>(Cbuf, nullptr, out);
}

// round 9
// speedup vs baseline: 4.2478x; 1.1097x over previous
#include <cuda_runtime.h>
#include <cstdint>

#define WDIM 512
#define NPIX (512*512)
#define ZM 30
#define NZP (ZM/2)

typedef unsigned long long ull;
typedef unsigned int uint;

// ---------------- device scratch ----------------
__device__ __align__(16) float2 d_tmpA[(size_t)ZM * NPIX];   // 63 MB
__device__ __align__(16) float2 d_tmpB[(size_t)ZM * NPIX];   // 63 MB
__device__ __align__(16) float  d_q   [(size_t)ZM * NPIX];   // packed colFFT(q), 15 cpx planes
__device__ __align__(16) float  d_fluo[(size_t)ZM * NPIX];   // fluo, reused as Cbuf
__device__ __align__(16) float  d_xyf [(size_t)NPIX * 16];   // 16 MB: [0,8MB)=hi b32 pairs, [8,16MB)=lo
__device__ int   d_part[256];
__device__ float d_cscale;

// ---------------- bf16 split helpers ----------------
// pack (x0 -> low bf16, x1 -> high bf16); lo = residual pair
__device__ __forceinline__ void split2(float x0, float x1, uint& h, uint& l) {
    uint hp;
    asm("cvt.rn.bf16x2.f32 %0, %1, %2;" : "=r"(hp) : "f"(x1), "f"(x0));
    float h0 = __uint_as_float(hp << 16);
    float h1 = __uint_as_float(hp & 0xffff0000u);
    float l0 = x0 - h0, l1 = x1 - h1;
    asm("cvt.rn.bf16x2.f32 %0, %1, %2;" : "=r"(l) : "f"(l1), "f"(l0));
    h = hp;
}

__device__ __forceinline__ void mma16816(float c[4], const uint a[4], uint2 b) {
    asm("mma.sync.aligned.m16n8k16.row.col.f32.bf16.bf16.f32 "
        "{%0,%1,%2,%3}, {%4,%5,%6,%7}, {%8,%9}, {%0,%1,%2,%3};"
        : "+f"(c[0]), "+f"(c[1]), "+f"(c[2]), "+f"(c[3])
        : "r"(a[0]), "r"(a[1]), "r"(a[2]), "r"(a[3]), "r"(b.x), "r"(b.y));
}

// ---------------- complex helpers ----------------
__device__ __forceinline__ float2 cmul(float2 a, float2 b) {
    return make_float2(fmaf(a.x, b.x, -a.y * b.y), fmaf(a.x, b.y, a.y * b.x));
}
__device__ __forceinline__ float2 cadd(float2 a, float2 b) { return make_float2(a.x + b.x, a.y + b.y); }
__device__ __forceinline__ float2 csub(float2 a, float2 b) { return make_float2(a.x - b.x, a.y - b.y); }

__device__ __forceinline__ int brev3(int j) { return ((j & 1) << 2) | (j & 2) | ((j >> 2) & 1); }
__device__ __forceinline__ int brev6(int t) { return (int)(__brev((unsigned)t) >> 26); }

#define PADI(p) ((p) + ((p) >> 5))
#define CSTRIDE 532

// ---------------- radix-8 butterflies ----------------
template<int DIR>
__device__ __forceinline__ void bf8_0(float2 e[8])
{
    const float d = (DIR > 0) ? 1.0f : -1.0f;
    float2 f[8];
    #pragma unroll
    for (int m = 0; m < 4; m++) {
        float2 u = e[2 * m], v = e[2 * m + 1];
        f[2 * m]     = cadd(u, v);
        f[2 * m + 1] = csub(u, v);
    }
    float2 g[8];
    #pragma unroll
    for (int hh = 0; hh < 2; hh++) {
        int o = 4 * hh;
        float2 v0 = f[o + 2];
        float2 v1 = make_float2(d * f[o + 3].y, -d * f[o + 3].x);
        g[o + 0] = cadd(f[o + 0], v0); g[o + 2] = csub(f[o + 0], v0);
        g[o + 1] = cadd(f[o + 1], v1); g[o + 3] = csub(f[o + 1], v1);
    }
    const float S2 = 0.70710678118654752f;
    float2 v0 = g[4];
    float2 v1 = cmul(g[5], make_float2(S2, -d * S2));
    float2 v2 = make_float2(d * g[6].y, -d * g[6].x);
    float2 v3 = cmul(g[7], make_float2(-S2, -d * S2));
    e[0] = cadd(g[0], v0); e[4] = csub(g[0], v0);
    e[1] = cadd(g[1], v1); e[5] = csub(g[1], v1);
    e[2] = cadd(g[2], v2); e[6] = csub(g[2], v2);
    e[3] = cadd(g[3], v3); e[7] = csub(g[3], v3);
}

template<int DIR>
__device__ __forceinline__ void bf8_g(float2 e[8], float r)
{
    const float d = (DIR > 0) ? 1.0f : -1.0f;
    float s1, c1;
    sincospif(r, &s1, &c1);
    float2 t1 = make_float2(c1, -d * s1);
    float2 t2 = cmul(t1, t1);
    float2 t4 = cmul(t2, t2);

    float2 f[8];
    #pragma unroll
    for (int m = 0; m < 4; m++) {
        float2 v = cmul(e[2 * m + 1], t4);
        f[2 * m]     = cadd(e[2 * m], v);
        f[2 * m + 1] = csub(e[2 * m], v);
    }
    float2 wb1 = make_float2(d * t2.y, -d * t2.x);
    float2 g[8];
    #pragma unroll
    for (int hh = 0; hh < 2; hh++) {
        int o = 4 * hh;
        float2 v0 = cmul(f[o + 2], t2);
        float2 v1 = cmul(f[o + 3], wb1);
        g[o + 0] = cadd(f[o + 0], v0); g[o + 2] = csub(f[o + 0], v0);
        g[o + 1] = cadd(f[o + 1], v1); g[o + 3] = csub(f[o + 1], v1);
    }
    const float S2 = 0.70710678118654752f;
    float2 wc1 = make_float2(S2 * (t1.x + d * t1.y), S2 * (t1.y - d * t1.x));
    float2 wc2 = make_float2(d * t1.y, -d * t1.x);
    float2 wc3 = make_float2(S2 * (-t1.x + d * t1.y), S2 * (-t1.y - d * t1.x));
    float2 v0 = cmul(g[4], t1);
    float2 v1 = cmul(g[5], wc1);
    float2 v2 = cmul(g[6], wc2);
    float2 v3 = cmul(g[7], wc3);
    e[0] = cadd(g[0], v0); e[4] = csub(g[0], v0);
    e[1] = cadd(g[1], v1); e[5] = csub(g[1], v1);
    e[2] = cadd(g[2], v2); e[6] = csub(g[2], v2);
    e[3] = cadd(g[3], v3); e[7] = csub(g[3], v3);
}

template<int DIR, bool PRESYNC>
__device__ __forceinline__ void fft_unit(float2* s, float2 e[8], int t, bool active)
{
    if (active) bf8_0<DIR>(e);
    if (PRESYNC) __syncthreads();
    if (active) {
        int b = brev6(t);
        #pragma unroll
        for (int j = 0; j < 8; j++) s[PADI(8 * b + j)] = e[j];
    }
    __syncthreads();
    if (active) {
        int b2 = t >> 3, k = t & 7;
        #pragma unroll
        for (int j = 0; j < 8; j++) e[j] = s[PADI(b2 * 64 + j * 8 + k)];
        bf8_g<DIR>(e, (float)k * (1.0f / 32.0f));
        #pragma unroll
        for (int j = 0; j < 8; j++) s[PADI(b2 * 64 + j * 8 + k)] = e[j];
    }
    __syncthreads();
    if (active) {
        #pragma unroll
        for (int j = 0; j < 8; j++) e[j] = s[PADI(j * 64 + t)];
        bf8_g<DIR>(e, (float)t * (1.0f / 256.0f));
    }
}

// ---------------- pupil sum ----------------
__global__ void __launch_bounds__(256) pupil_part(const float* __restrict__ pupil) {
    int tid = threadIdx.x, b = blockIdx.x;
    int v = 0;
    #pragma unroll 4
    for (int q = 0; q < 4; q++) {
        int i = b * 1024 + q * 256 + tid;
        v += (pupil[i] > 0.5f) ? 1 : 0;
    }
    #pragma unroll
    for (int o = 16; o; o >>= 1) v += __shfl_xor_sync(0xffffffffu, v, o);
    __shared__ int ws[8];
    if ((tid & 31) == 0) ws[tid >> 5] = v;
    __syncthreads();
    if (tid == 0) {
        int s = 0;
        #pragma unroll
        for (int w = 0; w < 8; w++) s += ws[w];
        d_part[b] = s;
    }
}

__global__ void __launch_bounds__(256) pupil_final() {
    int tid = threadIdx.x;
    int v = d_part[tid];
    #pragma unroll
    for (int o = 16; o; o >>= 1) v += __shfl_xor_sync(0xffffffffu, v, o);
    __shared__ int ws[8];
    if ((tid & 31) == 0) ws[tid >> 5] = v;
    __syncthreads();
    if (tid == 0) {
        int s = 0;
        #pragma unroll
        for (int w = 0; w < 8; w++) s += ws[w];
        d_cscale = (float)(1.0 / (68719476736.0 * (double)s));
    }
}

// ---------------- bilinear xy_feat + bf16 hi/lo split ----------------
__global__ void __launch_bounds__(256) xyfeat_kernel(
    const float* __restrict__ grid, const float* __restrict__ lerp,
    const int* __restrict__ x0, const int* __restrict__ y0,
    const int* __restrict__ x1, const int* __restrict__ y1)
{
    int p = blockIdx.x * 256 + threadIdx.x;
    float2 l = ((const float2*)lerp)[p];
    float lx = l.x, ly = l.y;
    int X0 = x0[p], Y0 = y0[p], X1 = x1[p], Y1 = y1[p];
    float w00 = (1.f - lx) * (1.f - ly);
    float w10 = lx * (1.f - ly);
    float w01 = (1.f - lx) * ly;
    float w11 = lx * ly;
    const float4* g00 = (const float4*)(grid + ((size_t)Y0 * WDIM + X0) * 16);
    const float4* g10 = (const float4*)(grid + ((size_t)Y0 * WDIM + X1) * 16);
    const float4* g01 = (const float4*)(grid + ((size_t)Y1 * WDIM + X0) * 16);
    const float4* g11 = (const float4*)(grid + ((size_t)Y1 * WDIM + X1) * 16);
    float f[16];
    #pragma unroll
    for (int q = 0; q < 4; q++) {
        float4 a = g00[q], b = g10[q], c = g01[q], d = g11[q];
        f[q * 4 + 0] = a.x * w00 + b.x * w10 + c.x * w01 + d.x * w11;
        f[q * 4 + 1] = a.y * w00 + b.y * w10 + c.y * w01 + d.y * w11;
        f[q * 4 + 2] = a.z * w00 + b.z * w10 + c.z * w01 + d.z * w11;
        f[q * 4 + 3] = a.w * w00 + b.w * w10 + c.w * w01 + d.w * w11;
    }
    uint hi[8], lo[8];
    #pragma unroll
    for (int t = 0; t < 8; t++) split2(f[2 * t], f[2 * t + 1], hi[t], lo[t]);
    uint* hip = (uint*)d_xyf;
    uint* lop = hip + (size_t)NPIX * 8;
    ((uint4*)(hip + (size_t)p * 8))[0] = make_uint4(hi[0], hi[1], hi[2], hi[3]);
    ((uint4*)(hip + (size_t)p * 8))[1] = make_uint4(hi[4], hi[5], hi[6], hi[7]);
    ((uint4*)(lop + (size_t)p * 8))[0] = make_uint4(lo[0], lo[1], lo[2], lo[3]);
    ((uint4*)(lop + (size_t)p * 8))[1] = make_uint4(lo[4], lo[5], lo[6], lo[7]);
}

// ---------------- tensor-core MLP (bf16 3-term split) ----------------
// Block: 128 threads (4 warps), each warp does 64 pixels (4 m16 tiles), one z.
// Chain: feat[16] -> 32 -> 32 -> 1, relu between; inter-layer data stays in
// registers (C-fragment layout == A-fragment layout for m16n8k16).
// 4 unrolled tiles give 16 independent MMA chains to hide HMMA latency.
__global__ void __launch_bounds__(128) mlp_kernel(
    const float* __restrict__ zarr, const float* __restrict__ zdat,
    const float* __restrict__ w1, const float* __restrict__ b1,
    const float* __restrict__ w2, const float* __restrict__ b2,
    const float* __restrict__ w3, const float* __restrict__ b3)
{
    __shared__ uint2 w1h[4][32], w1l[4][32];     // [n][lane]
    __shared__ uint2 w2h[8][32], w2l[8][32];     // [s*4+n][lane]
    __shared__ uint2 w3h[2][32], w3l[2][32];     // [s][lane]
    __shared__ float b1s[32], b2s[32];
    __shared__ float b3s;

    int tid = threadIdx.x, lane = tid & 31, warp = tid >> 5;
    int gid = lane >> 2, tig = lane & 3;
    int z = blockIdx.y;

    if (warp == 0) {
        float zv = zarr[z];
        float zn = (29.0f * zv) / 30.0f;
        float zfl = floorf(zn);
        int z0 = (int)zfl; z0 = min(max(z0, 0), ZM - 1);
        int z1 = min(z0 + 1, ZM - 1);
        float zl = zn - zfl;

        int ks[4] = { 2 * tig, 2 * tig + 1, 2 * tig + 8, 2 * tig + 9 };
        float zf[4];
        #pragma unroll
        for (int i = 0; i < 4; i++)
            zf[i] = zdat[z0 * 16 + ks[i]] * (1.0f - zl) + zdat[z1 * 16 + ks[i]] * zl;

        #pragma unroll
        for (int n = 0; n < 4; n++) {
            float wv[4];
            #pragma unroll
            for (int i = 0; i < 4; i++) wv[i] = w1[ks[i] * 32 + 8 * n + gid] * zf[i];
            uint h0, l0, h1, l1;
            split2(wv[0], wv[1], h0, l0);
            split2(wv[2], wv[3], h1, l1);
            w1h[n][lane] = make_uint2(h0, h1);
            w1l[n][lane] = make_uint2(l0, l1);
        }
        #pragma unroll
        for (int s = 0; s < 2; s++)
            #pragma unroll
            for (int n = 0; n < 4; n++) {
                float wv[4];
                #pragma unroll
                for (int i = 0; i < 4; i++) wv[i] = w2[(16 * s + ks[i]) * 32 + 8 * n + gid];
                uint h0, l0, h1, l1;
                split2(wv[0], wv[1], h0, l0);
                split2(wv[2], wv[3], h1, l1);
                w2h[s * 4 + n][lane] = make_uint2(h0, h1);
                w2l[s * 4 + n][lane] = make_uint2(l0, l1);
            }
        #pragma unroll
        for (int s = 0; s < 2; s++) {
            float wv[4];
            #pragma unroll
            for (int i = 0; i < 4; i++) wv[i] = (gid == 0) ? w3[16 * s + ks[i]] : 0.0f;
            uint h0, l0, h1, l1;
            split2(wv[0], wv[1], h0, l0);
            split2(wv[2], wv[3], h1, l1);
            w3h[s][lane] = make_uint2(h0, h1);
            w3l[s][lane] = make_uint2(l0, l1);
        }
        b1s[lane] = b1[lane];
        b2s[lane] = b2[lane];
        if (lane == 0) b3s = b3[0];
    }
    __syncthreads();

    const uint* hip = (const uint*)d_xyf;
    const uint* lop = hip + (size_t)NPIX * 8;
    uint pxb = blockIdx.x * 256 + warp * 64;
    float* fout = d_fluo + (size_t)z * NPIX;

    #pragma unroll
    for (int m = 0; m < 4; m++) {
        uint pb = pxb + m * 16;
        uint r0 = (pb + gid) * 8u;
        uint r1 = (pb + gid + 8) * 8u;
        uint Ah[4], Al[4];
        Ah[0] = hip[r0 + tig];     Ah[1] = hip[r1 + tig];
        Ah[2] = hip[r0 + tig + 4]; Ah[3] = hip[r1 + tig + 4];
        Al[0] = lop[r0 + tig];     Al[1] = lop[r1 + tig];
        Al[2] = lop[r0 + tig + 4]; Al[3] = lop[r1 + tig + 4];

        // layer 1: 16 -> 32
        float acc[4][4];
        #pragma unroll
        for (int n = 0; n < 4; n++) {
            float bb0 = b1s[8 * n + 2 * tig], bb1 = b1s[8 * n + 2 * tig + 1];
            acc[n][0] = bb0; acc[n][1] = bb1; acc[n][2] = bb0; acc[n][3] = bb1;
        }
        #pragma unroll
        for (int n = 0; n < 4; n++) {
            uint2 bh = w1h[n][lane], bl = w1l[n][lane];
            mma16816(acc[n], Ah, bh);
            mma16816(acc[n], Ah, bl);
            mma16816(acc[n], Al, bh);
        }

        // relu + split -> layer-2 A frags
        uint A2h[2][4], A2l[2][4];
        #pragma unroll
        for (int s = 0; s < 2; s++) {
            split2(fmaxf(acc[2*s][0], 0.f),   fmaxf(acc[2*s][1], 0.f),   A2h[s][0], A2l[s][0]);
            split2(fmaxf(acc[2*s][2], 0.f),   fmaxf(acc[2*s][3], 0.f),   A2h[s][1], A2l[s][1]);
            split2(fmaxf(acc[2*s+1][0], 0.f), fmaxf(acc[2*s+1][1], 0.f), A2h[s][2], A2l[s][2]);
            split2(fmaxf(acc[2*s+1][2], 0.f), fmaxf(acc[2*s+1][3], 0.f), A2h[s][3], A2l[s][3]);
        }

        // layer 2: 32 -> 32
        float acc2[4][4];
        #pragma unroll
        for (int n = 0; n < 4; n++) {
            float bb0 = b2s[8 * n + 2 * tig], bb1 = b2s[8 * n + 2 * tig + 1];
            acc2[n][0] = bb0; acc2[n][1] = bb1; acc2[n][2] = bb0; acc2[n][3] = bb1;
        }
        #pragma unroll
        for (int n = 0; n < 4; n++)
            #pragma unroll
            for (int s = 0; s < 2; s++) {
                uint2 bh = w2h[s * 4 + n][lane], bl = w2l[s * 4 + n][lane];
                mma16816(acc2[n], A2h[s], bh);
                mma16816(acc2[n], A2h[s], bl);
                mma16816(acc2[n], A2l[s], bh);
            }

        // relu + split -> layer-3 A frags
        uint A3h[2][4], A3l[2][4];
        #pragma unroll
        for (int s = 0; s < 2; s++) {
            split2(fmaxf(acc2[2*s][0], 0.f),   fmaxf(acc2[2*s][1], 0.f),   A3h[s][0], A3l[s][0]);
            split2(fmaxf(acc2[2*s][2], 0.f),   fmaxf(acc2[2*s][3], 0.f),   A3h[s][1], A3l[s][1]);
            split2(fmaxf(acc2[2*s+1][0], 0.f), fmaxf(acc2[2*s+1][1], 0.f), A3h[s][2], A3l[s][2]);
            split2(fmaxf(acc2[2*s+1][2], 0.f), fmaxf(acc2[2*s+1][3], 0.f), A3h[s][3], A3l[s][3]);
        }

        // layer 3: 32 -> 1 (padded to n8; only col 0 meaningful)
        float acc3[4];
        acc3[0] = (tig == 0) ? b3s : 0.0f;
        acc3[1] = 0.0f;
        acc3[2] = acc3[0];
        acc3[3] = 0.0f;
        #pragma unroll
        for (int s = 0; s < 2; s++) {
            uint2 bh = w3h[s][lane], bl = w3l[s][lane];
            mma16816(acc3, A3h[s], bh);
            mma16816(acc3, A3h[s], bl);
            mma16816(acc3, A3l[s], bh);
        }

        if (tig == 0) {
            fout[pb + gid]     = acc3[0];
            fout[pb + gid + 8] = acc3[2];
        }
    }
}

// ---------------- radix-8 row pass: 256 threads, 4 rows per block ----------------
template<int DIR, int MODE>
__global__ void __launch_bounds__(256) fft_row4(
    const float* __restrict__ rin, const float* __restrict__ aberr,
    float2* __restrict__ cout)
{
    __shared__ float2 sm[4][CSTRIDE];
    int tid = threadIdx.x;
    int u = tid >> 6, t = tid & 63;
    int r = blockIdx.x * 4 + u;
    int zp = blockIdx.y;
    size_t rb = (size_t)zp * NPIX + (size_t)r * WDIM;

    float2 e[8];
    if (MODE == 0) {
        #pragma unroll
        for (int j = 0; j < 8; j++) {
            int n = t + 64 * j;
            float p = rin[(size_t)r * WDIM + n];
            float ab = aberr[rb + n];
            float sn, cs; __sincosf(ab, &sn, &cs);
            e[brev3(j)] = make_float2(p * cs, p * sn);
        }
    } else {
        size_t b0 = (size_t)(2 * zp) * NPIX + (size_t)r * WDIM;
        size_t b1 = b0 + NPIX;
        #pragma unroll
        for (int j = 0; j < 8; j++) {
            int n = t + 64 * j;
            e[brev3(j)] = make_float2(rin[b0 + n], rin[b1 + n]);
        }
    }

    fft_unit<DIR, false>(&sm[u][0], e, t, true);

    #pragma unroll
    for (int j = 0; j < 8; j++) cout[rb + j * 64 + t] = e[j];
}

// ---------------- fused colQ pass ----------------
__global__ void __launch_bounds__(256) colq_kernel(
    const float2* __restrict__ in, float2* __restrict__ outp)
{
    __shared__ float2 sm[4 * CSTRIDE];
    int tid = threadIdx.x;
    int u = tid >> 6, t = tid & 63;
    int zp = blockIdx.y;
    int col0 = blockIdx.x * 2;

    #pragma unroll
    for (int q = 0; q < 8; q++) {
        int idx = tid + q * 256;
        int c = idx & 1, pl = (idx >> 1) & 1, i = idx >> 2;
        sm[(pl * 2 + c) * CSTRIDE + PADI(i)] =
            in[(size_t)(2 * zp + pl) * NPIX + (size_t)i * WDIM + col0 + c];
    }
    __syncthreads();

    float2* s = sm + u * CSTRIDE;
    float2 e[8];
    #pragma unroll
    for (int j = 0; j < 8; j++) e[brev3(j)] = s[PADI(t + 64 * j)];
    fft_unit<-1, true>(s, e, t, true);
    #pragma unroll
    for (int j = 0; j < 8; j++) s[PADI(j * 64 + t)] = e[j];
    __syncthreads();

    bool act = (u < 2);
    if (act) {
        float2* s0 = sm + u * CSTRIDE;
        float2* s1 = sm + (2 + u) * CSTRIDE;
        #pragma unroll
        for (int j = 0; j < 8; j++) {
            int n = t + 64 * j;
            float2 a0 = s0[PADI(n)];
            float2 a1 = s1[PADI(n)];
            e[brev3(j)] = make_float2(a0.x * a0.x + a0.y * a0.y,
                                      a1.x * a1.x + a1.y * a1.y);
        }
    }
    fft_unit<+1, true>(s, e, t, act);
    if (act) {
        #pragma unroll
        for (int j = 0; j < 8; j++) s[PADI(j * 64 + t)] = e[j];
    }
    __syncthreads();

    #pragma unroll
    for (int q = 0; q < 4; q++) {
        int idx = tid + q * 256;
        int c = idx & 1, i = idx >> 1;
        outp[(size_t)zp * NPIX + (size_t)i * WDIM + col0 + c] =
            sm[c * CSTRIDE + PADI(i)];
    }
}

// ---------------- fused crossQ pass ----------------
__global__ void __launch_bounds__(128) crossq_kernel(
    const float2* __restrict__ qcol, const float2* __restrict__ cSo,
    float2* __restrict__ cout)
{
    __shared__ float2 sm[2 * CSTRIDE];
    int tid = threadIdx.x;
    int u = tid >> 6, t = tid & 63;
    int b = blockIdx.x;
    int zp = blockIdx.y;
    size_t zb = (size_t)zp * NPIX;

    int ru = (b == 0) ? (u == 0 ? 0 : 256) : (u == 0 ? b : WDIM - b);
    int pu = (b == 0) ? u : 1 - u;
    int rn = (WDIM - ru) & (WDIM - 1);
    size_t rb  = zb + (size_t)ru * WDIM;
    size_t rbm = zb + (size_t)rn * WDIM;

    float2* s = sm + u * CSTRIDE;
    float2* sp = sm + pu * CSTRIDE;

    float2 e[8];
    #pragma unroll
    for (int j = 0; j < 8; j++) e[brev3(j)] = qcol[rb + t + 64 * j];
    fft_unit<+1, false>(s, e, t, true);
    #pragma unroll
    for (int j = 0; j < 8; j++) s[PADI(j * 64 + t)] = e[j];
    __syncthreads();

    float sc = 0.25f * d_cscale;
    #pragma unroll
    for (int j = 0; j < 8; j++) {
        int n = t + 64 * j;
        int nn = (WDIM - n) & (WDIM - 1);
        float2 Sq  = s[PADI(n)];
        float2 Sqm = sp[PADI(nn)];
        float2 So  = cSo[rb + n];
        float2 Som = cSo[rbm + nn];
        float2 Po = make_float2(So.x + Som.x, So.y - Som.y);
        float2 Mo = make_float2(So.x - Som.x, So.y + Som.y);
        float2 Pq = make_float2(Sq.x + Sqm.x, Sq.y - Sqm.y);
        float2 Mq = make_float2(Sq.x - Sqm.x, Sq.y + Sqm.y);
        float2 PP = cmul(Po, Pq);
        float2 MM = cmul(Mo, Mq);
        e[brev3(j)] = make_float2(sc * (PP.x + MM.y), sc * (PP.y - MM.x));
    }
    fft_unit<-1, true>(s, e, t, true);

    #pragma unroll
    for (int j = 0; j < 8; j++) cout[rb + j * 64 + t] = e[j];
}

// ---------------- radix-8 column pass: 256 threads, 4 cols per block ----------------
template<int DIR, int MODE>
__global__ void __launch_bounds__(256) fft_col4(
    const float2* __restrict__ in, float2* __restrict__ cout, float* __restrict__ rout)
{
    __shared__ float2 sm[4 * CSTRIDE];
    int tid = threadIdx.x;
    int zp = blockIdx.y;
    int col0 = blockIdx.x * 4;
    size_t zb = (size_t)zp * NPIX;

    #pragma unroll
    for (int q = 0; q < 8; q++) {
        int l = tid + q * 256;
        int c = l & 3, i = l >> 2;
        sm[c * CSTRIDE + PADI(i)] = in[zb + (size_t)i * WDIM + col0 + c];
    }
    __syncthreads();

    int u = tid >> 6, t = tid & 63;
    float2* s = sm + u * CSTRIDE;
    float2 e[8];
    #pragma unroll
    for (int j = 0; j < 8; j++) e[brev3(j)] = s[PADI(t + 64 * j)];
    fft_unit<DIR, true>(s, e, t, true);
    #pragma unroll
    for (int j = 0; j < 8; j++) s[PADI(j * 64 + t)] = e[j];
    __syncthreads();

    #pragma unroll
    for (int q = 0; q < 8; q++) {
        int l = tid + q * 256;
        int c = l & 3, i = l >> 2;
        float2 v = sm[c * CSTRIDE + PADI(i)];
        size_t sp = (size_t)i * WDIM + col0 + c;
        if (MODE == 1) {
            cout[zb + sp] = v;
        } else {
            rout[(size_t)(2 * zp) * NPIX + sp]     = v.x;
            rout[(size_t)(2 * zp + 1) * NPIX + sp] = v.y;
        }
    }
}

// ---------------- launcher ----------------
extern "C" void kernel_launch(void* const* d_in, const int* in_sizes, int n_in,
                              void* d_out, int out_size)
{
    const float* z     = (const float*)d_in[0];
    const float* grid  = (const float*)d_in[1];
    const float* zdat  = (const float*)d_in[2];
    const float* w1    = (const float*)d_in[3];
    const float* b1    = (const float*)d_in[4];
    const float* w2    = (const float*)d_in[5];
    const float* b2    = (const float*)d_in[6];
    const float* w3    = (const float*)d_in[7];
    const float* b3    = (const float*)d_in[8];
    const float* pupil = (const float*)d_in[9];
    const float* aberr = (const float*)d_in[10];
    const float* lerp  = (const float*)d_in[11];
    const int*   x0    = (const int*)d_in[12];
    const int*   y0    = (const int*)d_in[13];
    const int*   x1    = (const int*)d_in[14];
    const int*   y1    = (const int*)d_in[15];
    float* out = (float*)d_out;

    float2* tmpA; float2* tmpB; float* qbuf; float* fluo;
    cudaGetSymbolAddress((void**)&tmpA, d_tmpA);
    cudaGetSymbolAddress((void**)&tmpB, d_tmpB);
    cudaGetSymbolAddress((void**)&qbuf, d_q);
    cudaGetSymbolAddress((void**)&fluo, d_fluo);
    float2* qcol = (float2*)qbuf;
    float2* Cbuf = (float2*)fluo;

    // scalar normalizer 1/(N^4 * sum(pupil))
    pupil_part<<<256, 256>>>(pupil);
    pupil_final<<<1, 256>>>();

    // render path
    xyfeat_kernel<<<NPIX / 256, 256>>>(grid, lerp, x0, y0, x1, y1);
    mlp_kernel<<<dim3(NPIX / 256, ZM), 128>>>(z, zdat, w1, b1, w2, b2, w3, b3);

    // pupil path: rowIFFT(P) -> tmpA (30 planes)
    fft_row4<-1, 0><<<dim3(WDIM / 4, ZM), 256>>>(pupil, aberr, tmpA);
    // fused: col IFFT x2, |.|^2, packed forward col FFT -> qcol (15 planes)
    colq_kernel<<<dim3(WDIM / 2, NZP), 256>>>(tmpA, qcol);

    // So = F2(fluo) packed -> tmpB (col pass in-place)
    fft_row4<+1, 1><<<dim3(WDIM / 4, NZP), 256>>>(fluo, nullptr, tmpB);
    fft_col4<+1, 1><<<dim3(WDIM / 4, NZP), 256>>>(tmpB, tmpB, nullptr);

    // fused: Sq rows + Hermitian cross spectrum + row IFFT -> Cbuf
    crossq_kernel<<<dim3(WDIM / 2, NZP), 128>>>(qcol, tmpB, Cbuf);
    // inverse col pass, split packed planes into the 30 real output planes
    fft_col4<-1, 2><<<dim3(WDIM / 4, NZP), 256>>>(Cbuf, nullptr, out);
}

// round 10
// speedup vs baseline: 4.5542x; 1.0721x over previous
#include <cuda_runtime.h>
#include <cstdint>

#define WDIM 512
#define NPIX (512*512)
#define ZM 30
#define NZP (ZM/2)

typedef unsigned long long ull;
typedef unsigned int uint;

// ---------------- device scratch ----------------
__device__ __align__(16) float2 d_tmpA[(size_t)ZM * NPIX];   // 63 MB
__device__ __align__(16) float2 d_tmpB[(size_t)ZM * NPIX];   // 63 MB
__device__ __align__(16) float  d_q   [(size_t)ZM * NPIX];   // packed colFFT(q), 15 cpx planes
__device__ __align__(16) float  d_fluo[(size_t)ZM * NPIX];   // fluo, reused as Cbuf
__device__ __align__(16) float  d_xyf [(size_t)NPIX * 16];   // 16 MB: [0,8MB)=hi b32 pairs, [8,16MB)=lo
__device__ int   d_part[256];
__device__ float d_cscale;

// ---------------- bf16 split helpers ----------------
// pack (x0 -> low bf16, x1 -> high bf16); lo = residual pair
__device__ __forceinline__ void split2(float x0, float x1, uint& h, uint& l) {
    uint hp;
    asm("cvt.rn.bf16x2.f32 %0, %1, %2;" : "=r"(hp) : "f"(x1), "f"(x0));
    float h0 = __uint_as_float(hp << 16);
    float h1 = __uint_as_float(hp & 0xffff0000u);
    float l0 = x0 - h0, l1 = x1 - h1;
    asm("cvt.rn.bf16x2.f32 %0, %1, %2;" : "=r"(l) : "f"(l1), "f"(l0));
    h = hp;
}

__device__ __forceinline__ void mma16816(float c[4], const uint a[4], uint2 b) {
    asm("mma.sync.aligned.m16n8k16.row.col.f32.bf16.bf16.f32 "
        "{%0,%1,%2,%3}, {%4,%5,%6,%7}, {%8,%9}, {%0,%1,%2,%3};"
        : "+f"(c[0]), "+f"(c[1]), "+f"(c[2]), "+f"(c[3])
        : "r"(a[0]), "r"(a[1]), "r"(a[2]), "r"(a[3]), "r"(b.x), "r"(b.y));
}

// ---------------- complex helpers ----------------
__device__ __forceinline__ float2 cmul(float2 a, float2 b) {
    return make_float2(fmaf(a.x, b.x, -a.y * b.y), fmaf(a.x, b.y, a.y * b.x));
}
__device__ __forceinline__ float2 cadd(float2 a, float2 b) { return make_float2(a.x + b.x, a.y + b.y); }
__device__ __forceinline__ float2 csub(float2 a, float2 b) { return make_float2(a.x - b.x, a.y - b.y); }

__device__ __forceinline__ int brev3(int j) { return ((j & 1) << 2) | (j & 2) | ((j >> 2) & 1); }
__device__ __forceinline__ int brev6(int t) { return (int)(__brev((unsigned)t) >> 26); }

#define PADI(p) ((p) + ((p) >> 5))
#define CSTRIDE 532

// ---------------- radix-8 butterflies ----------------
template<int DIR>
__device__ __forceinline__ void bf8_0(float2 e[8])
{
    const float d = (DIR > 0) ? 1.0f : -1.0f;
    float2 f[8];
    #pragma unroll
    for (int m = 0; m < 4; m++) {
        float2 u = e[2 * m], v = e[2 * m + 1];
        f[2 * m]     = cadd(u, v);
        f[2 * m + 1] = csub(u, v);
    }
    float2 g[8];
    #pragma unroll
    for (int hh = 0; hh < 2; hh++) {
        int o = 4 * hh;
        float2 v0 = f[o + 2];
        float2 v1 = make_float2(d * f[o + 3].y, -d * f[o + 3].x);
        g[o + 0] = cadd(f[o + 0], v0); g[o + 2] = csub(f[o + 0], v0);
        g[o + 1] = cadd(f[o + 1], v1); g[o + 3] = csub(f[o + 1], v1);
    }
    const float S2 = 0.70710678118654752f;
    float2 v0 = g[4];
    float2 v1 = cmul(g[5], make_float2(S2, -d * S2));
    float2 v2 = make_float2(d * g[6].y, -d * g[6].x);
    float2 v3 = cmul(g[7], make_float2(-S2, -d * S2));
    e[0] = cadd(g[0], v0); e[4] = csub(g[0], v0);
    e[1] = cadd(g[1], v1); e[5] = csub(g[1], v1);
    e[2] = cadd(g[2], v2); e[6] = csub(g[2], v2);
    e[3] = cadd(g[3], v3); e[7] = csub(g[3], v3);
}

template<int DIR>
__device__ __forceinline__ void bf8_g(float2 e[8], float r)
{
    const float d = (DIR > 0) ? 1.0f : -1.0f;
    float s1, c1;
    sincospif(r, &s1, &c1);
    float2 t1 = make_float2(c1, -d * s1);
    float2 t2 = cmul(t1, t1);
    float2 t4 = cmul(t2, t2);

    float2 f[8];
    #pragma unroll
    for (int m = 0; m < 4; m++) {
        float2 v = cmul(e[2 * m + 1], t4);
        f[2 * m]     = cadd(e[2 * m], v);
        f[2 * m + 1] = csub(e[2 * m], v);
    }
    float2 wb1 = make_float2(d * t2.y, -d * t2.x);
    float2 g[8];
    #pragma unroll
    for (int hh = 0; hh < 2; hh++) {
        int o = 4 * hh;
        float2 v0 = cmul(f[o + 2], t2);
        float2 v1 = cmul(f[o + 3], wb1);
        g[o + 0] = cadd(f[o + 0], v0); g[o + 2] = csub(f[o + 0], v0);
        g[o + 1] = cadd(f[o + 1], v1); g[o + 3] = csub(f[o + 1], v1);
    }
    const float S2 = 0.70710678118654752f;
    float2 wc1 = make_float2(S2 * (t1.x + d * t1.y), S2 * (t1.y - d * t1.x));
    float2 wc2 = make_float2(d * t1.y, -d * t1.x);
    float2 wc3 = make_float2(S2 * (-t1.x + d * t1.y), S2 * (-t1.y - d * t1.x));
    float2 v0 = cmul(g[4], t1);
    float2 v1 = cmul(g[5], wc1);
    float2 v2 = cmul(g[6], wc2);
    float2 v3 = cmul(g[7], wc3);
    e[0] = cadd(g[0], v0); e[4] = csub(g[0], v0);
    e[1] = cadd(g[1], v1); e[5] = csub(g[1], v1);
    e[2] = cadd(g[2], v2); e[6] = csub(g[2], v2);
    e[3] = cadd(g[3], v3); e[7] = csub(g[3], v3);
}

template<int DIR, bool PRESYNC>
__device__ __forceinline__ void fft_unit(float2* s, float2 e[8], int t, bool active)
{
    if (active) bf8_0<DIR>(e);
    if (PRESYNC) __syncthreads();
    if (active) {
        int b = brev6(t);
        #pragma unroll
        for (int j = 0; j < 8; j++) s[PADI(8 * b + j)] = e[j];
    }
    __syncthreads();
    if (active) {
        int b2 = t >> 3, k = t & 7;
        #pragma unroll
        for (int j = 0; j < 8; j++) e[j] = s[PADI(b2 * 64 + j * 8 + k)];
        bf8_g<DIR>(e, (float)k * (1.0f / 32.0f));
        #pragma unroll
        for (int j = 0; j < 8; j++) s[PADI(b2 * 64 + j * 8 + k)] = e[j];
    }
    __syncthreads();
    if (active) {
        #pragma unroll
        for (int j = 0; j < 8; j++) e[j] = s[PADI(j * 64 + t)];
        bf8_g<DIR>(e, (float)t * (1.0f / 256.0f));
    }
}

// ---------------- pupil sum ----------------
__global__ void __launch_bounds__(256) pupil_part(const float* __restrict__ pupil) {
    int tid = threadIdx.x, b = blockIdx.x;
    int v = 0;
    #pragma unroll 4
    for (int q = 0; q < 4; q++) {
        int i = b * 1024 + q * 256 + tid;
        v += (pupil[i] > 0.5f) ? 1 : 0;
    }
    #pragma unroll
    for (int o = 16; o; o >>= 1) v += __shfl_xor_sync(0xffffffffu, v, o);
    __shared__ int ws[8];
    if ((tid & 31) == 0) ws[tid >> 5] = v;
    __syncthreads();
    if (tid == 0) {
        int s = 0;
        #pragma unroll
        for (int w = 0; w < 8; w++) s += ws[w];
        d_part[b] = s;
    }
}

__global__ void __launch_bounds__(256) pupil_final() {
    int tid = threadIdx.x;
    int v = d_part[tid];
    #pragma unroll
    for (int o = 16; o; o >>= 1) v += __shfl_xor_sync(0xffffffffu, v, o);
    __shared__ int ws[8];
    if ((tid & 31) == 0) ws[tid >> 5] = v;
    __syncthreads();
    if (tid == 0) {
        int s = 0;
        #pragma unroll
        for (int w = 0; w < 8; w++) s += ws[w];
        d_cscale = (float)(1.0 / (68719476736.0 * (double)s));
    }
}

// ---------------- bilinear xy_feat + bf16 hi/lo split ----------------
__global__ void __launch_bounds__(256) xyfeat_kernel(
    const float* __restrict__ grid, const float* __restrict__ lerp,
    const int* __restrict__ x0, const int* __restrict__ y0,
    const int* __restrict__ x1, const int* __restrict__ y1)
{
    int p = blockIdx.x * 256 + threadIdx.x;
    float2 l = ((const float2*)lerp)[p];
    float lx = l.x, ly = l.y;
    int X0 = x0[p], Y0 = y0[p], X1 = x1[p], Y1 = y1[p];
    float w00 = (1.f - lx) * (1.f - ly);
    float w10 = lx * (1.f - ly);
    float w01 = (1.f - lx) * ly;
    float w11 = lx * ly;
    const float4* g00 = (const float4*)(grid + ((size_t)Y0 * WDIM + X0) * 16);
    const float4* g10 = (const float4*)(grid + ((size_t)Y0 * WDIM + X1) * 16);
    const float4* g01 = (const float4*)(grid + ((size_t)Y1 * WDIM + X0) * 16);
    const float4* g11 = (const float4*)(grid + ((size_t)Y1 * WDIM + X1) * 16);
    float f[16];
    #pragma unroll
    for (int q = 0; q < 4; q++) {
        float4 a = g00[q], b = g10[q], c = g01[q], d = g11[q];
        f[q * 4 + 0] = a.x * w00 + b.x * w10 + c.x * w01 + d.x * w11;
        f[q * 4 + 1] = a.y * w00 + b.y * w10 + c.y * w01 + d.y * w11;
        f[q * 4 + 2] = a.z * w00 + b.z * w10 + c.z * w01 + d.z * w11;
        f[q * 4 + 3] = a.w * w00 + b.w * w10 + c.w * w01 + d.w * w11;
    }
    uint hi[8], lo[8];
    #pragma unroll
    for (int t = 0; t < 8; t++) split2(f[2 * t], f[2 * t + 1], hi[t], lo[t]);
    uint* hip = (uint*)d_xyf;
    uint* lop = hip + (size_t)NPIX * 8;
    ((uint4*)(hip + (size_t)p * 8))[0] = make_uint4(hi[0], hi[1], hi[2], hi[3]);
    ((uint4*)(hip + (size_t)p * 8))[1] = make_uint4(hi[4], hi[5], hi[6], hi[7]);
    ((uint4*)(lop + (size_t)p * 8))[0] = make_uint4(lo[0], lo[1], lo[2], lo[3]);
    ((uint4*)(lop + (size_t)p * 8))[1] = make_uint4(lo[4], lo[5], lo[6], lo[7]);
}

// ---------------- tensor-core MLP (bf16 3-term split) ----------------
// Block: 128 threads (4 warps), each warp does 64 pixels (4 m16 tiles), one z.
// Layers 1-2 on tensor cores; layer 3 (32 -> 1) as scalar fp32 dot + shfl
// reduce (each thread already holds 8 cols x 2 rows of the layer-2 output).
__global__ void __launch_bounds__(128) mlp_kernel(
    const float* __restrict__ zarr, const float* __restrict__ zdat,
    const float* __restrict__ w1, const float* __restrict__ b1,
    const float* __restrict__ w2, const float* __restrict__ b2,
    const float* __restrict__ w3, const float* __restrict__ b3)
{
    __shared__ uint2 w1h[4][32], w1l[4][32];     // [n][lane]
    __shared__ uint2 w2h[8][32], w2l[8][32];     // [s*4+n][lane]
    __shared__ float w3s[32];
    __shared__ float b1s[32], b2s[32];
    __shared__ float b3s;

    int tid = threadIdx.x, lane = tid & 31, warp = tid >> 5;
    int gid = lane >> 2, tig = lane & 3;
    int z = blockIdx.y;

    if (warp == 0) {
        float zv = zarr[z];
        float zn = (29.0f * zv) / 30.0f;
        float zfl = floorf(zn);
        int z0 = (int)zfl; z0 = min(max(z0, 0), ZM - 1);
        int z1 = min(z0 + 1, ZM - 1);
        float zl = zn - zfl;

        int ks[4] = { 2 * tig, 2 * tig + 1, 2 * tig + 8, 2 * tig + 9 };
        float zf[4];
        #pragma unroll
        for (int i = 0; i < 4; i++)
            zf[i] = zdat[z0 * 16 + ks[i]] * (1.0f - zl) + zdat[z1 * 16 + ks[i]] * zl;

        #pragma unroll
        for (int n = 0; n < 4; n++) {
            float wv[4];
            #pragma unroll
            for (int i = 0; i < 4; i++) wv[i] = w1[ks[i] * 32 + 8 * n + gid] * zf[i];
            uint h0, l0, h1, l1;
            split2(wv[0], wv[1], h0, l0);
            split2(wv[2], wv[3], h1, l1);
            w1h[n][lane] = make_uint2(h0, h1);
            w1l[n][lane] = make_uint2(l0, l1);
        }
        #pragma unroll
        for (int s = 0; s < 2; s++)
            #pragma unroll
            for (int n = 0; n < 4; n++) {
                float wv[4];
                #pragma unroll
                for (int i = 0; i < 4; i++) wv[i] = w2[(16 * s + ks[i]) * 32 + 8 * n + gid];
                uint h0, l0, h1, l1;
                split2(wv[0], wv[1], h0, l0);
                split2(wv[2], wv[3], h1, l1);
                w2h[s * 4 + n][lane] = make_uint2(h0, h1);
                w2l[s * 4 + n][lane] = make_uint2(l0, l1);
            }
        w3s[lane] = w3[lane];
        b1s[lane] = b1[lane];
        b2s[lane] = b2[lane];
        if (lane == 0) b3s = b3[0];
    }
    __syncthreads();

    const uint* hip = (const uint*)d_xyf;
    const uint* lop = hip + (size_t)NPIX * 8;
    uint pxb = blockIdx.x * 256 + warp * 64;
    float* fout = d_fluo + (size_t)z * NPIX;

    // this thread's 8 layer-3 weights (cols 8n+2tig, 8n+2tig+1)
    float w3r[8];
    #pragma unroll
    for (int n = 0; n < 4; n++) {
        w3r[2 * n]     = w3s[8 * n + 2 * tig];
        w3r[2 * n + 1] = w3s[8 * n + 2 * tig + 1];
    }
    float bias3 = b3s;

    #pragma unroll
    for (int m = 0; m < 4; m++) {
        uint pb = pxb + m * 16;
        uint r0 = (pb + gid) * 8u;
        uint r1 = (pb + gid + 8) * 8u;
        uint Ah[4], Al[4];
        Ah[0] = hip[r0 + tig];     Ah[1] = hip[r1 + tig];
        Ah[2] = hip[r0 + tig + 4]; Ah[3] = hip[r1 + tig + 4];
        Al[0] = lop[r0 + tig];     Al[1] = lop[r1 + tig];
        Al[2] = lop[r0 + tig + 4]; Al[3] = lop[r1 + tig + 4];

        // layer 1: 16 -> 32
        float acc[4][4];
        #pragma unroll
        for (int n = 0; n < 4; n++) {
            float bb0 = b1s[8 * n + 2 * tig], bb1 = b1s[8 * n + 2 * tig + 1];
            acc[n][0] = bb0; acc[n][1] = bb1; acc[n][2] = bb0; acc[n][3] = bb1;
        }
        #pragma unroll
        for (int n = 0; n < 4; n++) {
            uint2 bh = w1h[n][lane], bl = w1l[n][lane];
            mma16816(acc[n], Ah, bh);
            mma16816(acc[n], Ah, bl);
            mma16816(acc[n], Al, bh);
        }

        // relu + split -> layer-2 A frags
        uint A2h[2][4], A2l[2][4];
        #pragma unroll
        for (int s = 0; s < 2; s++) {
            split2(fmaxf(acc[2*s][0], 0.f),   fmaxf(acc[2*s][1], 0.f),   A2h[s][0], A2l[s][0]);
            split2(fmaxf(acc[2*s][2], 0.f),   fmaxf(acc[2*s][3], 0.f),   A2h[s][1], A2l[s][1]);
            split2(fmaxf(acc[2*s+1][0], 0.f), fmaxf(acc[2*s+1][1], 0.f), A2h[s][2], A2l[s][2]);
            split2(fmaxf(acc[2*s+1][2], 0.f), fmaxf(acc[2*s+1][3], 0.f), A2h[s][3], A2l[s][3]);
        }

        // layer 2: 32 -> 32
        float acc2[4][4];
        #pragma unroll
        for (int n = 0; n < 4; n++) {
            float bb0 = b2s[8 * n + 2 * tig], bb1 = b2s[8 * n + 2 * tig + 1];
            acc2[n][0] = bb0; acc2[n][1] = bb1; acc2[n][2] = bb0; acc2[n][3] = bb1;
        }
        #pragma unroll
        for (int n = 0; n < 4; n++)
            #pragma unroll
            for (int s = 0; s < 2; s++) {
                uint2 bh = w2h[s * 4 + n][lane], bl = w2l[s * 4 + n][lane];
                mma16816(acc2[n], A2h[s], bh);
                mma16816(acc2[n], A2h[s], bl);
                mma16816(acc2[n], A2l[s], bh);
            }

        // layer 3: 32 -> 1 in fp32 scalar (relu fused into the dot product)
        float p0 = 0.0f, p1 = 0.0f;
        #pragma unroll
        for (int n = 0; n < 4; n++) {
            p0 = fmaf(fmaxf(acc2[n][0], 0.f), w3r[2 * n],     p0);
            p0 = fmaf(fmaxf(acc2[n][1], 0.f), w3r[2 * n + 1], p0);
            p1 = fmaf(fmaxf(acc2[n][2], 0.f), w3r[2 * n],     p1);
            p1 = fmaf(fmaxf(acc2[n][3], 0.f), w3r[2 * n + 1], p1);
        }
        p0 += __shfl_xor_sync(0xffffffffu, p0, 1);
        p0 += __shfl_xor_sync(0xffffffffu, p0, 2);
        p1 += __shfl_xor_sync(0xffffffffu, p1, 1);
        p1 += __shfl_xor_sync(0xffffffffu, p1, 2);

        if (tig == 0) {
            fout[pb + gid]     = p0 + bias3;
            fout[pb + gid + 8] = p1 + bias3;
        }
    }
}

// ---------------- radix-8 row pass: 256 threads, 4 rows per block ----------------
template<int DIR, int MODE>
__global__ void __launch_bounds__(256) fft_row4(
    const float* __restrict__ rin, const float* __restrict__ aberr,
    float2* __restrict__ cout)
{
    __shared__ float2 sm[4][CSTRIDE];
    int tid = threadIdx.x;
    int u = tid >> 6, t = tid & 63;
    int r = blockIdx.x * 4 + u;
    int zp = blockIdx.y;
    size_t rb = (size_t)zp * NPIX + (size_t)r * WDIM;

    float2 e[8];
    if (MODE == 0) {
        #pragma unroll
        for (int j = 0; j < 8; j++) {
            int n = t + 64 * j;
            float p = rin[(size_t)r * WDIM + n];
            float ab = aberr[rb + n];
            float sn, cs; __sincosf(ab, &sn, &cs);
            e[brev3(j)] = make_float2(p * cs, p * sn);
        }
    } else {
        size_t b0 = (size_t)(2 * zp) * NPIX + (size_t)r * WDIM;
        size_t b1 = b0 + NPIX;
        #pragma unroll
        for (int j = 0; j < 8; j++) {
            int n = t + 64 * j;
            e[brev3(j)] = make_float2(rin[b0 + n], rin[b1 + n]);
        }
    }

    fft_unit<DIR, false>(&sm[u][0], e, t, true);

    #pragma unroll
    for (int j = 0; j < 8; j++) cout[rb + j * 64 + t] = e[j];
}

// ---------------- fused colQ pass ----------------
__global__ void __launch_bounds__(256) colq_kernel(
    const float2* __restrict__ in, float2* __restrict__ outp)
{
    __shared__ float2 sm[4 * CSTRIDE];
    int tid = threadIdx.x;
    int u = tid >> 6, t = tid & 63;
    int zp = blockIdx.y;
    int col0 = blockIdx.x * 2;

    #pragma unroll
    for (int q = 0; q < 8; q++) {
        int idx = tid + q * 256;
        int c = idx & 1, pl = (idx >> 1) & 1, i = idx >> 2;
        sm[(pl * 2 + c) * CSTRIDE + PADI(i)] =
            in[(size_t)(2 * zp + pl) * NPIX + (size_t)i * WDIM + col0 + c];
    }
    __syncthreads();

    float2* s = sm + u * CSTRIDE;
    float2 e[8];
    #pragma unroll
    for (int j = 0; j < 8; j++) e[brev3(j)] = s[PADI(t + 64 * j)];
    fft_unit<-1, true>(s, e, t, true);
    #pragma unroll
    for (int j = 0; j < 8; j++) s[PADI(j * 64 + t)] = e[j];
    __syncthreads();

    bool act = (u < 2);
    if (act) {
        float2* s0 = sm + u * CSTRIDE;
        float2* s1 = sm + (2 + u) * CSTRIDE;
        #pragma unroll
        for (int j = 0; j < 8; j++) {
            int n = t + 64 * j;
            float2 a0 = s0[PADI(n)];
            float2 a1 = s1[PADI(n)];
            e[brev3(j)] = make_float2(a0.x * a0.x + a0.y * a0.y,
                                      a1.x * a1.x + a1.y * a1.y);
        }
    }
    fft_unit<+1, true>(s, e, t, act);
    if (act) {
        #pragma unroll
        for (int j = 0; j < 8; j++) s[PADI(j * 64 + t)] = e[j];
    }
    __syncthreads();

    #pragma unroll
    for (int q = 0; q < 4; q++) {
        int idx = tid + q * 256;
        int c = idx & 1, i = idx >> 1;
        outp[(size_t)zp * NPIX + (size_t)i * WDIM + col0 + c] =
            sm[c * CSTRIDE + PADI(i)];
    }
}

// ---------------- fused crossQ pass ----------------
__global__ void __launch_bounds__(128) crossq_kernel(
    const float2* __restrict__ qcol, const float2* __restrict__ cSo,
    float2* __restrict__ cout)
{
    __shared__ float2 sm[2 * CSTRIDE];
    int tid = threadIdx.x;
    int u = tid >> 6, t = tid & 63;
    int b = blockIdx.x;
    int zp = blockIdx.y;
    size_t zb = (size_t)zp * NPIX;

    int ru = (b == 0) ? (u == 0 ? 0 : 256) : (u == 0 ? b : WDIM - b);
    int pu = (b == 0) ? u : 1 - u;
    int rn = (WDIM - ru) & (WDIM - 1);
    size_t rb  = zb + (size_t)ru * WDIM;
    size_t rbm = zb + (size_t)rn * WDIM;

    float2* s = sm + u * CSTRIDE;
    float2* sp = sm + pu * CSTRIDE;

    float2 e[8];
    #pragma unroll
    for (int j = 0; j < 8; j++) e[brev3(j)] = qcol[rb + t + 64 * j];
    fft_unit<+1, false>(s, e, t, true);
    #pragma unroll
    for (int j = 0; j < 8; j++) s[PADI(j * 64 + t)] = e[j];
    __syncthreads();

    float sc = 0.25f * d_cscale;
    #pragma unroll
    for (int j = 0; j < 8; j++) {
        int n = t + 64 * j;
        int nn = (WDIM - n) & (WDIM - 1);
        float2 Sq  = s[PADI(n)];
        float2 Sqm = sp[PADI(nn)];
        float2 So  = cSo[rb + n];
        float2 Som = cSo[rbm + nn];
        float2 Po = make_float2(So.x + Som.x, So.y - Som.y);
        float2 Mo = make_float2(So.x - Som.x, So.y + Som.y);
        float2 Pq = make_float2(Sq.x + Sqm.x, Sq.y - Sqm.y);
        float2 Mq = make_float2(Sq.x - Sqm.x, Sq.y + Sqm.y);
        float2 PP = cmul(Po, Pq);
        float2 MM = cmul(Mo, Mq);
        e[brev3(j)] = make_float2(sc * (PP.x + MM.y), sc * (PP.y - MM.x));
    }
    fft_unit<-1, true>(s, e, t, true);

    #pragma unroll
    for (int j = 0; j < 8; j++) cout[rb + j * 64 + t] = e[j];
}

// ---------------- radix-8 column pass: 256 threads, 4 cols per block ----------------
template<int DIR, int MODE>
__global__ void __launch_bounds__(256) fft_col4(
    const float2* __restrict__ in, float2* __restrict__ cout, float* __restrict__ rout)
{
    __shared__ float2 sm[4 * CSTRIDE];
    int tid = threadIdx.x;
    int zp = blockIdx.y;
    int col0 = blockIdx.x * 4;
    size_t zb = (size_t)zp * NPIX;

    #pragma unroll
    for (int q = 0; q < 8; q++) {
        int l = tid + q * 256;
        int c = l & 3, i = l >> 2;
        sm[c * CSTRIDE + PADI(i)] = in[zb + (size_t)i * WDIM + col0 + c];
    }
    __syncthreads();

    int u = tid >> 6, t = tid & 63;
    float2* s = sm + u * CSTRIDE;
    float2 e[8];
    #pragma unroll
    for (int j = 0; j < 8; j++) e[brev3(j)] = s[PADI(t + 64 * j)];
    fft_unit<DIR, true>(s, e, t, true);
    #pragma unroll
    for (int j = 0; j < 8; j++) s[PADI(j * 64 + t)] = e[j];
    __syncthreads();

    #pragma unroll
    for (int q = 0; q < 8; q++) {
        int l = tid + q * 256;
        int c = l & 3, i = l >> 2;
        float2 v = sm[c * CSTRIDE + PADI(i)];
        size_t sp = (size_t)i * WDIM + col0 + c;
        if (MODE == 1) {
            cout[zb + sp] = v;
        } else {
            rout[(size_t)(2 * zp) * NPIX + sp]     = v.x;
            rout[(size_t)(2 * zp + 1) * NPIX + sp] = v.y;
        }
    }
}

// ---------------- launcher ----------------
extern "C" void kernel_launch(void* const* d_in, const int* in_sizes, int n_in,
                              void* d_out, int out_size)
{
    const float* z     = (const float*)d_in[0];
    const float* grid  = (const float*)d_in[1];
    const float* zdat  = (const float*)d_in[2];
    const float* w1    = (const float*)d_in[3];
    const float* b1    = (const float*)d_in[4];
    const float* w2    = (const float*)d_in[5];
    const float* b2    = (const float*)d_in[6];
    const float* w3    = (const float*)d_in[7];
    const float* b3    = (const float*)d_in[8];
    const float* pupil = (const float*)d_in[9];
    const float* aberr = (const float*)d_in[10];
    const float* lerp  = (const float*)d_in[11];
    const int*   x0    = (const int*)d_in[12];
    const int*   y0    = (const int*)d_in[13];
    const int*   x1    = (const int*)d_in[14];
    const int*   y1    = (const int*)d_in[15];
    float* out = (float*)d_out;

    float2* tmpA; float2* tmpB; float* qbuf; float* fluo;
    cudaGetSymbolAddress((void**)&tmpA, d_tmpA);
    cudaGetSymbolAddress((void**)&tmpB, d_tmpB);
    cudaGetSymbolAddress((void**)&qbuf, d_q);
    cudaGetSymbolAddress((void**)&fluo, d_fluo);
    float2* qcol = (float2*)qbuf;
    float2* Cbuf = (float2*)fluo;

    // scalar normalizer 1/(N^4 * sum(pupil))
    pupil_part<<<256, 256>>>(pupil);
    pupil_final<<<1, 256>>>();

    // render path
    xyfeat_kernel<<<NPIX / 256, 256>>>(grid, lerp, x0, y0, x1, y1);
    mlp_kernel<<<dim3(NPIX / 256, ZM), 128>>>(z, zdat, w1, b1, w2, b2, w3, b3);

    // pupil path: rowIFFT(P) -> tmpA (30 planes)
    fft_row4<-1, 0><<<dim3(WDIM / 4, ZM), 256>>>(pupil, aberr, tmpA);
    // fused: col IFFT x2, |.|^2, packed forward col FFT -> qcol (15 planes)
    colq_kernel<<<dim3(WDIM / 2, NZP), 256>>>(tmpA, qcol);

    // So = F2(fluo) packed -> tmpB (col pass in-place)
    fft_row4<+1, 1><<<dim3(WDIM / 4, NZP), 256>>>(fluo, nullptr, tmpB);
    fft_col4<+1, 1><<<dim3(WDIM / 4, NZP), 256>>>(tmpB, tmpB, nullptr);

    // fused: Sq rows + Hermitian cross spectrum + row IFFT -> Cbuf
    crossq_kernel<<<dim3(WDIM / 2, NZP), 128>>>(qcol, tmpB, Cbuf);
    // inverse col pass, split packed planes into the 30 real output planes
    fft_col4<-1, 2><<<dim3(WDIM / 4, NZP), 256>>>(Cbuf, nullptr, out);
}

// round 11
// speedup vs baseline: 4.6058x; 1.0113x over previous
#include <cuda_runtime.h>
#include <cstdint>

#define WDIM 512
#define NPIX (512*512)
#define ZM 30
#define NZP (ZM/2)

typedef unsigned long long ull;
typedef unsigned int uint;

// ---------------- device scratch ----------------
__device__ __align__(16) float2 d_tmpA[(size_t)ZM * NPIX];   // 63 MB
__device__ __align__(16) float2 d_tmpB[(size_t)ZM * NPIX];   // 63 MB
__device__ __align__(16) float  d_q   [(size_t)ZM * NPIX];   // packed colFFT(q), 15 cpx planes
__device__ __align__(16) float  d_fluo[(size_t)ZM * NPIX];   // fluo, reused as Cbuf
__device__ __align__(16) float  d_xyf [(size_t)NPIX * 16];   // 16 MB: [0,8MB)=hi b32 pairs, [8,16MB)=lo
__device__ int   d_part[256];
__device__ float d_cscale;

// ---------------- bf16 split helpers ----------------
// pack (x0 -> low bf16, x1 -> high bf16); lo = residual pair
__device__ __forceinline__ void split2(float x0, float x1, uint& h, uint& l) {
    uint hp;
    asm("cvt.rn.bf16x2.f32 %0, %1, %2;" : "=r"(hp) : "f"(x1), "f"(x0));
    float h0 = __uint_as_float(hp << 16);
    float h1 = __uint_as_float(hp & 0xffff0000u);
    float l0 = x0 - h0, l1 = x1 - h1;
    asm("cvt.rn.bf16x2.f32 %0, %1, %2;" : "=r"(l) : "f"(l1), "f"(l0));
    h = hp;
}

__device__ __forceinline__ void mma16816(float c[4], const uint a[4], uint2 b) {
    asm("mma.sync.aligned.m16n8k16.row.col.f32.bf16.bf16.f32 "
        "{%0,%1,%2,%3}, {%4,%5,%6,%7}, {%8,%9}, {%0,%1,%2,%3};"
        : "+f"(c[0]), "+f"(c[1]), "+f"(c[2]), "+f"(c[3])
        : "r"(a[0]), "r"(a[1]), "r"(a[2]), "r"(a[3]), "r"(b.x), "r"(b.y));
}

// ---------------- complex helpers ----------------
__device__ __forceinline__ float2 cmul(float2 a, float2 b) {
    return make_float2(fmaf(a.x, b.x, -a.y * b.y), fmaf(a.x, b.y, a.y * b.x));
}
__device__ __forceinline__ float2 cadd(float2 a, float2 b) { return make_float2(a.x + b.x, a.y + b.y); }
__device__ __forceinline__ float2 csub(float2 a, float2 b) { return make_float2(a.x - b.x, a.y - b.y); }

__device__ __forceinline__ int brev3(int j) { return ((j & 1) << 2) | (j & 2) | ((j >> 2) & 1); }
__device__ __forceinline__ int brev6(int t) { return (int)(__brev((unsigned)t) >> 26); }

#define PADI(p) ((p) + ((p) >> 5))
#define CSTRIDE 532

// ---------------- radix-8 butterflies ----------------
template<int DIR>
__device__ __forceinline__ void bf8_0(float2 e[8])
{
    const float d = (DIR > 0) ? 1.0f : -1.0f;
    float2 f[8];
    #pragma unroll
    for (int m = 0; m < 4; m++) {
        float2 u = e[2 * m], v = e[2 * m + 1];
        f[2 * m]     = cadd(u, v);
        f[2 * m + 1] = csub(u, v);
    }
    float2 g[8];
    #pragma unroll
    for (int hh = 0; hh < 2; hh++) {
        int o = 4 * hh;
        float2 v0 = f[o + 2];
        float2 v1 = make_float2(d * f[o + 3].y, -d * f[o + 3].x);
        g[o + 0] = cadd(f[o + 0], v0); g[o + 2] = csub(f[o + 0], v0);
        g[o + 1] = cadd(f[o + 1], v1); g[o + 3] = csub(f[o + 1], v1);
    }
    const float S2 = 0.70710678118654752f;
    float2 v0 = g[4];
    float2 v1 = cmul(g[5], make_float2(S2, -d * S2));
    float2 v2 = make_float2(d * g[6].y, -d * g[6].x);
    float2 v3 = cmul(g[7], make_float2(-S2, -d * S2));
    e[0] = cadd(g[0], v0); e[4] = csub(g[0], v0);
    e[1] = cadd(g[1], v1); e[5] = csub(g[1], v1);
    e[2] = cadd(g[2], v2); e[6] = csub(g[2], v2);
    e[3] = cadd(g[3], v3); e[7] = csub(g[3], v3);
}

template<int DIR>
__device__ __forceinline__ void bf8_g(float2 e[8], float r)
{
    const float d = (DIR > 0) ? 1.0f : -1.0f;
    float s1, c1;
    sincospif(r, &s1, &c1);
    float2 t1 = make_float2(c1, -d * s1);
    float2 t2 = cmul(t1, t1);
    float2 t4 = cmul(t2, t2);

    float2 f[8];
    #pragma unroll
    for (int m = 0; m < 4; m++) {
        float2 v = cmul(e[2 * m + 1], t4);
        f[2 * m]     = cadd(e[2 * m], v);
        f[2 * m + 1] = csub(e[2 * m], v);
    }
    float2 wb1 = make_float2(d * t2.y, -d * t2.x);
    float2 g[8];
    #pragma unroll
    for (int hh = 0; hh < 2; hh++) {
        int o = 4 * hh;
        float2 v0 = cmul(f[o + 2], t2);
        float2 v1 = cmul(f[o + 3], wb1);
        g[o + 0] = cadd(f[o + 0], v0); g[o + 2] = csub(f[o + 0], v0);
        g[o + 1] = cadd(f[o + 1], v1); g[o + 3] = csub(f[o + 1], v1);
    }
    const float S2 = 0.70710678118654752f;
    float2 wc1 = make_float2(S2 * (t1.x + d * t1.y), S2 * (t1.y - d * t1.x));
    float2 wc2 = make_float2(d * t1.y, -d * t1.x);
    float2 wc3 = make_float2(S2 * (-t1.x + d * t1.y), S2 * (-t1.y - d * t1.x));
    float2 v0 = cmul(g[4], t1);
    float2 v1 = cmul(g[5], wc1);
    float2 v2 = cmul(g[6], wc2);
    float2 v3 = cmul(g[7], wc3);
    e[0] = cadd(g[0], v0); e[4] = csub(g[0], v0);
    e[1] = cadd(g[1], v1); e[5] = csub(g[1], v1);
    e[2] = cadd(g[2], v2); e[6] = csub(g[2], v2);
    e[3] = cadd(g[3], v3); e[7] = csub(g[3], v3);
}

template<int DIR, bool PRESYNC>
__device__ __forceinline__ void fft_unit(float2* s, float2 e[8], int t, bool active)
{
    if (active) bf8_0<DIR>(e);
    if (PRESYNC) __syncthreads();
    if (active) {
        int b = brev6(t);
        #pragma unroll
        for (int j = 0; j < 8; j++) s[PADI(8 * b + j)] = e[j];
    }
    __syncthreads();
    if (active) {
        int b2 = t >> 3, k = t & 7;
        #pragma unroll
        for (int j = 0; j < 8; j++) e[j] = s[PADI(b2 * 64 + j * 8 + k)];
        bf8_g<DIR>(e, (float)k * (1.0f / 32.0f));
        #pragma unroll
        for (int j = 0; j < 8; j++) s[PADI(b2 * 64 + j * 8 + k)] = e[j];
    }
    __syncthreads();
    if (active) {
        #pragma unroll
        for (int j = 0; j < 8; j++) e[j] = s[PADI(j * 64 + t)];
        bf8_g<DIR>(e, (float)t * (1.0f / 256.0f));
    }
}

// ---------------- pupil sum ----------------
__global__ void __launch_bounds__(256) pupil_part(const float* __restrict__ pupil) {
    int tid = threadIdx.x, b = blockIdx.x;
    int v = 0;
    #pragma unroll 4
    for (int q = 0; q < 4; q++) {
        int i = b * 1024 + q * 256 + tid;
        v += (pupil[i] > 0.5f) ? 1 : 0;
    }
    #pragma unroll
    for (int o = 16; o; o >>= 1) v += __shfl_xor_sync(0xffffffffu, v, o);
    __shared__ int ws[8];
    if ((tid & 31) == 0) ws[tid >> 5] = v;
    __syncthreads();
    if (tid == 0) {
        int s = 0;
        #pragma unroll
        for (int w = 0; w < 8; w++) s += ws[w];
        d_part[b] = s;
    }
}

__global__ void __launch_bounds__(256) pupil_final() {
    int tid = threadIdx.x;
    int v = d_part[tid];
    #pragma unroll
    for (int o = 16; o; o >>= 1) v += __shfl_xor_sync(0xffffffffu, v, o);
    __shared__ int ws[8];
    if ((tid & 31) == 0) ws[tid >> 5] = v;
    __syncthreads();
    if (tid == 0) {
        int s = 0;
        #pragma unroll
        for (int w = 0; w < 8; w++) s += ws[w];
        d_cscale = (float)(1.0 / (68719476736.0 * (double)s));
    }
}

// ---------------- bilinear xy_feat + bf16 hi/lo split ----------------
__global__ void __launch_bounds__(256) xyfeat_kernel(
    const float* __restrict__ grid, const float* __restrict__ lerp,
    const int* __restrict__ x0, const int* __restrict__ y0,
    const int* __restrict__ x1, const int* __restrict__ y1)
{
    int p = blockIdx.x * 256 + threadIdx.x;
    float2 l = ((const float2*)lerp)[p];
    float lx = l.x, ly = l.y;
    int X0 = x0[p], Y0 = y0[p], X1 = x1[p], Y1 = y1[p];
    float w00 = (1.f - lx) * (1.f - ly);
    float w10 = lx * (1.f - ly);
    float w01 = (1.f - lx) * ly;
    float w11 = lx * ly;
    const float4* g00 = (const float4*)(grid + ((size_t)Y0 * WDIM + X0) * 16);
    const float4* g10 = (const float4*)(grid + ((size_t)Y0 * WDIM + X1) * 16);
    const float4* g01 = (const float4*)(grid + ((size_t)Y1 * WDIM + X0) * 16);
    const float4* g11 = (const float4*)(grid + ((size_t)Y1 * WDIM + X1) * 16);
    float f[16];
    #pragma unroll
    for (int q = 0; q < 4; q++) {
        float4 a = g00[q], b = g10[q], c = g01[q], d = g11[q];
        f[q * 4 + 0] = a.x * w00 + b.x * w10 + c.x * w01 + d.x * w11;
        f[q * 4 + 1] = a.y * w00 + b.y * w10 + c.y * w01 + d.y * w11;
        f[q * 4 + 2] = a.z * w00 + b.z * w10 + c.z * w01 + d.z * w11;
        f[q * 4 + 3] = a.w * w00 + b.w * w10 + c.w * w01 + d.w * w11;
    }
    uint hi[8], lo[8];
    #pragma unroll
    for (int t = 0; t < 8; t++) split2(f[2 * t], f[2 * t + 1], hi[t], lo[t]);
    uint* hip = (uint*)d_xyf;
    uint* lop = hip + (size_t)NPIX * 8;
    ((uint4*)(hip + (size_t)p * 8))[0] = make_uint4(hi[0], hi[1], hi[2], hi[3]);
    ((uint4*)(hip + (size_t)p * 8))[1] = make_uint4(hi[4], hi[5], hi[6], hi[7]);
    ((uint4*)(lop + (size_t)p * 8))[0] = make_uint4(lo[0], lo[1], lo[2], lo[3]);
    ((uint4*)(lop + (size_t)p * 8))[1] = make_uint4(lo[4], lo[5], lo[6], lo[7]);
}

// ---------------- tensor-core MLP (bf16 3-term split) ----------------
// Block: 128 threads (4 warps), each warp does 64 pixels (4 m16 tiles), one z.
// Layers 1-2 on tensor cores; layer 3 (32 -> 1) as scalar fp32 dot + shfl
// reduce (each thread already holds 8 cols x 2 rows of the layer-2 output).
__global__ void __launch_bounds__(128) mlp_kernel(
    const float* __restrict__ zarr, const float* __restrict__ zdat,
    const float* __restrict__ w1, const float* __restrict__ b1,
    const float* __restrict__ w2, const float* __restrict__ b2,
    const float* __restrict__ w3, const float* __restrict__ b3)
{
    __shared__ uint2 w1h[4][32], w1l[4][32];     // [n][lane]
    __shared__ uint2 w2h[8][32], w2l[8][32];     // [s*4+n][lane]
    __shared__ float w3s[32];
    __shared__ float b1s[32], b2s[32];
    __shared__ float b3s;

    int tid = threadIdx.x, lane = tid & 31, warp = tid >> 5;
    int gid = lane >> 2, tig = lane & 3;
    int z = blockIdx.y;

    if (warp == 0) {
        float zv = zarr[z];
        float zn = (29.0f * zv) / 30.0f;
        float zfl = floorf(zn);
        int z0 = (int)zfl; z0 = min(max(z0, 0), ZM - 1);
        int z1 = min(z0 + 1, ZM - 1);
        float zl = zn - zfl;

        int ks[4] = { 2 * tig, 2 * tig + 1, 2 * tig + 8, 2 * tig + 9 };
        float zf[4];
        #pragma unroll
        for (int i = 0; i < 4; i++)
            zf[i] = zdat[z0 * 16 + ks[i]] * (1.0f - zl) + zdat[z1 * 16 + ks[i]] * zl;

        #pragma unroll
        for (int n = 0; n < 4; n++) {
            float wv[4];
            #pragma unroll
            for (int i = 0; i < 4; i++) wv[i] = w1[ks[i] * 32 + 8 * n + gid] * zf[i];
            uint h0, l0, h1, l1;
            split2(wv[0], wv[1], h0, l0);
            split2(wv[2], wv[3], h1, l1);
            w1h[n][lane] = make_uint2(h0, h1);
            w1l[n][lane] = make_uint2(l0, l1);
        }
        #pragma unroll
        for (int s = 0; s < 2; s++)
            #pragma unroll
            for (int n = 0; n < 4; n++) {
                float wv[4];
                #pragma unroll
                for (int i = 0; i < 4; i++) wv[i] = w2[(16 * s + ks[i]) * 32 + 8 * n + gid];
                uint h0, l0, h1, l1;
                split2(wv[0], wv[1], h0, l0);
                split2(wv[2], wv[3], h1, l1);
                w2h[s * 4 + n][lane] = make_uint2(h0, h1);
                w2l[s * 4 + n][lane] = make_uint2(l0, l1);
            }
        w3s[lane] = w3[lane];
        b1s[lane] = b1[lane];
        b2s[lane] = b2[lane];
        if (lane == 0) b3s = b3[0];
    }
    __syncthreads();

    const uint* hip = (const uint*)d_xyf;
    const uint* lop = hip + (size_t)NPIX * 8;
    uint pxb = blockIdx.x * 256 + warp * 64;
    float* fout = d_fluo + (size_t)z * NPIX;

    // this thread's 8 layer-3 weights (cols 8n+2tig, 8n+2tig+1)
    float w3r[8];
    #pragma unroll
    for (int n = 0; n < 4; n++) {
        w3r[2 * n]     = w3s[8 * n + 2 * tig];
        w3r[2 * n + 1] = w3s[8 * n + 2 * tig + 1];
    }
    float bias3 = b3s;

    #pragma unroll
    for (int m = 0; m < 4; m++) {
        uint pb = pxb + m * 16;
        uint r0 = (pb + gid) * 8u;
        uint r1 = (pb + gid + 8) * 8u;
        uint Ah[4], Al[4];
        Ah[0] = hip[r0 + tig];     Ah[1] = hip[r1 + tig];
        Ah[2] = hip[r0 + tig + 4]; Ah[3] = hip[r1 + tig + 4];
        Al[0] = lop[r0 + tig];     Al[1] = lop[r1 + tig];
        Al[2] = lop[r0 + tig + 4]; Al[3] = lop[r1 + tig + 4];

        // layer 1: 16 -> 32
        float acc[4][4];
        #pragma unroll
        for (int n = 0; n < 4; n++) {
            float bb0 = b1s[8 * n + 2 * tig], bb1 = b1s[8 * n + 2 * tig + 1];
            acc[n][0] = bb0; acc[n][1] = bb1; acc[n][2] = bb0; acc[n][3] = bb1;
        }
        #pragma unroll
        for (int n = 0; n < 4; n++) {
            uint2 bh = w1h[n][lane], bl = w1l[n][lane];
            mma16816(acc[n], Ah, bh);
            mma16816(acc[n], Ah, bl);
            mma16816(acc[n], Al, bh);
        }

        // relu + split -> layer-2 A frags
        uint A2h[2][4], A2l[2][4];
        #pragma unroll
        for (int s = 0; s < 2; s++) {
            split2(fmaxf(acc[2*s][0], 0.f),   fmaxf(acc[2*s][1], 0.f),   A2h[s][0], A2l[s][0]);
            split2(fmaxf(acc[2*s][2], 0.f),   fmaxf(acc[2*s][3], 0.f),   A2h[s][1], A2l[s][1]);
            split2(fmaxf(acc[2*s+1][0], 0.f), fmaxf(acc[2*s+1][1], 0.f), A2h[s][2], A2l[s][2]);
            split2(fmaxf(acc[2*s+1][2], 0.f), fmaxf(acc[2*s+1][3], 0.f), A2h[s][3], A2l[s][3]);
        }

        // layer 2: 32 -> 32
        float acc2[4][4];
        #pragma unroll
        for (int n = 0; n < 4; n++) {
            float bb0 = b2s[8 * n + 2 * tig], bb1 = b2s[8 * n + 2 * tig + 1];
            acc2[n][0] = bb0; acc2[n][1] = bb1; acc2[n][2] = bb0; acc2[n][3] = bb1;
        }
        #pragma unroll
        for (int n = 0; n < 4; n++)
            #pragma unroll
            for (int s = 0; s < 2; s++) {
                uint2 bh = w2h[s * 4 + n][lane], bl = w2l[s * 4 + n][lane];
                mma16816(acc2[n], A2h[s], bh);
                mma16816(acc2[n], A2h[s], bl);
                mma16816(acc2[n], A2l[s], bh);
            }

        // layer 3: 32 -> 1 in fp32 scalar (relu fused into the dot product)
        float p0 = 0.0f, p1 = 0.0f;
        #pragma unroll
        for (int n = 0; n < 4; n++) {
            p0 = fmaf(fmaxf(acc2[n][0], 0.f), w3r[2 * n],     p0);
            p0 = fmaf(fmaxf(acc2[n][1], 0.f), w3r[2 * n + 1], p0);
            p1 = fmaf(fmaxf(acc2[n][2], 0.f), w3r[2 * n],     p1);
            p1 = fmaf(fmaxf(acc2[n][3], 0.f), w3r[2 * n + 1], p1);
        }
        p0 += __shfl_xor_sync(0xffffffffu, p0, 1);
        p0 += __shfl_xor_sync(0xffffffffu, p0, 2);
        p1 += __shfl_xor_sync(0xffffffffu, p1, 1);
        p1 += __shfl_xor_sync(0xffffffffu, p1, 2);

        if (tig == 0) {
            fout[pb + gid]     = p0 + bias3;
            fout[pb + gid + 8] = p1 + bias3;
        }
    }
}

// ---------------- radix-8 row pass: 256 threads, 4 rows per block ----------------
template<int DIR, int MODE>
__global__ void __launch_bounds__(256) fft_row4(
    const float* __restrict__ rin, const float* __restrict__ aberr,
    float2* __restrict__ cout)
{
    __shared__ float2 sm[4][CSTRIDE];
    int tid = threadIdx.x;
    int u = tid >> 6, t = tid & 63;
    int r = blockIdx.x * 4 + u;
    int zp = blockIdx.y;
    size_t rb = (size_t)zp * NPIX + (size_t)r * WDIM;

    float2 e[8];
    if (MODE == 0) {
        #pragma unroll
        for (int j = 0; j < 8; j++) {
            int n = t + 64 * j;
            float p = rin[(size_t)r * WDIM + n];
            float ab = aberr[rb + n];
            float sn, cs; __sincosf(ab, &sn, &cs);
            e[brev3(j)] = make_float2(p * cs, p * sn);
        }
    } else {
        size_t b0 = (size_t)(2 * zp) * NPIX + (size_t)r * WDIM;
        size_t b1 = b0 + NPIX;
        #pragma unroll
        for (int j = 0; j < 8; j++) {
            int n = t + 64 * j;
            e[brev3(j)] = make_float2(rin[b0 + n], rin[b1 + n]);
        }
    }

    fft_unit<DIR, false>(&sm[u][0], e, t, true);

    #pragma unroll
    for (int j = 0; j < 8; j++) cout[rb + j * 64 + t] = e[j];
}

// ---------------- fused colQ pass ----------------
__global__ void __launch_bounds__(256) colq_kernel(
    const float2* __restrict__ in, float2* __restrict__ outp)
{
    __shared__ float2 sm[4 * CSTRIDE];
    int tid = threadIdx.x;
    int u = tid >> 6, t = tid & 63;
    int zp = blockIdx.y;
    int col0 = blockIdx.x * 2;

    #pragma unroll
    for (int q = 0; q < 8; q++) {
        int idx = tid + q * 256;
        int c = idx & 1, pl = (idx >> 1) & 1, i = idx >> 2;
        sm[(pl * 2 + c) * CSTRIDE + PADI(i)] =
            in[(size_t)(2 * zp + pl) * NPIX + (size_t)i * WDIM + col0 + c];
    }
    __syncthreads();

    float2* s = sm + u * CSTRIDE;
    float2 e[8];
    #pragma unroll
    for (int j = 0; j < 8; j++) e[brev3(j)] = s[PADI(t + 64 * j)];
    fft_unit<-1, true>(s, e, t, true);
    #pragma unroll
    for (int j = 0; j < 8; j++) s[PADI(j * 64 + t)] = e[j];
    __syncthreads();

    bool act = (u < 2);
    if (act) {
        float2* s0 = sm + u * CSTRIDE;
        float2* s1 = sm + (2 + u) * CSTRIDE;
        #pragma unroll
        for (int j = 0; j < 8; j++) {
            int n = t + 64 * j;
            float2 a0 = s0[PADI(n)];
            float2 a1 = s1[PADI(n)];
            e[brev3(j)] = make_float2(a0.x * a0.x + a0.y * a0.y,
                                      a1.x * a1.x + a1.y * a1.y);
        }
    }
    fft_unit<+1, true>(s, e, t, act);
    if (act) {
        #pragma unroll
        for (int j = 0; j < 8; j++) s[PADI(j * 64 + t)] = e[j];
    }
    __syncthreads();

    #pragma unroll
    for (int q = 0; q < 4; q++) {
        int idx = tid + q * 256;
        int c = idx & 1, i = idx >> 1;
        outp[(size_t)zp * NPIX + (size_t)i * WDIM + col0 + c] =
            sm[c * CSTRIDE + PADI(i)];
    }
}

// ---------------- fused crossQ pass ----------------
__global__ void __launch_bounds__(128) crossq_kernel(
    const float2* __restrict__ qcol, const float2* __restrict__ cSo,
    float2* __restrict__ cout)
{
    __shared__ float2 sm[2 * CSTRIDE];
    int tid = threadIdx.x;
    int u = tid >> 6, t = tid & 63;
    int b = blockIdx.x;
    int zp = blockIdx.y;
    size_t zb = (size_t)zp * NPIX;

    int ru = (b == 0) ? (u == 0 ? 0 : 256) : (u == 0 ? b : WDIM - b);
    int pu = (b == 0) ? u : 1 - u;
    int rn = (WDIM - ru) & (WDIM - 1);
    size_t rb  = zb + (size_t)ru * WDIM;
    size_t rbm = zb + (size_t)rn * WDIM;

    float2* s = sm + u * CSTRIDE;
    float2* sp = sm + pu * CSTRIDE;

    float2 e[8];
    #pragma unroll
    for (int j = 0; j < 8; j++) e[brev3(j)] = qcol[rb + t + 64 * j];
    fft_unit<+1, false>(s, e, t, true);
    #pragma unroll
    for (int j = 0; j < 8; j++) s[PADI(j * 64 + t)] = e[j];
    __syncthreads();

    float sc = 0.25f * d_cscale;
    #pragma unroll
    for (int j = 0; j < 8; j++) {
        int n = t + 64 * j;
        int nn = (WDIM - n) & (WDIM - 1);
        float2 Sq  = s[PADI(n)];
        float2 Sqm = sp[PADI(nn)];
        float2 So  = cSo[rb + n];
        float2 Som = cSo[rbm + nn];
        float2 Po = make_float2(So.x + Som.x, So.y - Som.y);
        float2 Mo = make_float2(So.x - Som.x, So.y + Som.y);
        float2 Pq = make_float2(Sq.x + Sqm.x, Sq.y - Sqm.y);
        float2 Mq = make_float2(Sq.x - Sqm.x, Sq.y + Sqm.y);
        float2 PP = cmul(Po, Pq);
        float2 MM = cmul(Mo, Mq);
        e[brev3(j)] = make_float2(sc * (PP.x + MM.y), sc * (PP.y - MM.x));
    }
    fft_unit<-1, true>(s, e, t, true);

    #pragma unroll
    for (int j = 0; j < 8; j++) cout[rb + j * 64 + t] = e[j];
}

// ---------------- radix-8 column pass: 256 threads, 4 cols per block ----------------
template<int DIR, int MODE>
__global__ void __launch_bounds__(256) fft_col4(
    const float2* __restrict__ in, float2* __restrict__ cout, float* __restrict__ rout)
{
    __shared__ float2 sm[4 * CSTRIDE];
    int tid = threadIdx.x;
    int zp = blockIdx.y;
    int col0 = blockIdx.x * 4;
    size_t zb = (size_t)zp * NPIX;

    #pragma unroll
    for (int q = 0; q < 8; q++) {
        int l = tid + q * 256;
        int c = l & 3, i = l >> 2;
        sm[c * CSTRIDE + PADI(i)] = in[zb + (size_t)i * WDIM + col0 + c];
    }
    __syncthreads();

    int u = tid >> 6, t = tid & 63;
    float2* s = sm + u * CSTRIDE;
    float2 e[8];
    #pragma unroll
    for (int j = 0; j < 8; j++) e[brev3(j)] = s[PADI(t + 64 * j)];
    fft_unit<DIR, true>(s, e, t, true);
    #pragma unroll
    for (int j = 0; j < 8; j++) s[PADI(j * 64 + t)] = e[j];
    __syncthreads();

    #pragma unroll
    for (int q = 0; q < 8; q++) {
        int l = tid + q * 256;
        int c = l & 3, i = l >> 2;
        float2 v = sm[c * CSTRIDE + PADI(i)];
        size_t sp = (size_t)i * WDIM + col0 + c;
        if (MODE == 1) {
            cout[zb + sp] = v;
        } else {
            rout[(size_t)(2 * zp) * NPIX + sp]     = v.x;
            rout[(size_t)(2 * zp + 1) * NPIX + sp] = v.y;
        }
    }
}

// ---------------- launcher ----------------
extern "C" void kernel_launch(void* const* d_in, const int* in_sizes, int n_in,
                              void* d_out, int out_size)
{
    const float* z     = (const float*)d_in[0];
    const float* grid  = (const float*)d_in[1];
    const float* zdat  = (const float*)d_in[2];
    const float* w1    = (const float*)d_in[3];
    const float* b1    = (const float*)d_in[4];
    const float* w2    = (const float*)d_in[5];
    const float* b2    = (const float*)d_in[6];
    const float* w3    = (const float*)d_in[7];
    const float* b3    = (const float*)d_in[8];
    const float* pupil = (const float*)d_in[9];
    const float* aberr = (const float*)d_in[10];
    const float* lerp  = (const float*)d_in[11];
    const int*   x0    = (const int*)d_in[12];
    const int*   y0    = (const int*)d_in[13];
    const int*   x1    = (const int*)d_in[14];
    const int*   y1    = (const int*)d_in[15];
    float* out = (float*)d_out;

    float2* tmpA; float2* tmpB; float* qbuf; float* fluo;
    cudaGetSymbolAddress((void**)&tmpA, d_tmpA);
    cudaGetSymbolAddress((void**)&tmpB, d_tmpB);
    cudaGetSymbolAddress((void**)&qbuf, d_q);
    cudaGetSymbolAddress((void**)&fluo, d_fluo);
    float2* qcol = (float2*)qbuf;
    float2* Cbuf = (float2*)fluo;

    // Side stream for the pupil path (independent of render path until crossq).
    // Created fresh each call; intentionally NOT destroyed here — the stream is
    // part of an in-progress capture and destroying it would invalidate the
    // graph. No device memory is involved. The captured work is identical on
    // every call.
    cudaStream_t sA;
    cudaStreamCreateWithFlags(&sA, cudaStreamNonBlocking);
    cudaEvent_t evFork, evJoin;
    cudaEventCreateWithFlags(&evFork, cudaEventDisableTiming);
    cudaEventCreateWithFlags(&evJoin, cudaEventDisableTiming);

    // fork: side stream inherits the capture via the event
    cudaEventRecord(evFork, 0);
    cudaStreamWaitEvent(sA, evFork, 0);

    // ---- side stream: pupil path ----
    pupil_part<<<256, 256, 0, sA>>>(pupil);
    pupil_final<<<1, 256, 0, sA>>>();
    // rowIFFT(P) -> tmpA (30 planes)
    fft_row4<-1, 0><<<dim3(WDIM / 4, ZM), 256, 0, sA>>>(pupil, aberr, tmpA);
    // fused: col IFFT x2, |.|^2, packed forward col FFT -> qcol (15 planes)
    colq_kernel<<<dim3(WDIM / 2, NZP), 256, 0, sA>>>(tmpA, qcol);
    cudaEventRecord(evJoin, sA);

    // ---- main stream: render path ----
    xyfeat_kernel<<<NPIX / 256, 256>>>(grid, lerp, x0, y0, x1, y1);
    mlp_kernel<<<dim3(NPIX / 256, ZM), 128>>>(z, zdat, w1, b1, w2, b2, w3, b3);
    // So = F2(fluo) packed -> tmpB (col pass in-place)
    fft_row4<+1, 1><<<dim3(WDIM / 4, NZP), 256>>>(fluo, nullptr, tmpB);
    fft_col4<+1, 1><<<dim3(WDIM / 4, NZP), 256>>>(tmpB, tmpB, nullptr);

    // join: crossq needs qcol + cscale from the side stream
    cudaStreamWaitEvent(0, evJoin, 0);

    // fused: Sq rows + Hermitian cross spectrum + row IFFT -> Cbuf
    crossq_kernel<<<dim3(WDIM / 2, NZP), 128>>>(qcol, tmpB, Cbuf);
    // inverse col pass, split packed planes into the 30 real output planes
    fft_col4<-1, 2><<<dim3(WDIM / 4, NZP), 256>>>(Cbuf, nullptr, out);
}

// round 13
// speedup vs baseline: 4.7510x; 1.0315x over previous
#include <cuda_runtime.h>
#include <cstdint>

#define WDIM 512
#define NPIX (512*512)
#define ZM 30
#define NZP (ZM/2)

typedef unsigned long long ull;
typedef unsigned int uint;

// ---------------- device scratch ----------------
__device__ __align__(16) float2 d_tmpA[(size_t)ZM * NPIX];   // 63 MB
__device__ __align__(16) float2 d_tmpB[(size_t)ZM * NPIX];   // 63 MB
__device__ __align__(16) float  d_q   [(size_t)ZM * NPIX];   // packed colFFT(q), 15 cpx planes
__device__ __align__(16) float  d_fluo[(size_t)ZM * NPIX];   // fluo, reused as Cbuf
__device__ __align__(16) float  d_xyf [(size_t)NPIX * 16];   // 16 MB: [0,8MB)=hi b32 pairs, [8,16MB)=lo
__device__ int   d_part[256];
__device__ float d_cscale;

// ---------------- bf16 split helpers ----------------
__device__ __forceinline__ void split2(float x0, float x1, uint& h, uint& l) {
    uint hp;
    asm("cvt.rn.bf16x2.f32 %0, %1, %2;" : "=r"(hp) : "f"(x1), "f"(x0));
    float h0 = __uint_as_float(hp << 16);
    float h1 = __uint_as_float(hp & 0xffff0000u);
    float l0 = x0 - h0, l1 = x1 - h1;
    asm("cvt.rn.bf16x2.f32 %0, %1, %2;" : "=r"(l) : "f"(l1), "f"(l0));
    h = hp;
}

__device__ __forceinline__ void mma16816(float c[4], const uint a[4], uint2 b) {
    asm("mma.sync.aligned.m16n8k16.row.col.f32.bf16.bf16.f32 "
        "{%0,%1,%2,%3}, {%4,%5,%6,%7}, {%8,%9}, {%0,%1,%2,%3};"
        : "+f"(c[0]), "+f"(c[1]), "+f"(c[2]), "+f"(c[3])
        : "r"(a[0]), "r"(a[1]), "r"(a[2]), "r"(a[3]), "r"(b.x), "r"(b.y));
}

// ---------------- complex helpers ----------------
__device__ __forceinline__ float2 cmul(float2 a, float2 b) {
    return make_float2(fmaf(a.x, b.x, -a.y * b.y), fmaf(a.x, b.y, a.y * b.x));
}
__device__ __forceinline__ float2 cadd(float2 a, float2 b) { return make_float2(a.x + b.x, a.y + b.y); }
__device__ __forceinline__ float2 csub(float2 a, float2 b) { return make_float2(a.x - b.x, a.y - b.y); }

__device__ __forceinline__ int brev3(int j) { return ((j & 1) << 2) | (j & 2) | ((j >> 2) & 1); }
__device__ __forceinline__ int brev6(int t) { return (int)(__brev((unsigned)t) >> 26); }

#define PADI(p) ((p) + ((p) >> 5))
#define CSTRIDE 532

// ---------------- radix-8 butterflies ----------------
template<int DIR>
__device__ __forceinline__ void bf8_0(float2 e[8])
{
    const float d = (DIR > 0) ? 1.0f : -1.0f;
    float2 f[8];
    #pragma unroll
    for (int m = 0; m < 4; m++) {
        float2 u = e[2 * m], v = e[2 * m + 1];
        f[2 * m]     = cadd(u, v);
        f[2 * m + 1] = csub(u, v);
    }
    float2 g[8];
    #pragma unroll
    for (int hh = 0; hh < 2; hh++) {
        int o = 4 * hh;
        float2 v0 = f[o + 2];
        float2 v1 = make_float2(d * f[o + 3].y, -d * f[o + 3].x);
        g[o + 0] = cadd(f[o + 0], v0); g[o + 2] = csub(f[o + 0], v0);
        g[o + 1] = cadd(f[o + 1], v1); g[o + 3] = csub(f[o + 1], v1);
    }
    const float S2 = 0.70710678118654752f;
    float2 v0 = g[4];
    float2 v1 = cmul(g[5], make_float2(S2, -d * S2));
    float2 v2 = make_float2(d * g[6].y, -d * g[6].x);
    float2 v3 = cmul(g[7], make_float2(-S2, -d * S2));
    e[0] = cadd(g[0], v0); e[4] = csub(g[0], v0);
    e[1] = cadd(g[1], v1); e[5] = csub(g[1], v1);
    e[2] = cadd(g[2], v2); e[6] = csub(g[2], v2);
    e[3] = cadd(g[3], v3); e[7] = csub(g[3], v3);
}

template<int DIR>
__device__ __forceinline__ void bf8_g(float2 e[8], float r)
{
    const float d = (DIR > 0) ? 1.0f : -1.0f;
    float s1, c1;
    sincospif(r, &s1, &c1);
    float2 t1 = make_float2(c1, -d * s1);
    float2 t2 = cmul(t1, t1);
    float2 t4 = cmul(t2, t2);

    float2 f[8];
    #pragma unroll
    for (int m = 0; m < 4; m++) {
        float2 v = cmul(e[2 * m + 1], t4);
        f[2 * m]     = cadd(e[2 * m], v);
        f[2 * m + 1] = csub(e[2 * m], v);
    }
    float2 wb1 = make_float2(d * t2.y, -d * t2.x);
    float2 g[8];
    #pragma unroll
    for (int hh = 0; hh < 2; hh++) {
        int o = 4 * hh;
        float2 v0 = cmul(f[o + 2], t2);
        float2 v1 = cmul(f[o + 3], wb1);
        g[o + 0] = cadd(f[o + 0], v0); g[o + 2] = csub(f[o + 0], v0);
        g[o + 1] = cadd(f[o + 1], v1); g[o + 3] = csub(f[o + 1], v1);
    }
    const float S2 = 0.70710678118654752f;
    float2 wc1 = make_float2(S2 * (t1.x + d * t1.y), S2 * (t1.y - d * t1.x));
    float2 wc2 = make_float2(d * t1.y, -d * t1.x);
    float2 wc3 = make_float2(S2 * (-t1.x + d * t1.y), S2 * (-t1.y - d * t1.x));
    float2 v0 = cmul(g[4], t1);
    float2 v1 = cmul(g[5], wc1);
    float2 v2 = cmul(g[6], wc2);
    float2 v3 = cmul(g[7], wc3);
    e[0] = cadd(g[0], v0); e[4] = csub(g[0], v0);
    e[1] = cadd(g[1], v1); e[5] = csub(g[1], v1);
    e[2] = cadd(g[2], v2); e[6] = csub(g[2], v2);
    e[3] = cadd(g[3], v3); e[7] = csub(g[3], v3);
}

template<int DIR, bool PRESYNC>
__device__ __forceinline__ void fft_unit(float2* s, float2 e[8], int t, bool active)
{
    if (active) bf8_0<DIR>(e);
    if (PRESYNC) __syncthreads();
    if (active) {
        int b = brev6(t);
        #pragma unroll
        for (int j = 0; j < 8; j++) s[PADI(8 * b + j)] = e[j];
    }
    __syncthreads();
    if (active) {
        int b2 = t >> 3, k = t & 7;
        #pragma unroll
        for (int j = 0; j < 8; j++) e[j] = s[PADI(b2 * 64 + j * 8 + k)];
        bf8_g<DIR>(e, (float)k * (1.0f / 32.0f));
        #pragma unroll
        for (int j = 0; j < 8; j++) s[PADI(b2 * 64 + j * 8 + k)] = e[j];
    }
    __syncthreads();
    if (active) {
        #pragma unroll
        for (int j = 0; j < 8; j++) e[j] = s[PADI(j * 64 + t)];
        bf8_g<DIR>(e, (float)t * (1.0f / 256.0f));
    }
}

// ---------------- pupil sum ----------------
__global__ void __launch_bounds__(256) pupil_part(const float* __restrict__ pupil) {
    int tid = threadIdx.x, b = blockIdx.x;
    int v = 0;
    #pragma unroll 4
    for (int q = 0; q < 4; q++) {
        int i = b * 1024 + q * 256 + tid;
        v += (pupil[i] > 0.5f) ? 1 : 0;
    }
    #pragma unroll
    for (int o = 16; o; o >>= 1) v += __shfl_xor_sync(0xffffffffu, v, o);
    __shared__ int ws[8];
    if ((tid & 31) == 0) ws[tid >> 5] = v;
    __syncthreads();
    if (tid == 0) {
        int s = 0;
        #pragma unroll
        for (int w = 0; w < 8; w++) s += ws[w];
        d_part[b] = s;
    }
}

__global__ void __launch_bounds__(256) pupil_final() {
    int tid = threadIdx.x;
    int v = d_part[tid];
    #pragma unroll
    for (int o = 16; o; o >>= 1) v += __shfl_xor_sync(0xffffffffu, v, o);
    __shared__ int ws[8];
    if ((tid & 31) == 0) ws[tid >> 5] = v;
    __syncthreads();
    if (tid == 0) {
        int s = 0;
        #pragma unroll
        for (int w = 0; w < 8; w++) s += ws[w];
        d_cscale = (float)(1.0 / (68719476736.0 * (double)s));
    }
}

// ---------------- bilinear xy_feat + bf16 hi/lo split ----------------
__global__ void __launch_bounds__(256) xyfeat_kernel(
    const float* __restrict__ grid, const float* __restrict__ lerp,
    const int* __restrict__ x0, const int* __restrict__ y0,
    const int* __restrict__ x1, const int* __restrict__ y1)
{
    int p = blockIdx.x * 256 + threadIdx.x;
    float2 l = ((const float2*)lerp)[p];
    float lx = l.x, ly = l.y;
    int X0 = x0[p], Y0 = y0[p], X1 = x1[p], Y1 = y1[p];
    float w00 = (1.f - lx) * (1.f - ly);
    float w10 = lx * (1.f - ly);
    float w01 = (1.f - lx) * ly;
    float w11 = lx * ly;
    const float4* g00 = (const float4*)(grid + ((size_t)Y0 * WDIM + X0) * 16);
    const float4* g10 = (const float4*)(grid + ((size_t)Y0 * WDIM + X1) * 16);
    const float4* g01 = (const float4*)(grid + ((size_t)Y1 * WDIM + X0) * 16);
    const float4* g11 = (const float4*)(grid + ((size_t)Y1 * WDIM + X1) * 16);
    float f[16];
    #pragma unroll
    for (int q = 0; q < 4; q++) {
        float4 a = g00[q], b = g10[q], c = g01[q], d = g11[q];
        f[q * 4 + 0] = a.x * w00 + b.x * w10 + c.x * w01 + d.x * w11;
        f[q * 4 + 1] = a.y * w00 + b.y * w10 + c.y * w01 + d.y * w11;
        f[q * 4 + 2] = a.z * w00 + b.z * w10 + c.z * w01 + d.z * w11;
        f[q * 4 + 3] = a.w * w00 + b.w * w10 + c.w * w01 + d.w * w11;
    }
    uint hi[8], lo[8];
    #pragma unroll
    for (int t = 0; t < 8; t++) split2(f[2 * t], f[2 * t + 1], hi[t], lo[t]);
    uint* hip = (uint*)d_xyf;
    uint* lop = hip + (size_t)NPIX * 8;
    ((uint4*)(hip + (size_t)p * 8))[0] = make_uint4(hi[0], hi[1], hi[2], hi[3]);
    ((uint4*)(hip + (size_t)p * 8))[1] = make_uint4(hi[4], hi[5], hi[6], hi[7]);
    ((uint4*)(lop + (size_t)p * 8))[0] = make_uint4(lo[0], lo[1], lo[2], lo[3]);
    ((uint4*)(lop + (size_t)p * 8))[1] = make_uint4(lo[4], lo[5], lo[6], lo[7]);
}

// ---------------- tensor-core MLP (bf16 3-term split) ----------------
__global__ void __launch_bounds__(128) mlp_kernel(
    const float* __restrict__ zarr, const float* __restrict__ zdat,
    const float* __restrict__ w1, const float* __restrict__ b1,
    const float* __restrict__ w2, const float* __restrict__ b2,
    const float* __restrict__ w3, const float* __restrict__ b3)
{
    __shared__ uint2 w1h[4][32], w1l[4][32];     // [n][lane]
    __shared__ uint2 w2h[8][32], w2l[8][32];     // [s*4+n][lane]
    __shared__ float w3s[32];
    __shared__ float b1s[32], b2s[32];
    __shared__ float b3s;

    int tid = threadIdx.x, lane = tid & 31, warp = tid >> 5;
    int gid = lane >> 2, tig = lane & 3;
    int z = blockIdx.y;

    if (warp == 0) {
        float zv = zarr[z];
        float zn = (29.0f * zv) / 30.0f;
        float zfl = floorf(zn);
        int z0 = (int)zfl; z0 = min(max(z0, 0), ZM - 1);
        int z1 = min(z0 + 1, ZM - 1);
        float zl = zn - zfl;

        int ks[4] = { 2 * tig, 2 * tig + 1, 2 * tig + 8, 2 * tig + 9 };
        float zf[4];
        #pragma unroll
        for (int i = 0; i < 4; i++)
            zf[i] = zdat[z0 * 16 + ks[i]] * (1.0f - zl) + zdat[z1 * 16 + ks[i]] * zl;

        #pragma unroll
        for (int n = 0; n < 4; n++) {
            float wv[4];
            #pragma unroll
            for (int i = 0; i < 4; i++) wv[i] = w1[ks[i] * 32 + 8 * n + gid] * zf[i];
            uint h0, l0, h1, l1;
            split2(wv[0], wv[1], h0, l0);
            split2(wv[2], wv[3], h1, l1);
            w1h[n][lane] = make_uint2(h0, h1);
            w1l[n][lane] = make_uint2(l0, l1);
        }
        #pragma unroll
        for (int s = 0; s < 2; s++)
            #pragma unroll
            for (int n = 0; n < 4; n++) {
                float wv[4];
                #pragma unroll
                for (int i = 0; i < 4; i++) wv[i] = w2[(16 * s + ks[i]) * 32 + 8 * n + gid];
                uint h0, l0, h1, l1;
                split2(wv[0], wv[1], h0, l0);
                split2(wv[2], wv[3], h1, l1);
                w2h[s * 4 + n][lane] = make_uint2(h0, h1);
                w2l[s * 4 + n][lane] = make_uint2(l0, l1);
            }
        w3s[lane] = w3[lane];
        b1s[lane] = b1[lane];
        b2s[lane] = b2[lane];
        if (lane == 0) b3s = b3[0];
    }
    __syncthreads();

    const uint* hip = (const uint*)d_xyf;
    const uint* lop = hip + (size_t)NPIX * 8;
    uint pxb = blockIdx.x * 256 + warp * 64;
    float* fout = d_fluo + (size_t)z * NPIX;

    float w3r[8];
    #pragma unroll
    for (int n = 0; n < 4; n++) {
        w3r[2 * n]     = w3s[8 * n + 2 * tig];
        w3r[2 * n + 1] = w3s[8 * n + 2 * tig + 1];
    }
    float bias3 = b3s;

    #pragma unroll
    for (int m = 0; m < 4; m++) {
        uint pb = pxb + m * 16;
        uint r0 = (pb + gid) * 8u;
        uint r1 = (pb + gid + 8) * 8u;
        uint Ah[4], Al[4];
        Ah[0] = hip[r0 + tig];     Ah[1] = hip[r1 + tig];
        Ah[2] = hip[r0 + tig + 4]; Ah[3] = hip[r1 + tig + 4];
        Al[0] = lop[r0 + tig];     Al[1] = lop[r1 + tig];
        Al[2] = lop[r0 + tig + 4]; Al[3] = lop[r1 + tig + 4];

        // layer 1: 16 -> 32
        float acc[4][4];
        #pragma unroll
        for (int n = 0; n < 4; n++) {
            float bb0 = b1s[8 * n + 2 * tig], bb1 = b1s[8 * n + 2 * tig + 1];
            acc[n][0] = bb0; acc[n][1] = bb1; acc[n][2] = bb0; acc[n][3] = bb1;
        }
        #pragma unroll
        for (int n = 0; n < 4; n++) {
            uint2 bh = w1h[n][lane], bl = w1l[n][lane];
            mma16816(acc[n], Ah, bh);
            mma16816(acc[n], Ah, bl);
            mma16816(acc[n], Al, bh);
        }

        // relu + split -> layer-2 A frags
        uint A2h[2][4], A2l[2][4];
        #pragma unroll
        for (int s = 0; s < 2; s++) {
            split2(fmaxf(acc[2*s][0], 0.f),   fmaxf(acc[2*s][1], 0.f),   A2h[s][0], A2l[s][0]);
            split2(fmaxf(acc[2*s][2], 0.f),   fmaxf(acc[2*s][3], 0.f),   A2h[s][1], A2l[s][1]);
            split2(fmaxf(acc[2*s+1][0], 0.f), fmaxf(acc[2*s+1][1], 0.f), A2h[s][2], A2l[s][2]);
            split2(fmaxf(acc[2*s+1][2], 0.f), fmaxf(acc[2*s+1][3], 0.f), A2h[s][3], A2l[s][3]);
        }

        // layer 2: 32 -> 32
        float acc2[4][4];
        #pragma unroll
        for (int n = 0; n < 4; n++) {
            float bb0 = b2s[8 * n + 2 * tig], bb1 = b2s[8 * n + 2 * tig + 1];
            acc2[n][0] = bb0; acc2[n][1] = bb1; acc2[n][2] = bb0; acc2[n][3] = bb1;
        }
        #pragma unroll
        for (int n = 0; n < 4; n++)
            #pragma unroll
            for (int s = 0; s < 2; s++) {
                uint2 bh = w2h[s * 4 + n][lane], bl = w2l[s * 4 + n][lane];
                mma16816(acc2[n], A2h[s], bh);
                mma16816(acc2[n], A2h[s], bl);
                mma16816(acc2[n], A2l[s], bh);
            }

        // layer 3: 32 -> 1 in fp32 scalar (relu fused into the dot product)
        float p0 = 0.0f, p1 = 0.0f;
        #pragma unroll
        for (int n = 0; n < 4; n++) {
            p0 = fmaf(fmaxf(acc2[n][0], 0.f), w3r[2 * n],     p0);
            p0 = fmaf(fmaxf(acc2[n][1], 0.f), w3r[2 * n + 1], p0);
            p1 = fmaf(fmaxf(acc2[n][2], 0.f), w3r[2 * n],     p1);
            p1 = fmaf(fmaxf(acc2[n][3], 0.f), w3r[2 * n + 1], p1);
        }
        p0 += __shfl_xor_sync(0xffffffffu, p0, 1);
        p0 += __shfl_xor_sync(0xffffffffu, p0, 2);
        p1 += __shfl_xor_sync(0xffffffffu, p1, 1);
        p1 += __shfl_xor_sync(0xffffffffu, p1, 2);

        if (tig == 0) {
            fout[pb + gid]     = p0 + bias3;
            fout[pb + gid + 8] = p1 + bias3;
        }
    }
}

// ---------------- radix-8 row pass: 256 threads, 4 rows per block ----------------
template<int DIR, int MODE>
__global__ void __launch_bounds__(256) fft_row4(
    const float* __restrict__ rin, const float* __restrict__ aberr,
    float2* __restrict__ cout)
{
    __shared__ float2 sm[4][CSTRIDE];
    int tid = threadIdx.x;
    int u = tid >> 6, t = tid & 63;
    int r = blockIdx.x * 4 + u;
    int zp = blockIdx.y;
    size_t rb = (size_t)zp * NPIX + (size_t)r * WDIM;

    float2 e[8];
    if (MODE == 0) {
        #pragma unroll
        for (int j = 0; j < 8; j++) {
            int n = t + 64 * j;
            float p = rin[(size_t)r * WDIM + n];
            float ab = aberr[rb + n];
            float sn, cs; __sincosf(ab, &sn, &cs);
            e[brev3(j)] = make_float2(p * cs, p * sn);
        }
    } else {
        size_t b0 = (size_t)(2 * zp) * NPIX + (size_t)r * WDIM;
        size_t b1 = b0 + NPIX;
        #pragma unroll
        for (int j = 0; j < 8; j++) {
            int n = t + 64 * j;
            e[brev3(j)] = make_float2(rin[b0 + n], rin[b1 + n]);
        }
    }

    fft_unit<DIR, false>(&sm[u][0], e, t, true);

    #pragma unroll
    for (int j = 0; j < 8; j++) cout[rb + j * 64 + t] = e[j];
}

// ---------------- fused colQ pass: 512 threads, 4 columns, plane pair ----------------
// Phase 1 (8 units): inverse col FFT of both planes' 4 columns.
// Phase 2 (4 units): forward col FFT of packed |A0|^2 + i|A1|^2.
__global__ void __launch_bounds__(512) colq_kernel(
    const float2* __restrict__ in, float2* __restrict__ outp)
{
    __shared__ float2 sm[8 * CSTRIDE];
    int tid = threadIdx.x;
    int u = tid >> 6, t = tid & 63;
    int zp = blockIdx.y;
    int col0 = blockIdx.x * 4;

    #pragma unroll
    for (int q = 0; q < 8; q++) {
        int idx = tid + q * 512;
        int c = idx & 3, pl = (idx >> 2) & 1, i = idx >> 3;
        sm[(pl * 4 + c) * CSTRIDE + PADI(i)] =
            in[(size_t)(2 * zp + pl) * NPIX + (size_t)i * WDIM + col0 + c];
    }
    __syncthreads();

    // phase 1: inverse FFT per unit (u -> plane u>>2, col u&3)
    float2* s = sm + u * CSTRIDE;
    float2 e[8];
    #pragma unroll
    for (int j = 0; j < 8; j++) e[brev3(j)] = s[PADI(t + 64 * j)];
    fft_unit<-1, true>(s, e, t, true);
    #pragma unroll
    for (int j = 0; j < 8; j++) s[PADI(j * 64 + t)] = e[j];
    __syncthreads();

    // phase 2: packed forward FFT (units 0..3; unit c reads planes c and 4+c)
    bool act = (u < 4);
    if (act) {
        float2* s0 = sm + u * CSTRIDE;
        float2* s1 = sm + (4 + u) * CSTRIDE;
        #pragma unroll
        for (int j = 0; j < 8; j++) {
            int n = t + 64 * j;
            float2 a0 = s0[PADI(n)];
            float2 a1 = s1[PADI(n)];
            e[brev3(j)] = make_float2(a0.x * a0.x + a0.y * a0.y,
                                      a1.x * a1.x + a1.y * a1.y);
        }
    }
    fft_unit<+1, true>(s, e, t, act);
    if (act) {
        #pragma unroll
        for (int j = 0; j < 8; j++) s[PADI(j * 64 + t)] = e[j];
    }
    __syncthreads();

    #pragma unroll
    for (int q = 0; q < 4; q++) {
        int idx = tid + q * 512;
        int c = idx & 3, i = idx >> 2;
        outp[(size_t)zp * NPIX + (size_t)i * WDIM + col0 + c] =
            sm[c * CSTRIDE + PADI(i)];
    }
}

// ---------------- fused crossQ pass ----------------
__global__ void __launch_bounds__(128) crossq_kernel(
    const float2* __restrict__ qcol, const float2* __restrict__ cSo,
    float2* __restrict__ cout)
{
    __shared__ float2 sm[2 * CSTRIDE];
    int tid = threadIdx.x;
    int u = tid >> 6, t = tid & 63;
    int b = blockIdx.x;
    int zp = blockIdx.y;
    size_t zb = (size_t)zp * NPIX;

    int ru = (b == 0) ? (u == 0 ? 0 : 256) : (u == 0 ? b : WDIM - b);
    int pu = (b == 0) ? u : 1 - u;
    int rn = (WDIM - ru) & (WDIM - 1);
    size_t rb  = zb + (size_t)ru * WDIM;
    size_t rbm = zb + (size_t)rn * WDIM;

    float2* s = sm + u * CSTRIDE;
    float2* sp = sm + pu * CSTRIDE;

    float2 e[8];
    #pragma unroll
    for (int j = 0; j < 8; j++) e[brev3(j)] = qcol[rb + t + 64 * j];
    fft_unit<+1, false>(s, e, t, true);
    #pragma unroll
    for (int j = 0; j < 8; j++) s[PADI(j * 64 + t)] = e[j];
    __syncthreads();

    float sc = 0.25f * d_cscale;
    #pragma unroll
    for (int j = 0; j < 8; j++) {
        int n = t + 64 * j;
        int nn = (WDIM - n) & (WDIM - 1);
        float2 Sq  = s[PADI(n)];
        float2 Sqm = sp[PADI(nn)];
        float2 So  = cSo[rb + n];
        float2 Som = cSo[rbm + nn];
        float2 Po = make_float2(So.x + Som.x, So.y - Som.y);
        float2 Mo = make_float2(So.x - Som.x, So.y + Som.y);
        float2 Pq = make_float2(Sq.x + Sqm.x, Sq.y - Sqm.y);
        float2 Mq = make_float2(Sq.x - Sqm.x, Sq.y + Sqm.y);
        float2 PP = cmul(Po, Pq);
        float2 MM = cmul(Mo, Mq);
        e[brev3(j)] = make_float2(sc * (PP.x + MM.y), sc * (PP.y - MM.x));
    }
    fft_unit<-1, true>(s, e, t, true);

    #pragma unroll
    for (int j = 0; j < 8; j++) cout[rb + j * 64 + t] = e[j];
}

// ---------------- radix-8 column pass: 512 threads, 8 cols per block ----------------
// MODE 1: write complex (in-place safe)
// MODE 2: split: rout[2zp]=Re, rout[2zp+1]=Im   (DIR=-1)
template<int DIR, int MODE>
__global__ void __launch_bounds__(512) fft_col8(
    const float2* __restrict__ in, float2* __restrict__ cout, float* __restrict__ rout)
{
    __shared__ float2 sm[8 * CSTRIDE];
    int tid = threadIdx.x;
    int zp = blockIdx.y;
    int col0 = blockIdx.x * 8;
    size_t zb = (size_t)zp * NPIX;

    #pragma unroll
    for (int q = 0; q < 8; q++) {
        int l = tid + q * 512;
        int c = l & 7, i = l >> 3;
        sm[c * CSTRIDE + PADI(i)] = in[zb + (size_t)i * WDIM + col0 + c];
    }
    __syncthreads();

    int u = tid >> 6, t = tid & 63;
    float2* s = sm + u * CSTRIDE;
    float2 e[8];
    #pragma unroll
    for (int j = 0; j < 8; j++) e[brev3(j)] = s[PADI(t + 64 * j)];
    fft_unit<DIR, true>(s, e, t, true);
    #pragma unroll
    for (int j = 0; j < 8; j++) s[PADI(j * 64 + t)] = e[j];
    __syncthreads();

    #pragma unroll
    for (int q = 0; q < 8; q++) {
        int l = tid + q * 512;
        int c = l & 7, i = l >> 3;
        float2 v = sm[c * CSTRIDE + PADI(i)];
        size_t sp = (size_t)i * WDIM + col0 + c;
        if (MODE == 1) {
            cout[zb + sp] = v;
        } else {
            rout[(size_t)(2 * zp) * NPIX + sp]     = v.x;
            rout[(size_t)(2 * zp + 1) * NPIX + sp] = v.y;
        }
    }
}

// ---------------- launcher ----------------
extern "C" void kernel_launch(void* const* d_in, const int* in_sizes, int n_in,
                              void* d_out, int out_size)
{
    const float* z     = (const float*)d_in[0];
    const float* grid  = (const float*)d_in[1];
    const float* zdat  = (const float*)d_in[2];
    const float* w1    = (const float*)d_in[3];
    const float* b1    = (const float*)d_in[4];
    const float* w2    = (const float*)d_in[5];
    const float* b2    = (const float*)d_in[6];
    const float* w3    = (const float*)d_in[7];
    const float* b3    = (const float*)d_in[8];
    const float* pupil = (const float*)d_in[9];
    const float* aberr = (const float*)d_in[10];
    const float* lerp  = (const float*)d_in[11];
    const int*   x0    = (const int*)d_in[12];
    const int*   y0    = (const int*)d_in[13];
    const int*   x1    = (const int*)d_in[14];
    const int*   y1    = (const int*)d_in[15];
    float* out = (float*)d_out;

    float2* tmpA; float2* tmpB; float* qbuf; float* fluo;
    cudaGetSymbolAddress((void**)&tmpA, d_tmpA);
    cudaGetSymbolAddress((void**)&tmpB, d_tmpB);
    cudaGetSymbolAddress((void**)&qbuf, d_q);
    cudaGetSymbolAddress((void**)&fluo, d_fluo);
    float2* qcol = (float2*)qbuf;
    float2* Cbuf = (float2*)fluo;

    // Side stream for the pupil path (independent of render path until crossq).
    // Created fresh each call; intentionally NOT destroyed (capture-owned).
    cudaStream_t sA;
    cudaStreamCreateWithFlags(&sA, cudaStreamNonBlocking);
    cudaEvent_t evFork, evJoin;
    cudaEventCreateWithFlags(&evFork, cudaEventDisableTiming);
    cudaEventCreateWithFlags(&evJoin, cudaEventDisableTiming);

    cudaEventRecord(evFork, 0);
    cudaStreamWaitEvent(sA, evFork, 0);

    // ---- side stream: pupil path ----
    pupil_part<<<256, 256, 0, sA>>>(pupil);
    pupil_final<<<1, 256, 0, sA>>>();
    fft_row4<-1, 0><<<dim3(WDIM / 4, ZM), 256, 0, sA>>>(pupil, aberr, tmpA);
    colq_kernel<<<dim3(WDIM / 4, NZP), 512, 0, sA>>>(tmpA, qcol);
    cudaEventRecord(evJoin, sA);

    // ---- main stream: render path ----
    xyfeat_kernel<<<NPIX / 256, 256>>>(grid, lerp, x0, y0, x1, y1);
    mlp_kernel<<<dim3(NPIX / 256, ZM), 128>>>(z, zdat, w1, b1, w2, b2, w3, b3);
    fft_row4<+1, 1><<<dim3(WDIM / 4, NZP), 256>>>(fluo, nullptr, tmpB);
    fft_col8<+1, 1><<<dim3(WDIM / 8, NZP), 512>>>(tmpB, tmpB, nullptr);

    cudaStreamWaitEvent(0, evJoin, 0);

    crossq_kernel<<<dim3(WDIM / 2, NZP), 128>>>(qcol, tmpB, Cbuf);
    fft_col8<-1, 2><<<dim3(WDIM / 8, NZP), 512>>>(Cbuf, nullptr, out);
}